// round 3
// baseline (speedup 1.0000x reference)
#include <cuda_runtime.h>
#include <math.h>

#define HID 768
#define NHEAD 12
#define HDIM 64
#define FF 3072
#define NLAYER 12
#define WIN 256

// ---------------- scratch (device globals; no allocation allowed) -------------
__device__ float g_x[4096 * 768];
__device__ float g_qkv[4096 * 2304];
__device__ float g_a[4096 * 768];
__device__ float g_t[4096 * 768];
__device__ float g_h[4096 * 3072];
__device__ float g_wqkv[768 * 2304];
__device__ float g_bqkv[2304];
__device__ float g_emb[16 * 768];

// ---------------- SGEMM: C[M,N] = A[M,K] @ B[K,N] + bias[N] (+optional GELU) ---
// BM=BN=128, BK=8, 256 threads, 8x8 per thread, double buffered.
// Requires M%128==0, N%128==0, K%8==0 (true for all shapes used).
template <bool GELU>
__global__ __launch_bounds__(256, 2)
void sgemm_bias(const float* __restrict__ A, const float* __restrict__ B,
                const float* __restrict__ bias, float* __restrict__ C,
                int M, int N, int K)
{
    __shared__ __align__(16) float As[2][8][128];
    __shared__ __align__(16) float Bs[2][8][128];
    const int tid  = threadIdx.x;
    const int row0 = blockIdx.y * 128;
    const int col0 = blockIdx.x * 128;
    const int tx   = tid & 15, ty = tid >> 4;

    const int a_row = tid >> 1;
    const int a_col = (tid & 1) << 2;
    const int b_row = tid >> 5;
    const int b_col = (tid & 31) << 2;

    const float* Ap = A + (size_t)(row0 + a_row) * K + a_col;
    const float* Bp = B + (size_t)b_row * N + col0 + b_col;

    float4 a4 = *(const float4*)Ap;
    float4 b4 = *(const float4*)Bp;
    As[0][a_col + 0][a_row] = a4.x;
    As[0][a_col + 1][a_row] = a4.y;
    As[0][a_col + 2][a_row] = a4.z;
    As[0][a_col + 3][a_row] = a4.w;
    *(float4*)&Bs[0][b_row][b_col] = b4;
    __syncthreads();

    float acc[8][8];
#pragma unroll
    for (int i = 0; i < 8; i++)
#pragma unroll
        for (int j = 0; j < 8; j++) acc[i][j] = 0.f;

    const int nk = K >> 3;
    for (int kt = 0; kt < nk; kt++) {
        const int cur = kt & 1;
        if (kt + 1 < nk) {
            a4 = *(const float4*)(Ap + (size_t)(kt + 1) * 8);
            b4 = *(const float4*)(Bp + (size_t)(kt + 1) * 8 * N);
        }
#pragma unroll
        for (int k = 0; k < 8; k++) {
            float ra[8], rb[8];
            *(float4*)&ra[0] = *(const float4*)&As[cur][k][ty * 8];
            *(float4*)&ra[4] = *(const float4*)&As[cur][k][ty * 8 + 4];
            *(float4*)&rb[0] = *(const float4*)&Bs[cur][k][tx * 8];
            *(float4*)&rb[4] = *(const float4*)&Bs[cur][k][tx * 8 + 4];
#pragma unroll
            for (int i = 0; i < 8; i++)
#pragma unroll
                for (int j = 0; j < 8; j++) acc[i][j] += ra[i] * rb[j];
        }
        if (kt + 1 < nk) {
            const int nxt = cur ^ 1;
            As[nxt][a_col + 0][a_row] = a4.x;
            As[nxt][a_col + 1][a_row] = a4.y;
            As[nxt][a_col + 2][a_row] = a4.z;
            As[nxt][a_col + 3][a_row] = a4.w;
            *(float4*)&Bs[nxt][b_row][b_col] = b4;
        }
        __syncthreads();
    }

#pragma unroll
    for (int i = 0; i < 8; i++) {
        const size_t r = (size_t)(row0 + ty * 8 + i);
#pragma unroll
        for (int j = 0; j < 8; j += 4) {
            const int c = col0 + tx * 8 + j;
            float4 o;
            o.x = acc[i][j + 0] + bias[c + 0];
            o.y = acc[i][j + 1] + bias[c + 1];
            o.z = acc[i][j + 2] + bias[c + 2];
            o.w = acc[i][j + 3] + bias[c + 3];
            if (GELU) {
                o.x = 0.5f * o.x * (1.f + erff(o.x * 0.70710678118654752f));
                o.y = 0.5f * o.y * (1.f + erff(o.y * 0.70710678118654752f));
                o.z = 0.5f * o.z * (1.f + erff(o.z * 0.70710678118654752f));
                o.w = 0.5f * o.w * (1.f + erff(o.w * 0.70710678118654752f));
            }
            *(float4*)&C[r * N + c] = o;
        }
    }
}

// ---------------- pack Wq|Wk|Wv -> [768, 2304] (and biases) ---------------------
__global__ __launch_bounds__(256)
void pack_qkv_kernel(const float* __restrict__ Wq, const float* __restrict__ Wk,
                     const float* __restrict__ Wv, const float* __restrict__ bq,
                     const float* __restrict__ bk, const float* __restrict__ bv,
                     float* __restrict__ W, float* __restrict__ bias)
{
    const int i = blockIdx.x * 256 + threadIdx.x;   // 0 .. 768*768-1
    const int k = i / 768, n = i % 768;
    const size_t o = (size_t)k * 2304 + n;
    W[o]        = Wq[i];
    W[o + 768]  = Wk[i];
    W[o + 1536] = Wv[i];
    if (i < 768) { bias[i] = bq[i]; bias[768 + i] = bk[i]; bias[1536 + i] = bv[i]; }
}

// ---------------- embedding + layernorm ---------------------------------------
__global__ __launch_bounds__(256)
void embed_ln_kernel(const int* __restrict__ ids, const float* __restrict__ we,
                     const float* __restrict__ pe, const float* __restrict__ tt,
                     const float* __restrict__ g, const float* __restrict__ bta,
                     float* __restrict__ x, int S)
{
    const int tok = blockIdx.x;
    const int s   = tok % S;
    const int tid = threadIdx.x;
    const int id  = ids[tok];
    __shared__ float red[256];
    float v[3];
    float sum = 0.f;
#pragma unroll
    for (int i = 0; i < 3; i++) {
        const int dd = tid + i * 256;
        float t = we[(size_t)id * 768 + dd] + pe[(size_t)(s + 2) * 768 + dd] + tt[dd];
        v[i] = t;
        sum += t;
    }
    red[tid] = sum;
    __syncthreads();
    for (int st = 128; st > 0; st >>= 1) { if (tid < st) red[tid] += red[tid + st]; __syncthreads(); }
    const float mu = red[0] * (1.f / 768.f);
    __syncthreads();
    float vs = 0.f;
#pragma unroll
    for (int i = 0; i < 3; i++) { float dv = v[i] - mu; vs += dv * dv; }
    red[tid] = vs;
    __syncthreads();
    for (int st = 128; st > 0; st >>= 1) { if (tid < st) red[tid] += red[tid + st]; __syncthreads(); }
    const float rstd = rsqrtf(red[0] * (1.f / 768.f) + 1e-5f);
    const size_t base = (size_t)tok * 768;
#pragma unroll
    for (int i = 0; i < 3; i++) {
        const int dd = tid + i * 256;
        x[base + dd] = (v[i] - mu) * rstd * g[dd] + bta[dd];
    }
}

// ---------------- x = LN(x + delta) -------------------------------------------
__global__ __launch_bounds__(256)
void add_ln_kernel(float* __restrict__ x, const float* __restrict__ dlt,
                   const float* __restrict__ g, const float* __restrict__ bta)
{
    const int tok = blockIdx.x;
    const int tid = threadIdx.x;
    __shared__ float red[256];
    const size_t base = (size_t)tok * 768;
    float v[3];
    float sum = 0.f;
#pragma unroll
    for (int i = 0; i < 3; i++) {
        const int dd = tid + i * 256;
        float t = x[base + dd] + dlt[base + dd];
        v[i] = t;
        sum += t;
    }
    red[tid] = sum;
    __syncthreads();
    for (int st = 128; st > 0; st >>= 1) { if (tid < st) red[tid] += red[tid + st]; __syncthreads(); }
    const float mu = red[0] * (1.f / 768.f);
    __syncthreads();
    float vs = 0.f;
#pragma unroll
    for (int i = 0; i < 3; i++) { float dv = v[i] - mu; vs += dv * dv; }
    red[tid] = vs;
    __syncthreads();
    for (int st = 128; st > 0; st >>= 1) { if (tid < st) red[tid] += red[tid + st]; __syncthreads(); }
    const float rstd = rsqrtf(red[0] * (1.f / 768.f) + 1e-5f);
#pragma unroll
    for (int i = 0; i < 3; i++) {
        const int dd = tid + i * 256;
        x[base + dd] = (v[i] - mu) * rstd * g[dd] + bta[dd];
    }
}

// ---------------- sliding-window attention (coalesced, warp-per-key) -----------
// One block (128 thr = 4 warps) per (b, s, h). QKV packed rows of 2304 floats:
// q at [0,768), k at [768,1536), v at [1536,2304) within each token row.
__global__ __launch_bounds__(128)
void attn_kernel(const float* __restrict__ QKV, const int* __restrict__ amask,
                 float* __restrict__ O, int S)
{
    const int s = blockIdx.x, b = blockIdx.y, h = blockIdx.z;
    const int tid = threadIdx.x, lane = tid & 31, warp = tid >> 5;
    __shared__ float sc[513];
    __shared__ float redm[4], reds[4];
    __shared__ float obuf[3][64];

    const size_t RS = 2304;
    const size_t base = (size_t)b * S * RS + (size_t)h * 64;
    const float* Q = QKV + base;
    const float* K = QKV + base + 768;
    const float* V = QKV + base + 1536;

    int j0 = s - WIN; if (j0 < 0) j0 = 0;
    int j1 = s + WIN; if (j1 > S - 1) j1 = S - 1;
    const int nk = j1 - j0 + 1;

    const float2 q2 = *(const float2*)&Q[(size_t)s * RS + 2 * lane];

    // scores: one warp per key, coalesced 256B K-row read, shuffle reduce
    float lmax = -1e30f;
    for (int jj = warp; jj < nk; jj += 4) {
        const int j = j0 + jj;
        const float2 k2 = *(const float2*)&K[(size_t)j * RS + 2 * lane];
        float p = q2.x * k2.x + q2.y * k2.y;
#pragma unroll
        for (int off = 16; off; off >>= 1) p += __shfl_xor_sync(0xffffffffu, p, off);
        p *= 0.125f;
        if (amask[b * S + j] == 0) p = -1e9f;
        if (lane == 0) sc[jj] = p;
        lmax = fmaxf(lmax, p);
    }
    if (lane == 0) redm[warp] = lmax;
    __syncthreads();
    const float m = fmaxf(fmaxf(redm[0], redm[1]), fmaxf(redm[2], redm[3]));

    // softmax numerator + sum
    float lsum = 0.f;
    for (int jj = tid; jj < nk; jj += 128) {
        const float e = __expf(sc[jj] - m);
        sc[jj] = e;
        lsum += e;
    }
#pragma unroll
    for (int off = 16; off; off >>= 1) lsum += __shfl_xor_sync(0xffffffffu, lsum, off);
    if (lane == 0) reds[warp] = lsum;
    __syncthreads();
    const float inv = 1.f / (reds[0] + reds[1] + reds[2] + reds[3]);

    // output: 4-way key split, lanes cover 64 dims as float2 (coalesced V reads)
    float accx = 0.f, accy = 0.f;
    for (int jj = warp; jj < nk; jj += 4) {
        const float p = sc[jj];
        const float2 v2 = *(const float2*)&V[(size_t)(j0 + jj) * RS + 2 * lane];
        accx += p * v2.x;
        accy += p * v2.y;
    }
    if (warp) { obuf[warp - 1][2 * lane] = accx; obuf[warp - 1][2 * lane + 1] = accy; }
    __syncthreads();
    if (warp == 0) {
        accx += obuf[0][2 * lane] + obuf[1][2 * lane] + obuf[2][2 * lane];
        accy += obuf[0][2 * lane + 1] + obuf[1][2 * lane + 1] + obuf[2][2 * lane + 1];
        float2 o2 = make_float2(accx * inv, accy * inv);
        *(float2*)&O[((size_t)b * S + s) * 768 + h * 64 + 2 * lane] = o2;
    }
}

// ---------------- span pooling ---------------------------------------------------
__global__ __launch_bounds__(256)
void span_pool_kernel(const float* __restrict__ seq, const float* __restrict__ masks,
                      const int* __restrict__ sidx, float* __restrict__ emb, int S)
{
    const int t = blockIdx.x;
    const int b = sidx[t];
    const int tid = threadIdx.x;
    float acc0 = 0.f, acc1 = 0.f, acc2 = 0.f, msum = 0.f;
    for (int s = 0; s < S; s++) {
        const float m = masks[(size_t)t * S + s];
        msum += m;
        const float* row = seq + (size_t)(b * S + s) * 768;
        acc0 += m * row[tid];
        acc1 += m * row[tid + 256];
        acc2 += m * row[tid + 512];
    }
    const float inv = 1.f / fmaxf(msum, 1e-9f);
    emb[(size_t)t * 768 + tid]       = acc0 * inv;
    emb[(size_t)t * 768 + tid + 256] = acc1 * inv;
    emb[(size_t)t * 768 + tid + 512] = acc2 * inv;
}

// ---------------- projection head: relu(emb@pW1+pb1)@pW2+pb2, L2-normalize ------
__global__ __launch_bounds__(256)
void proj_kernel(const float* __restrict__ emb, const float* __restrict__ pW1,
                 const float* __restrict__ pb1, const float* __restrict__ pW2,
                 const float* __restrict__ pb2, float* __restrict__ out)
{
    const int t = blockIdx.x;
    const int tid = threadIdx.x;
    __shared__ float e[768];
    __shared__ float hdn[768];
    __shared__ float o[128];
    __shared__ float red[256];
    for (int d = tid; d < 768; d += 256) e[d] = emb[(size_t)t * 768 + d];
    __syncthreads();
    for (int j = tid; j < 768; j += 256) {
        float acc = pb1[j];
        for (int d = 0; d < 768; d++) acc += e[d] * pW1[(size_t)d * 768 + j];
        hdn[j] = fmaxf(acc, 0.f);
    }
    __syncthreads();
    if (tid < 128) {
        float acc = pb2[tid];
        for (int j = 0; j < 768; j++) acc += hdn[j] * pW2[(size_t)j * 128 + tid];
        o[tid] = acc;
    }
    __syncthreads();
    red[tid] = (tid < 128) ? o[tid] * o[tid] : 0.f;
    __syncthreads();
    for (int st = 128; st > 0; st >>= 1) { if (tid < st) red[tid] += red[tid + st]; __syncthreads(); }
    const float inv = 1.f / fmaxf(sqrtf(red[0]), 1e-12f);
    if (tid < 128) out[(size_t)t * 128 + tid] = o[tid] * inv;
}

// ---------------- driver ----------------------------------------------------------
extern "C" void kernel_launch(void* const* d_in, const int* in_sizes, int n_in,
                              void* d_out, int out_size)
{
    const int*   doc_ids   = (const int*)d_in[0];
    const int*   doc_mask  = (const int*)d_in[1];
    const int*   sum_ids   = (const int*)d_in[2];
    const int*   sum_mask  = (const int*)d_in[3];
    const float* og_masks  = (const float*)d_in[4];
    const float* llm_masks = (const float*)d_in[5];
    const int*   sidx      = (const int*)d_in[6];
    const float* word_emb  = (const float*)d_in[7];
    const float* pos_emb   = (const float*)d_in[8];
    const float* tt_emb    = (const float*)d_in[9];
    const float* ln_emb_g  = (const float*)d_in[10];
    const float* ln_emb_b  = (const float*)d_in[11];
    const float* Wq = (const float*)d_in[12];
    const float* bq = (const float*)d_in[13];
    const float* Wk = (const float*)d_in[14];
    const float* bk = (const float*)d_in[15];
    const float* Wv = (const float*)d_in[16];
    const float* bv = (const float*)d_in[17];
    const float* Wo = (const float*)d_in[18];
    const float* bo = (const float*)d_in[19];
    const float* ln1_g = (const float*)d_in[20];
    const float* ln1_b = (const float*)d_in[21];
    const float* W1 = (const float*)d_in[22];
    const float* b1 = (const float*)d_in[23];
    const float* W2 = (const float*)d_in[24];
    const float* b2 = (const float*)d_in[25];
    const float* ln2_g = (const float*)d_in[26];
    const float* ln2_b = (const float*)d_in[27];
    const float* pW1 = (const float*)d_in[28];
    const float* pb1 = (const float*)d_in[29];
    const float* pW2 = (const float*)d_in[30];
    const float* pb2 = (const float*)d_in[31];
    float* out = (float*)d_out;

    float *x, *qkv, *a, *tmp, *h, *wqkv, *bqkv, *emb;
    cudaGetSymbolAddress((void**)&x, g_x);
    cudaGetSymbolAddress((void**)&qkv, g_qkv);
    cudaGetSymbolAddress((void**)&a, g_a);
    cudaGetSymbolAddress((void**)&tmp, g_t);
    cudaGetSymbolAddress((void**)&h, g_h);
    cudaGetSymbolAddress((void**)&wqkv, g_wqkv);
    cudaGetSymbolAddress((void**)&bqkv, g_bqkv);
    cudaGetSymbolAddress((void**)&emb, g_emb);

    auto encode = [&](const int* ids, const int* amask, int B, int S) {
        const int T = B * S;
        embed_ln_kernel<<<T, 256>>>(ids, word_emb, pos_emb, tt_emb, ln_emb_g, ln_emb_b, x, S);
        for (int l = 0; l < NLAYER; l++) {
            const size_t wo  = (size_t)l * 768 * 768;
            const size_t w1o = (size_t)l * 768 * 3072;
            const size_t w2o = (size_t)l * 3072 * 768;
            dim3 g768(6, T / 128), g2304(18, T / 128), g3072(24, T / 128);

            pack_qkv_kernel<<<(768 * 768) / 256, 256>>>(Wq + wo, Wk + wo, Wv + wo,
                                                        bq + l * 768, bk + l * 768, bv + l * 768,
                                                        wqkv, bqkv);
            sgemm_bias<false><<<g2304, 256>>>(x, wqkv, bqkv, qkv, T, 2304, 768);
            attn_kernel<<<dim3(S, B, NHEAD), 128>>>(qkv, amask, a, S);
            sgemm_bias<false><<<g768, 256>>>(a, Wo + wo, bo + l * 768, tmp, T, 768, 768);
            add_ln_kernel<<<T, 256>>>(x, tmp, ln1_g + l * 768, ln1_b + l * 768);
            sgemm_bias<true><<<g3072, 256>>>(x, W1 + w1o, b1 + l * 3072, h, T, 3072, 768);
            sgemm_bias<false><<<g768, 256>>>(h, W2 + w2o, b2 + l * 768, tmp, T, 768, 3072);
            add_ln_kernel<<<T, 256>>>(x, tmp, ln2_g + l * 768, ln2_b + l * 768);
        }
    };

    // doc pass -> human embeddings
    encode(doc_ids, doc_mask, 2, 2048);
    span_pool_kernel<<<16, 256>>>(x, og_masks, sidx, emb, 2048);
    proj_kernel<<<16, 256>>>(emb, pW1, pb1, pW2, pb2, out);

    // summary pass -> llm embeddings
    encode(sum_ids, sum_mask, 2, 512);
    span_pool_kernel<<<16, 256>>>(x, llm_masks, sidx, emb, 512);
    proj_kernel<<<16, 256>>>(emb, pW1, pb1, pW2, pb2, out + 16 * 128);
}

// round 6
// speedup vs baseline: 1.1340x; 1.1340x over previous
#include <cuda_runtime.h>
#include <cuda_bf16.h>
#include <stdint.h>
#include <math.h>

#define WIN 256

// ---------------- scratch (device globals; no allocation allowed) -------------
__device__ float g_x[4096 * 768];
__device__ float g_qkv[4096 * 2304];
__device__ float g_a[4096 * 768];
__device__ float g_t[4096 * 768];
__device__ float g_h[4096 * 3072];
__device__ float g_emb[16 * 768];
__device__ float g_bqkv[12 * 2304];
// bf16x3 weight layouts: [3K][N] per layer (rows [0,K)=hi, [K,2K)=lo, [2K,3K)=hi)
__device__ __nv_bfloat16 g_wqkv3[(size_t)12 * 2304 * 2304];
__device__ __nv_bfloat16 g_wo3[(size_t)12 * 2304 * 768];
__device__ __nv_bfloat16 g_w13[(size_t)12 * 2304 * 3072];
__device__ __nv_bfloat16 g_w23[(size_t)12 * 9216 * 768];

// ---------------- weight conversion: W[K][N] fp32 -> [3K][N] bf16 (hi,lo,hi) ----
__global__ __launch_bounds__(256)
void conv_w_kernel(const float* __restrict__ W, __nv_bfloat16* __restrict__ W3,
                   int K, int N)
{
    const int l = blockIdx.y;
    const size_t i = (size_t)blockIdx.x * 256 + threadIdx.x;   // < K*N
    const float w = W[(size_t)l * K * N + i];
    const __nv_bfloat16 hi = __float2bfloat16_rn(w);
    const __nv_bfloat16 lo = __float2bfloat16_rn(w - __bfloat162float(hi));
    __nv_bfloat16* O = W3 + (size_t)l * 3 * K * N;
    O[i] = hi;
    O[(size_t)K * N + i] = lo;
    O[(size_t)2 * K * N + i] = hi;
}

// ---------------- QKV pack + convert: Wq|Wk|Wv -> [3*768][2304] bf16 ------------
__global__ __launch_bounds__(256)
void conv_qkv_kernel(const float* __restrict__ Wq, const float* __restrict__ Wk,
                     const float* __restrict__ Wv, const float* __restrict__ bq,
                     const float* __restrict__ bk, const float* __restrict__ bv,
                     __nv_bfloat16* __restrict__ W3, float* __restrict__ bias)
{
    const int l = blockIdx.y;
    const int i = blockIdx.x * 256 + threadIdx.x;   // < 768*2304
    const int k = i / 2304, n = i % 2304;
    const float* src = (n < 768) ? Wq : (n < 1536) ? Wk : Wv;
    const int nn = (n < 768) ? n : (n < 1536) ? n - 768 : n - 1536;
    const float w = src[((size_t)l * 768 + k) * 768 + nn];
    const __nv_bfloat16 hi = __float2bfloat16_rn(w);
    const __nv_bfloat16 lo = __float2bfloat16_rn(w - __bfloat162float(hi));
    __nv_bfloat16* O = W3 + (size_t)l * 2304 * 2304;
    O[(size_t)k * 2304 + n] = hi;
    O[(size_t)(768 + k) * 2304 + n] = lo;
    O[(size_t)(1536 + k) * 2304 + n] = hi;
    if (i < 2304) {
        const float* bsrc = (i < 768) ? bq : (i < 1536) ? bk : bv;
        const int bn = (i < 768) ? i : (i < 1536) ? i - 768 : i - 1536;
        bias[l * 2304 + i] = bsrc[(size_t)l * 768 + bn];
    }
}

// ---------------- bf16x3 tensor-core GEMM --------------------------------------
// C[M,N] = X[M,K](fp32, split on the fly) @ B3[3K,N](bf16) + bias  (+opt GELU)
// BM=128, BN=128, BK=32, 256 thr = 8 warps (2m x 4n), mma m16n8k16 bf16.
// Requires M%128==0, N%128==0, K%32==0.
template <bool GELU>
__global__ __launch_bounds__(256, 1)
void gemm_bf16x3(const float* __restrict__ X, const __nv_bfloat16* __restrict__ B3,
                 const float* __restrict__ bias, float* __restrict__ C,
                 int M, int N, int K)
{
    __shared__ __align__(16) __nv_bfloat16 As[2][128][40];
    __shared__ __align__(16) __nv_bfloat16 Bs[2][32][136];
    const int tid  = threadIdx.x;
    const int lane = tid & 31, warp = tid >> 5;
    const int wm = warp >> 2, wn = warp & 3;
    const int row0 = blockIdx.y * 128, col0 = blockIdx.x * 128;
    const int nk = (3 * K) >> 5;

    const int arow = tid >> 1;          // 0..127
    const int acol = (tid & 1) * 16;    // 0 or 16 (halfs)
    const int brow = tid >> 3;          // 0..31
    const int bcol = (tid & 7) * 16;    // 0..112 (halfs)

    float4 ap[4];
    uint4  bp[2];

    auto loadg = [&](int kt) {
        const int seg  = (kt * 32) / K;
        const int kcol = kt * 32 - seg * K;
        const float* Xp = X + (size_t)(row0 + arow) * K + kcol + acol;
        ap[0] = ((const float4*)Xp)[0];
        ap[1] = ((const float4*)Xp)[1];
        ap[2] = ((const float4*)Xp)[2];
        ap[3] = ((const float4*)Xp)[3];
        const __nv_bfloat16* Bp = B3 + (size_t)(kt * 32 + brow) * N + col0 + bcol;
        bp[0] = ((const uint4*)Bp)[0];
        bp[1] = ((const uint4*)Bp)[1];
    };
    auto stores = [&](int buf, int kt) {
        const bool is_hi = ((kt * 32) / K) < 2;
        __nv_bfloat16 hb[16];
#pragma unroll
        for (int i = 0; i < 4; i++) {
            const float v[4] = {ap[i].x, ap[i].y, ap[i].z, ap[i].w};
#pragma unroll
            for (int j = 0; j < 4; j++) {
                const __nv_bfloat16 hi = __float2bfloat16_rn(v[j]);
                hb[i * 4 + j] = is_hi ? hi
                                      : __float2bfloat16_rn(v[j] - __bfloat162float(hi));
            }
        }
        *(uint4*)&As[buf][arow][acol]     = ((uint4*)hb)[0];
        *(uint4*)&As[buf][arow][acol + 8] = ((uint4*)hb)[1];
        *(uint4*)&Bs[buf][brow][bcol]     = bp[0];
        *(uint4*)&Bs[buf][brow][bcol + 8] = bp[1];
    };

    float acc[4][4][4];
#pragma unroll
    for (int mi = 0; mi < 4; mi++)
#pragma unroll
        for (int nj = 0; nj < 4; nj++)
#pragma unroll
            for (int q = 0; q < 4; q++) acc[mi][nj][q] = 0.f;

    loadg(0);
    stores(0, 0);
    __syncthreads();

    for (int kt = 0; kt < nk; kt++) {
        const int cur = kt & 1;
        if (kt + 1 < nk) loadg(kt + 1);

        const unsigned aBase = (unsigned)__cvta_generic_to_shared(&As[cur][0][0]);
        const unsigned bBase = (unsigned)__cvta_generic_to_shared(&Bs[cur][0][0]);
#pragma unroll
        for (int ks = 0; ks < 2; ks++) {
            unsigned afrag[4][4];
            unsigned bfrag[4][2];
#pragma unroll
            for (int mi = 0; mi < 4; mi++) {
                const int r = wm * 64 + mi * 16 + (lane & 15);
                const int c = ks * 16 + (lane >> 4) * 8;
                const unsigned addr = aBase + (unsigned)(r * 40 + c) * 2u;
                asm volatile("ldmatrix.sync.aligned.m8n8.x4.shared.b16 {%0,%1,%2,%3}, [%4];"
                             : "=r"(afrag[mi][0]), "=r"(afrag[mi][1]),
                               "=r"(afrag[mi][2]), "=r"(afrag[mi][3])
                             : "r"(addr));
            }
#pragma unroll
            for (int nj = 0; nj < 4; nj++) {
                const int kr = ks * 16 + (lane & 15);
                const int c  = wn * 32 + nj * 8;
                const unsigned addr = bBase + (unsigned)(kr * 136 + c) * 2u;
                asm volatile("ldmatrix.sync.aligned.m8n8.x2.trans.shared.b16 {%0,%1}, [%2];"
                             : "=r"(bfrag[nj][0]), "=r"(bfrag[nj][1])
                             : "r"(addr));
            }
#pragma unroll
            for (int mi = 0; mi < 4; mi++)
#pragma unroll
                for (int nj = 0; nj < 4; nj++)
                    asm volatile("mma.sync.aligned.m16n8k16.row.col.f32.bf16.bf16.f32 "
                                 "{%0,%1,%2,%3}, {%4,%5,%6,%7}, {%8,%9}, {%0,%1,%2,%3};"
                                 : "+f"(acc[mi][nj][0]), "+f"(acc[mi][nj][1]),
                                   "+f"(acc[mi][nj][2]), "+f"(acc[mi][nj][3])
                                 : "r"(afrag[mi][0]), "r"(afrag[mi][1]),
                                   "r"(afrag[mi][2]), "r"(afrag[mi][3]),
                                   "r"(bfrag[nj][0]), "r"(bfrag[nj][1]));
        }

        if (kt + 1 < nk) stores(cur ^ 1, kt + 1);
        __syncthreads();
    }

#pragma unroll
    for (int mi = 0; mi < 4; mi++) {
        const int r = row0 + wm * 64 + mi * 16 + (lane >> 2);
#pragma unroll
        for (int nj = 0; nj < 4; nj++) {
            const int c = col0 + wn * 32 + nj * 8 + (lane & 3) * 2;
            const float2 b2 = *(const float2*)&bias[c];
            float o0 = acc[mi][nj][0] + b2.x;
            float o1 = acc[mi][nj][1] + b2.y;
            float o2 = acc[mi][nj][2] + b2.x;
            float o3 = acc[mi][nj][3] + b2.y;
            if (GELU) {
                o0 = 0.5f * o0 * (1.f + erff(o0 * 0.70710678118654752f));
                o1 = 0.5f * o1 * (1.f + erff(o1 * 0.70710678118654752f));
                o2 = 0.5f * o2 * (1.f + erff(o2 * 0.70710678118654752f));
                o3 = 0.5f * o3 * (1.f + erff(o3 * 0.70710678118654752f));
            }
            *(float2*)&C[(size_t)r * N + c]       = make_float2(o0, o1);
            *(float2*)&C[(size_t)(r + 8) * N + c] = make_float2(o2, o3);
        }
    }
}

// ---------------- embedding + layernorm ---------------------------------------
__global__ __launch_bounds__(256)
void embed_ln_kernel(const int* __restrict__ ids, const float* __restrict__ we,
                     const float* __restrict__ pe, const float* __restrict__ tt,
                     const float* __restrict__ g, const float* __restrict__ bta,
                     float* __restrict__ x, int S)
{
    const int tok = blockIdx.x;
    const int s   = tok % S;
    const int tid = threadIdx.x;
    const int id  = ids[tok];
    __shared__ float red[256];
    float v[3];
    float sum = 0.f;
#pragma unroll
    for (int i = 0; i < 3; i++) {
        const int dd = tid + i * 256;
        float t = we[(size_t)id * 768 + dd] + pe[(size_t)(s + 2) * 768 + dd] + tt[dd];
        v[i] = t;
        sum += t;
    }
    red[tid] = sum;
    __syncthreads();
    for (int st = 128; st > 0; st >>= 1) { if (tid < st) red[tid] += red[tid + st]; __syncthreads(); }
    const float mu = red[0] * (1.f / 768.f);
    __syncthreads();
    float vs = 0.f;
#pragma unroll
    for (int i = 0; i < 3; i++) { float dv = v[i] - mu; vs += dv * dv; }
    red[tid] = vs;
    __syncthreads();
    for (int st = 128; st > 0; st >>= 1) { if (tid < st) red[tid] += red[tid + st]; __syncthreads(); }
    const float rstd = rsqrtf(red[0] * (1.f / 768.f) + 1e-5f);
    const size_t base = (size_t)tok * 768;
#pragma unroll
    for (int i = 0; i < 3; i++) {
        const int dd = tid + i * 256;
        x[base + dd] = (v[i] - mu) * rstd * g[dd] + bta[dd];
    }
}

// ---------------- x = LN(x + delta) -------------------------------------------
__global__ __launch_bounds__(256)
void add_ln_kernel(float* __restrict__ x, const float* __restrict__ dlt,
                   const float* __restrict__ g, const float* __restrict__ bta)
{
    const int tok = blockIdx.x;
    const int tid = threadIdx.x;
    __shared__ float red[256];
    const size_t base = (size_t)tok * 768;
    float v[3];
    float sum = 0.f;
#pragma unroll
    for (int i = 0; i < 3; i++) {
        const int dd = tid + i * 256;
        float t = x[base + dd] + dlt[base + dd];
        v[i] = t;
        sum += t;
    }
    red[tid] = sum;
    __syncthreads();
    for (int st = 128; st > 0; st >>= 1) { if (tid < st) red[tid] += red[tid + st]; __syncthreads(); }
    const float mu = red[0] * (1.f / 768.f);
    __syncthreads();
    float vs = 0.f;
#pragma unroll
    for (int i = 0; i < 3; i++) { float dv = v[i] - mu; vs += dv * dv; }
    red[tid] = vs;
    __syncthreads();
    for (int st = 128; st > 0; st >>= 1) { if (tid < st) red[tid] += red[tid + st]; __syncthreads(); }
    const float rstd = rsqrtf(red[0] * (1.f / 768.f) + 1e-5f);
#pragma unroll
    for (int i = 0; i < 3; i++) {
        const int dd = tid + i * 256;
        x[base + dd] = (v[i] - mu) * rstd * g[dd] + bta[dd];
    }
}

// ---------------- sliding-window attention (coalesced, warp-per-key) -----------
__global__ __launch_bounds__(128)
void attn_kernel(const float* __restrict__ QKV, const int* __restrict__ amask,
                 float* __restrict__ O, int S)
{
    const int s = blockIdx.x, b = blockIdx.y, h = blockIdx.z;
    const int tid = threadIdx.x, lane = tid & 31, warp = tid >> 5;
    __shared__ float sc[513];
    __shared__ float redm[4], reds[4];
    __shared__ float obuf[3][64];

    const size_t RS = 2304;
    const size_t base = (size_t)b * S * RS + (size_t)h * 64;
    const float* Q = QKV + base;
    const float* K = QKV + base + 768;
    const float* V = QKV + base + 1536;

    int j0 = s - WIN; if (j0 < 0) j0 = 0;
    int j1 = s + WIN; if (j1 > S - 1) j1 = S - 1;
    const int nk = j1 - j0 + 1;

    const float2 q2 = *(const float2*)&Q[(size_t)s * RS + 2 * lane];

    float lmax = -1e30f;
    for (int jj = warp; jj < nk; jj += 4) {
        const int j = j0 + jj;
        const float2 k2 = *(const float2*)&K[(size_t)j * RS + 2 * lane];
        float p = q2.x * k2.x + q2.y * k2.y;
#pragma unroll
        for (int off = 16; off; off >>= 1) p += __shfl_xor_sync(0xffffffffu, p, off);
        p *= 0.125f;
        if (amask[b * S + j] == 0) p = -1e9f;
        if (lane == 0) sc[jj] = p;
        lmax = fmaxf(lmax, p);
    }
    if (lane == 0) redm[warp] = lmax;
    __syncthreads();
    const float m = fmaxf(fmaxf(redm[0], redm[1]), fmaxf(redm[2], redm[3]));

    float lsum = 0.f;
    for (int jj = tid; jj < nk; jj += 128) {
        const float e = __expf(sc[jj] - m);
        sc[jj] = e;
        lsum += e;
    }
#pragma unroll
    for (int off = 16; off; off >>= 1) lsum += __shfl_xor_sync(0xffffffffu, lsum, off);
    if (lane == 0) reds[warp] = lsum;
    __syncthreads();
    const float inv = 1.f / (reds[0] + reds[1] + reds[2] + reds[3]);

    float accx = 0.f, accy = 0.f;
    for (int jj = warp; jj < nk; jj += 4) {
        const float p = sc[jj];
        const float2 v2 = *(const float2*)&V[(size_t)(j0 + jj) * RS + 2 * lane];
        accx += p * v2.x;
        accy += p * v2.y;
    }
    if (warp) { obuf[warp - 1][2 * lane] = accx; obuf[warp - 1][2 * lane + 1] = accy; }
    __syncthreads();
    if (warp == 0) {
        accx += obuf[0][2 * lane] + obuf[1][2 * lane] + obuf[2][2 * lane];
        accy += obuf[0][2 * lane + 1] + obuf[1][2 * lane + 1] + obuf[2][2 * lane + 1];
        float2 o2 = make_float2(accx * inv, accy * inv);
        *(float2*)&O[((size_t)b * S + s) * 768 + h * 64 + 2 * lane] = o2;
    }
}

// ---------------- span pooling ---------------------------------------------------
__global__ __launch_bounds__(256)
void span_pool_kernel(const float* __restrict__ seq, const float* __restrict__ masks,
                      const int* __restrict__ sidx, float* __restrict__ emb, int S)
{
    const int t = blockIdx.x;
    const int b = sidx[t];
    const int tid = threadIdx.x;
    float acc0 = 0.f, acc1 = 0.f, acc2 = 0.f, msum = 0.f;
    for (int s = 0; s < S; s++) {
        const float m = masks[(size_t)t * S + s];
        msum += m;
        const float* row = seq + (size_t)(b * S + s) * 768;
        acc0 += m * row[tid];
        acc1 += m * row[tid + 256];
        acc2 += m * row[tid + 512];
    }
    const float inv = 1.f / fmaxf(msum, 1e-9f);
    emb[(size_t)t * 768 + tid]       = acc0 * inv;
    emb[(size_t)t * 768 + tid + 256] = acc1 * inv;
    emb[(size_t)t * 768 + tid + 512] = acc2 * inv;
}

// ---------------- projection head ----------------------------------------------
__global__ __launch_bounds__(256)
void proj_kernel(const float* __restrict__ emb, const float* __restrict__ pW1,
                 const float* __restrict__ pb1, const float* __restrict__ pW2,
                 const float* __restrict__ pb2, float* __restrict__ out)
{
    const int t = blockIdx.x;
    const int tid = threadIdx.x;
    __shared__ float e[768];
    __shared__ float hdn[768];
    __shared__ float o[128];
    __shared__ float red[256];
    for (int d = tid; d < 768; d += 256) e[d] = emb[(size_t)t * 768 + d];
    __syncthreads();
    for (int j = tid; j < 768; j += 256) {
        float acc = pb1[j];
        for (int d = 0; d < 768; d++) acc += e[d] * pW1[(size_t)d * 768 + j];
        hdn[j] = fmaxf(acc, 0.f);
    }
    __syncthreads();
    if (tid < 128) {
        float acc = pb2[tid];
        for (int j = 0; j < 768; j++) acc += hdn[j] * pW2[(size_t)j * 128 + tid];
        o[tid] = acc;
    }
    __syncthreads();
    red[tid] = (tid < 128) ? o[tid] * o[tid] : 0.f;
    __syncthreads();
    for (int st = 128; st > 0; st >>= 1) { if (tid < st) red[tid] += red[tid + st]; __syncthreads(); }
    const float inv = 1.f / fmaxf(sqrtf(red[0]), 1e-12f);
    if (tid < 128) out[(size_t)t * 128 + tid] = o[tid] * inv;
}

// ---------------- driver ----------------------------------------------------------
extern "C" void kernel_launch(void* const* d_in, const int* in_sizes, int n_in,
                              void* d_out, int out_size)
{
    const int*   doc_ids   = (const int*)d_in[0];
    const int*   doc_mask  = (const int*)d_in[1];
    const int*   sum_ids   = (const int*)d_in[2];
    const int*   sum_mask  = (const int*)d_in[3];
    const float* og_masks  = (const float*)d_in[4];
    const float* llm_masks = (const float*)d_in[5];
    const int*   sidx      = (const int*)d_in[6];
    const float* word_emb  = (const float*)d_in[7];
    const float* pos_emb   = (const float*)d_in[8];
    const float* tt_emb    = (const float*)d_in[9];
    const float* ln_emb_g  = (const float*)d_in[10];
    const float* ln_emb_b  = (const float*)d_in[11];
    const float* Wq = (const float*)d_in[12];
    const float* bq = (const float*)d_in[13];
    const float* Wk = (const float*)d_in[14];
    const float* bk = (const float*)d_in[15];
    const float* Wv = (const float*)d_in[16];
    const float* bv = (const float*)d_in[17];
    const float* Wo = (const float*)d_in[18];
    const float* bo = (const float*)d_in[19];
    const float* ln1_g = (const float*)d_in[20];
    const float* ln1_b = (const float*)d_in[21];
    const float* W1 = (const float*)d_in[22];
    const float* b1 = (const float*)d_in[23];
    const float* W2 = (const float*)d_in[24];
    const float* b2 = (const float*)d_in[25];
    const float* ln2_g = (const float*)d_in[26];
    const float* ln2_b = (const float*)d_in[27];
    const float* pW1 = (const float*)d_in[28];
    const float* pb1 = (const float*)d_in[29];
    const float* pW2 = (const float*)d_in[30];
    const float* pb2 = (const float*)d_in[31];
    float* out = (float*)d_out;

    float *x, *qkv, *a, *tmp, *h, *emb, *bqkv;
    __nv_bfloat16 *wqkv3, *wo3, *w13, *w23;
    cudaGetSymbolAddress((void**)&x, g_x);
    cudaGetSymbolAddress((void**)&qkv, g_qkv);
    cudaGetSymbolAddress((void**)&a, g_a);
    cudaGetSymbolAddress((void**)&tmp, g_t);
    cudaGetSymbolAddress((void**)&h, g_h);
    cudaGetSymbolAddress((void**)&emb, g_emb);
    cudaGetSymbolAddress((void**)&bqkv, g_bqkv);
    cudaGetSymbolAddress((void**)&wqkv3, g_wqkv3);
    cudaGetSymbolAddress((void**)&wo3, g_wo3);
    cudaGetSymbolAddress((void**)&w13, g_w13);
    cudaGetSymbolAddress((void**)&w23, g_w23);

    // one-time (per launch) weight conversion to bf16x3 layouts
    conv_qkv_kernel<<<dim3(6912, 12), 256>>>(Wq, Wk, Wv, bq, bk, bv, wqkv3, bqkv);
    conv_w_kernel<<<dim3(2304, 12), 256>>>(Wo, wo3, 768, 768);
    conv_w_kernel<<<dim3(9216, 12), 256>>>(W1, w13, 768, 3072);
    conv_w_kernel<<<dim3(9216, 12), 256>>>(W2, w23, 3072, 768);

    auto encode = [&](const int* ids, const int* amask, int B, int S) {
        const int T = B * S;
        embed_ln_kernel<<<T, 256>>>(ids, word_emb, pos_emb, tt_emb, ln_emb_g, ln_emb_b, x, S);
        for (int l = 0; l < 12; l++) {
            dim3 g768(6, T / 128), g2304(18, T / 128), g3072(24, T / 128);
            gemm_bf16x3<false><<<g2304, 256>>>(x, wqkv3 + (size_t)l * 2304 * 2304,
                                               bqkv + l * 2304, qkv, T, 2304, 768);
            attn_kernel<<<dim3(S, B, 12), 128>>>(qkv, amask, a, S);
            gemm_bf16x3<false><<<g768, 256>>>(a, wo3 + (size_t)l * 2304 * 768,
                                              bo + l * 768, tmp, T, 768, 768);
            add_ln_kernel<<<T, 256>>>(x, tmp, ln1_g + l * 768, ln1_b + l * 768);
            gemm_bf16x3<true><<<g3072, 256>>>(x, w13 + (size_t)l * 2304 * 3072,
                                              b1 + l * 3072, h, T, 3072, 768);
            gemm_bf16x3<false><<<g768, 256>>>(h, w23 + (size_t)l * 9216 * 768,
                                              b2 + l * 768, tmp, T, 768, 3072);
            add_ln_kernel<<<T, 256>>>(x, tmp, ln2_g + l * 768, ln2_b + l * 768);
        }
    };

    // doc pass -> human embeddings
    encode(doc_ids, doc_mask, 2, 2048);
    span_pool_kernel<<<16, 256>>>(x, og_masks, sidx, emb, 2048);
    proj_kernel<<<16, 256>>>(emb, pW1, pb1, pW2, pb2, out);

    // summary pass -> llm embeddings
    encode(sum_ids, sum_mask, 2, 512);
    span_pool_kernel<<<16, 256>>>(x, llm_masks, sidx, emb, 512);
    proj_kernel<<<16, 256>>>(emb, pW1, pb1, pW2, pb2, out + 16 * 128);
}

// round 7
// speedup vs baseline: 1.8227x; 1.6073x over previous
#include <cuda_runtime.h>
#include <cuda_bf16.h>
#include <stdint.h>
#include <math.h>

#define WIN 256

// ---------------- scratch (device globals; no allocation allowed) -------------
__device__ float g_x[4096 * 768];
__device__ float g_qkv[4096 * 2304];
__device__ float g_t[4096 * 768];
__device__ float g_emb[16 * 768];
__device__ float g_bqkv[12 * 2304];
// split activations: [M][2K] bf16, cols [0,K)=hi, [K,2K)=lo
__device__ __nv_bfloat16 g_xs[4096 * 1536];
__device__ __nv_bfloat16 g_as[4096 * 1536];
__device__ __nv_bfloat16 g_hs[(size_t)4096 * 6144];
// bf16x3 weight layouts: [3K][N] per layer (rows [0,K)=hi, [K,2K)=lo, [2K,3K)=hi)
__device__ __nv_bfloat16 g_wqkv3[(size_t)12 * 2304 * 2304];
__device__ __nv_bfloat16 g_wo3[(size_t)12 * 2304 * 768];
__device__ __nv_bfloat16 g_w13[(size_t)12 * 2304 * 3072];
__device__ __nv_bfloat16 g_w23[(size_t)12 * 9216 * 768];

// GEMM smem: 3 stages of (A 128x40 + B 32x136) bf16
#define GEMM_SMEM (3 * (128 * 40 + 32 * 136) * 2)

// ---------------- weight conversion: W[K][N] fp32 -> [3K][N] bf16 (hi,lo,hi) ----
__global__ __launch_bounds__(256)
void conv_w_kernel(const float* __restrict__ W, __nv_bfloat16* __restrict__ W3,
                   int K, int N)
{
    const int l = blockIdx.y;
    const size_t i = (size_t)blockIdx.x * 256 + threadIdx.x;   // < K*N
    const float w = W[(size_t)l * K * N + i];
    const __nv_bfloat16 hi = __float2bfloat16_rn(w);
    const __nv_bfloat16 lo = __float2bfloat16_rn(w - __bfloat162float(hi));
    __nv_bfloat16* O = W3 + (size_t)l * 3 * K * N;
    O[i] = hi;
    O[(size_t)K * N + i] = lo;
    O[(size_t)2 * K * N + i] = hi;
}

// ---------------- QKV pack + convert: Wq|Wk|Wv -> [3*768][2304] bf16 ------------
__global__ __launch_bounds__(256)
void conv_qkv_kernel(const float* __restrict__ Wq, const float* __restrict__ Wk,
                     const float* __restrict__ Wv, const float* __restrict__ bq,
                     const float* __restrict__ bk, const float* __restrict__ bv,
                     __nv_bfloat16* __restrict__ W3, float* __restrict__ bias)
{
    const int l = blockIdx.y;
    const int i = blockIdx.x * 256 + threadIdx.x;   // < 768*2304
    const int k = i / 2304, n = i % 2304;
    const float* src = (n < 768) ? Wq : (n < 1536) ? Wk : Wv;
    const int nn = (n < 768) ? n : (n < 1536) ? n - 768 : n - 1536;
    const float w = src[((size_t)l * 768 + k) * 768 + nn];
    const __nv_bfloat16 hi = __float2bfloat16_rn(w);
    const __nv_bfloat16 lo = __float2bfloat16_rn(w - __bfloat162float(hi));
    __nv_bfloat16* O = W3 + (size_t)l * 2304 * 2304;
    O[(size_t)k * 2304 + n] = hi;
    O[(size_t)(768 + k) * 2304 + n] = lo;
    O[(size_t)(1536 + k) * 2304 + n] = hi;
    if (i < 2304) {
        const float* bsrc = (i < 768) ? bq : (i < 1536) ? bk : bv;
        const int bn = (i < 768) ? i : (i < 1536) ? i - 768 : i - 1536;
        bias[l * 2304 + i] = bsrc[(size_t)l * 768 + bn];
    }
}

// ---------------- bf16x3 tensor-core GEMM, cp.async 3-stage ---------------------
// C[M,N] = Xs[M,2K](bf16 hi|lo) @ B3[3K,N](bf16) + bias
// seg0: Whi*xhi, seg1: Wlo*xhi, seg2: Whi*xlo.
// OUTMODE 0: fp32 C[M][N].  OUTMODE 1: gelu, then bf16 split out C[M][2N].
template <int OUTMODE>
__global__ __launch_bounds__(256, 2)
void gemm_bf16x3(const __nv_bfloat16* __restrict__ A2, const __nv_bfloat16* __restrict__ B3,
                 const float* __restrict__ bias, void* __restrict__ Cout,
                 int M, int N, int K)
{
    extern __shared__ __align__(16) unsigned char smem_raw[];
    __nv_bfloat16* As = (__nv_bfloat16*)smem_raw;                       // [3][128][40]
    __nv_bfloat16* Bs = (__nv_bfloat16*)(smem_raw + 3 * 128 * 40 * 2);  // [3][32][136]

    const int tid  = threadIdx.x;
    const int lane = tid & 31, warp = tid >> 5;
    const int wm = warp >> 2, wn = warp & 3;
    const int row0 = blockIdx.y * 128, col0 = blockIdx.x * 128;
    const int nk = (3 * K) >> 5;

    const int arow = tid >> 1;          // 0..127
    const int acol = (tid & 1) * 16;    // 0 or 16 (halfs)
    const int brow = tid >> 3;          // 0..31
    const int bcol = (tid & 7) * 16;    // 0..112 (halfs)

    auto issue = [&](int kt) {
        const int stg = kt % 3;
        const int kk = kt * 32;
        const int seg = kk / K;
        const int acolg = (seg == 2 ? K : 0) + (kk - seg * K);
        const __nv_bfloat16* Ag = A2 + (size_t)(row0 + arow) * (2 * K) + acolg + acol;
        const __nv_bfloat16* Bg = B3 + (size_t)(kk + brow) * N + col0 + bcol;
        const unsigned as_addr = (unsigned)__cvta_generic_to_shared(As + (stg * 128 + arow) * 40 + acol);
        const unsigned bs_addr = (unsigned)__cvta_generic_to_shared(Bs + (stg * 32 + brow) * 136 + bcol);
        asm volatile("cp.async.cg.shared.global [%0], [%1], 16;" :: "r"(as_addr), "l"(Ag));
        asm volatile("cp.async.cg.shared.global [%0], [%1], 16;" :: "r"(as_addr + 16), "l"(Ag + 8));
        asm volatile("cp.async.cg.shared.global [%0], [%1], 16;" :: "r"(bs_addr), "l"(Bg));
        asm volatile("cp.async.cg.shared.global [%0], [%1], 16;" :: "r"(bs_addr + 16), "l"(Bg + 8));
        asm volatile("cp.async.commit_group;");
    };

    float acc[4][4][4];
#pragma unroll
    for (int mi = 0; mi < 4; mi++)
#pragma unroll
        for (int nj = 0; nj < 4; nj++)
#pragma unroll
            for (int q = 0; q < 4; q++) acc[mi][nj][q] = 0.f;

    issue(0);
    issue(1);

    for (int kt = 0; kt < nk; kt++) {
        asm volatile("cp.async.wait_group 1;");
        __syncthreads();
        if (kt + 2 < nk) issue(kt + 2);
        else asm volatile("cp.async.commit_group;");

        const int stg = kt % 3;
        const unsigned aBase = (unsigned)__cvta_generic_to_shared(As + stg * 128 * 40);
        const unsigned bBase = (unsigned)__cvta_generic_to_shared(Bs + stg * 32 * 136);
#pragma unroll
        for (int ks = 0; ks < 2; ks++) {
            unsigned afrag[4][4];
            unsigned bfrag[4][2];
#pragma unroll
            for (int mi = 0; mi < 4; mi++) {
                const int r = wm * 64 + mi * 16 + (lane & 15);
                const int c = ks * 16 + (lane >> 4) * 8;
                const unsigned addr = aBase + (unsigned)(r * 40 + c) * 2u;
                asm volatile("ldmatrix.sync.aligned.m8n8.x4.shared.b16 {%0,%1,%2,%3}, [%4];"
                             : "=r"(afrag[mi][0]), "=r"(afrag[mi][1]),
                               "=r"(afrag[mi][2]), "=r"(afrag[mi][3])
                             : "r"(addr));
            }
#pragma unroll
            for (int nj = 0; nj < 4; nj++) {
                const int kr = ks * 16 + (lane & 15);
                const int c  = wn * 32 + nj * 8;
                const unsigned addr = bBase + (unsigned)(kr * 136 + c) * 2u;
                asm volatile("ldmatrix.sync.aligned.m8n8.x2.trans.shared.b16 {%0,%1}, [%2];"
                             : "=r"(bfrag[nj][0]), "=r"(bfrag[nj][1])
                             : "r"(addr));
            }
#pragma unroll
            for (int mi = 0; mi < 4; mi++)
#pragma unroll
                for (int nj = 0; nj < 4; nj++)
                    asm volatile("mma.sync.aligned.m16n8k16.row.col.f32.bf16.bf16.f32 "
                                 "{%0,%1,%2,%3}, {%4,%5,%6,%7}, {%8,%9}, {%0,%1,%2,%3};"
                                 : "+f"(acc[mi][nj][0]), "+f"(acc[mi][nj][1]),
                                   "+f"(acc[mi][nj][2]), "+f"(acc[mi][nj][3])
                                 : "r"(afrag[mi][0]), "r"(afrag[mi][1]),
                                   "r"(afrag[mi][2]), "r"(afrag[mi][3]),
                                   "r"(bfrag[nj][0]), "r"(bfrag[nj][1]));
        }
        __syncthreads();
    }

#pragma unroll
    for (int mi = 0; mi < 4; mi++) {
        const int r = row0 + wm * 64 + mi * 16 + (lane >> 2);
#pragma unroll
        for (int nj = 0; nj < 4; nj++) {
            const int c = col0 + wn * 32 + nj * 8 + (lane & 3) * 2;
            const float2 b2 = *(const float2*)&bias[c];
            float o0 = acc[mi][nj][0] + b2.x;
            float o1 = acc[mi][nj][1] + b2.y;
            float o2 = acc[mi][nj][2] + b2.x;
            float o3 = acc[mi][nj][3] + b2.y;
            if (OUTMODE == 0) {
                float* C = (float*)Cout;
                *(float2*)&C[(size_t)r * N + c]       = make_float2(o0, o1);
                *(float2*)&C[(size_t)(r + 8) * N + c] = make_float2(o2, o3);
            } else {
                o0 = 0.5f * o0 * (1.f + erff(o0 * 0.70710678118654752f));
                o1 = 0.5f * o1 * (1.f + erff(o1 * 0.70710678118654752f));
                o2 = 0.5f * o2 * (1.f + erff(o2 * 0.70710678118654752f));
                o3 = 0.5f * o3 * (1.f + erff(o3 * 0.70710678118654752f));
                __nv_bfloat16* C2 = (__nv_bfloat16*)Cout;
                const size_t rs = (size_t)2 * N;
                __nv_bfloat162 hp, lp;
                hp.x = __float2bfloat16_rn(o0);
                hp.y = __float2bfloat16_rn(o1);
                lp.x = __float2bfloat16_rn(o0 - __bfloat162float(hp.x));
                lp.y = __float2bfloat16_rn(o1 - __bfloat162float(hp.y));
                *(__nv_bfloat162*)&C2[(size_t)r * rs + c]     = hp;
                *(__nv_bfloat162*)&C2[(size_t)r * rs + N + c] = lp;
                hp.x = __float2bfloat16_rn(o2);
                hp.y = __float2bfloat16_rn(o3);
                lp.x = __float2bfloat16_rn(o2 - __bfloat162float(hp.x));
                lp.y = __float2bfloat16_rn(o3 - __bfloat162float(hp.y));
                *(__nv_bfloat162*)&C2[(size_t)(r + 8) * rs + c]     = hp;
                *(__nv_bfloat162*)&C2[(size_t)(r + 8) * rs + N + c] = lp;
            }
        }
    }
}

// ---------------- split write helper (device inline) ----------------------------
__device__ __forceinline__ void write_split(__nv_bfloat16* xs, size_t row, int col, float v)
{
    const __nv_bfloat16 hi = __float2bfloat16_rn(v);
    const __nv_bfloat16 lo = __float2bfloat16_rn(v - __bfloat162float(hi));
    xs[row * 1536 + col] = hi;
    xs[row * 1536 + 768 + col] = lo;
}

// ---------------- embedding + layernorm (writes x fp32 + xs split) --------------
__global__ __launch_bounds__(256)
void embed_ln_kernel(const int* __restrict__ ids, const float* __restrict__ we,
                     const float* __restrict__ pe, const float* __restrict__ tt,
                     const float* __restrict__ g, const float* __restrict__ bta,
                     float* __restrict__ x, __nv_bfloat16* __restrict__ xs, int S)
{
    const int tok = blockIdx.x;
    const int s   = tok % S;
    const int tid = threadIdx.x;
    const int id  = ids[tok];
    __shared__ float red[256];
    float v[3];
    float sum = 0.f;
#pragma unroll
    for (int i = 0; i < 3; i++) {
        const int dd = tid + i * 256;
        float t = we[(size_t)id * 768 + dd] + pe[(size_t)(s + 2) * 768 + dd] + tt[dd];
        v[i] = t;
        sum += t;
    }
    red[tid] = sum;
    __syncthreads();
    for (int st = 128; st > 0; st >>= 1) { if (tid < st) red[tid] += red[tid + st]; __syncthreads(); }
    const float mu = red[0] * (1.f / 768.f);
    __syncthreads();
    float vs = 0.f;
#pragma unroll
    for (int i = 0; i < 3; i++) { float dv = v[i] - mu; vs += dv * dv; }
    red[tid] = vs;
    __syncthreads();
    for (int st = 128; st > 0; st >>= 1) { if (tid < st) red[tid] += red[tid + st]; __syncthreads(); }
    const float rstd = rsqrtf(red[0] * (1.f / 768.f) + 1e-5f);
#pragma unroll
    for (int i = 0; i < 3; i++) {
        const int dd = tid + i * 256;
        const float o = (v[i] - mu) * rstd * g[dd] + bta[dd];
        x[(size_t)tok * 768 + dd] = o;
        write_split(xs, (size_t)tok, dd, o);
    }
}

// ---------------- x = LN(x + delta), writes x fp32 + xs split -------------------
__global__ __launch_bounds__(256)
void add_ln_kernel(float* __restrict__ x, const float* __restrict__ dlt,
                   const float* __restrict__ g, const float* __restrict__ bta,
                   __nv_bfloat16* __restrict__ xs)
{
    const int tok = blockIdx.x;
    const int tid = threadIdx.x;
    __shared__ float red[256];
    const size_t base = (size_t)tok * 768;
    float v[3];
    float sum = 0.f;
#pragma unroll
    for (int i = 0; i < 3; i++) {
        const int dd = tid + i * 256;
        float t = x[base + dd] + dlt[base + dd];
        v[i] = t;
        sum += t;
    }
    red[tid] = sum;
    __syncthreads();
    for (int st = 128; st > 0; st >>= 1) { if (tid < st) red[tid] += red[tid + st]; __syncthreads(); }
    const float mu = red[0] * (1.f / 768.f);
    __syncthreads();
    float vs = 0.f;
#pragma unroll
    for (int i = 0; i < 3; i++) { float dv = v[i] - mu; vs += dv * dv; }
    red[tid] = vs;
    __syncthreads();
    for (int st = 128; st > 0; st >>= 1) { if (tid < st) red[tid] += red[tid + st]; __syncthreads(); }
    const float rstd = rsqrtf(red[0] * (1.f / 768.f) + 1e-5f);
#pragma unroll
    for (int i = 0; i < 3; i++) {
        const int dd = tid + i * 256;
        const float o = (v[i] - mu) * rstd * g[dd] + bta[dd];
        x[base + dd] = o;
        write_split(xs, (size_t)tok, dd, o);
    }
}

// ---------------- sliding-window attention, 4 queries per block -----------------
// Block (128 thr) handles (b, h, 4 queries). QKV rows of 2304 floats.
// Output written as bf16 split [M][1536] (feeds the Wo GEMM).
__global__ __launch_bounds__(128)
void attn_kernel(const float* __restrict__ QKV, const int* __restrict__ amask,
                 __nv_bfloat16* __restrict__ AS, int S)
{
    const int q0 = blockIdx.x * 4, b = blockIdx.y, h = blockIdx.z;
    const int tid = threadIdx.x, lane = tid & 31, warp = tid >> 5;
    const int g = lane >> 4, li = lane & 15;
    __shared__ float sc[4][520];
    __shared__ float redm[8][4];
    __shared__ float reds[4][4];
    __shared__ float obuf[3][4][64];

    const size_t RS = 2304;
    const size_t base = (size_t)b * S * RS + (size_t)h * 64;
    const float* Q  = QKV + base;
    const float* Kp = QKV + base + 768;
    const float* Vp = QKV + base + 1536;

    int j0 = q0 - WIN; if (j0 < 0) j0 = 0;
    int j1 = q0 + 3 + WIN; if (j1 > S - 1) j1 = S - 1;
    const int nk = j1 - j0 + 1;

    float4 q4[4];
#pragma unroll
    for (int qi = 0; qi < 4; qi++)
        q4[qi] = *(const float4*)&Q[(size_t)(q0 + qi) * RS + 4 * li];

    // scores: 2 keys per warp iteration (16-lane groups), 4 queries each
    float lmax[4] = {-1e30f, -1e30f, -1e30f, -1e30f};
    for (int jj = warp * 2 + g; jj < nk; jj += 8) {
        const int j = j0 + jj;
        const float4 k4 = *(const float4*)&Kp[(size_t)j * RS + 4 * li];
        float p[4];
#pragma unroll
        for (int qi = 0; qi < 4; qi++)
            p[qi] = q4[qi].x * k4.x + q4[qi].y * k4.y + q4[qi].z * k4.z + q4[qi].w * k4.w;
#pragma unroll
        for (int off = 8; off; off >>= 1)
#pragma unroll
            for (int qi = 0; qi < 4; qi++)
                p[qi] += __shfl_xor_sync(0xffffffffu, p[qi], off);
        const int mok = amask[b * S + j];
#pragma unroll
        for (int qi = 0; qi < 4; qi++) {
            const int sq = q0 + qi;
            const bool valid = mok && (j >= sq - WIN) && (j <= sq + WIN);
            const float val = valid ? p[qi] * 0.125f : -1e9f;
            if (li == qi) sc[qi][jj] = val;
            lmax[qi] = fmaxf(lmax[qi], val);
        }
    }
    if (li == 0) {
#pragma unroll
        for (int qi = 0; qi < 4; qi++) redm[warp * 2 + g][qi] = lmax[qi];
    }
    __syncthreads();
    float m[4];
#pragma unroll
    for (int qi = 0; qi < 4; qi++) {
        float mm = redm[0][qi];
#pragma unroll
        for (int w = 1; w < 8; w++) mm = fmaxf(mm, redm[w][qi]);
        m[qi] = mm;
    }

    // exp + sums
    float lsum[4] = {0.f, 0.f, 0.f, 0.f};
    for (int jj = tid; jj < nk; jj += 128) {
#pragma unroll
        for (int qi = 0; qi < 4; qi++) {
            const float e = __expf(sc[qi][jj] - m[qi]);
            sc[qi][jj] = e;
            lsum[qi] += e;
        }
    }
#pragma unroll
    for (int off = 16; off; off >>= 1)
#pragma unroll
        for (int qi = 0; qi < 4; qi++)
            lsum[qi] += __shfl_xor_sync(0xffffffffu, lsum[qi], off);
    if (lane == 0) {
#pragma unroll
        for (int qi = 0; qi < 4; qi++) reds[warp][qi] = lsum[qi];
    }
    __syncthreads();
    float inv[4];
#pragma unroll
    for (int qi = 0; qi < 4; qi++)
        inv[qi] = 1.f / (reds[0][qi] + reds[1][qi] + reds[2][qi] + reds[3][qi]);

    // PV: warps split keys, each warp accumulates all 4 queries (lanes = dims)
    float ax[4] = {0.f, 0.f, 0.f, 0.f}, ay[4] = {0.f, 0.f, 0.f, 0.f};
    for (int jj = warp; jj < nk; jj += 4) {
        const float2 v2 = *(const float2*)&Vp[(size_t)(j0 + jj) * RS + 2 * lane];
#pragma unroll
        for (int qi = 0; qi < 4; qi++) {
            const float p = sc[qi][jj];
            ax[qi] += p * v2.x;
            ay[qi] += p * v2.y;
        }
    }
    if (warp) {
#pragma unroll
        for (int qi = 0; qi < 4; qi++) {
            obuf[warp - 1][qi][2 * lane]     = ax[qi];
            obuf[warp - 1][qi][2 * lane + 1] = ay[qi];
        }
    }
    __syncthreads();
    if (warp == 0) {
#pragma unroll
        for (int qi = 0; qi < 4; qi++) {
            float vx = ax[qi] + obuf[0][qi][2 * lane] + obuf[1][qi][2 * lane] + obuf[2][qi][2 * lane];
            float vy = ay[qi] + obuf[0][qi][2 * lane + 1] + obuf[1][qi][2 * lane + 1] + obuf[2][qi][2 * lane + 1];
            vx *= inv[qi];
            vy *= inv[qi];
            const size_t row = (size_t)b * S + q0 + qi;
            const int col = h * 64 + 2 * lane;
            __nv_bfloat162 hp, lp;
            hp.x = __float2bfloat16_rn(vx);
            hp.y = __float2bfloat16_rn(vy);
            lp.x = __float2bfloat16_rn(vx - __bfloat162float(hp.x));
            lp.y = __float2bfloat16_rn(vy - __bfloat162float(hp.y));
            *(__nv_bfloat162*)&AS[row * 1536 + col]       = hp;
            *(__nv_bfloat162*)&AS[row * 1536 + 768 + col] = lp;
        }
    }
}

// ---------------- span pooling ---------------------------------------------------
__global__ __launch_bounds__(256)
void span_pool_kernel(const float* __restrict__ seq, const float* __restrict__ masks,
                      const int* __restrict__ sidx, float* __restrict__ emb, int S)
{
    const int t = blockIdx.x;
    const int b = sidx[t];
    const int tid = threadIdx.x;
    float acc0 = 0.f, acc1 = 0.f, acc2 = 0.f, msum = 0.f;
    for (int s = 0; s < S; s++) {
        const float m = masks[(size_t)t * S + s];
        msum += m;
        const float* row = seq + (size_t)(b * S + s) * 768;
        acc0 += m * row[tid];
        acc1 += m * row[tid + 256];
        acc2 += m * row[tid + 512];
    }
    const float inv = 1.f / fmaxf(msum, 1e-9f);
    emb[(size_t)t * 768 + tid]       = acc0 * inv;
    emb[(size_t)t * 768 + tid + 256] = acc1 * inv;
    emb[(size_t)t * 768 + tid + 512] = acc2 * inv;
}

// ---------------- projection head ----------------------------------------------
__global__ __launch_bounds__(256)
void proj_kernel(const float* __restrict__ emb, const float* __restrict__ pW1,
                 const float* __restrict__ pb1, const float* __restrict__ pW2,
                 const float* __restrict__ pb2, float* __restrict__ out)
{
    const int t = blockIdx.x;
    const int tid = threadIdx.x;
    __shared__ float e[768];
    __shared__ float hdn[768];
    __shared__ float o[128];
    __shared__ float red[256];
    for (int d = tid; d < 768; d += 256) e[d] = emb[(size_t)t * 768 + d];
    __syncthreads();
    for (int j = tid; j < 768; j += 256) {
        float acc = pb1[j];
        for (int d = 0; d < 768; d++) acc += e[d] * pW1[(size_t)d * 768 + j];
        hdn[j] = fmaxf(acc, 0.f);
    }
    __syncthreads();
    if (tid < 128) {
        float acc = pb2[tid];
        for (int j = 0; j < 768; j++) acc += hdn[j] * pW2[(size_t)j * 128 + tid];
        o[tid] = acc;
    }
    __syncthreads();
    red[tid] = (tid < 128) ? o[tid] * o[tid] : 0.f;
    __syncthreads();
    for (int st = 128; st > 0; st >>= 1) { if (tid < st) red[tid] += red[tid + st]; __syncthreads(); }
    const float inv = 1.f / fmaxf(sqrtf(red[0]), 1e-12f);
    if (tid < 128) out[(size_t)t * 128 + tid] = o[tid] * inv;
}

// ---------------- driver ----------------------------------------------------------
extern "C" void kernel_launch(void* const* d_in, const int* in_sizes, int n_in,
                              void* d_out, int out_size)
{
    const int*   doc_ids   = (const int*)d_in[0];
    const int*   doc_mask  = (const int*)d_in[1];
    const int*   sum_ids   = (const int*)d_in[2];
    const int*   sum_mask  = (const int*)d_in[3];
    const float* og_masks  = (const float*)d_in[4];
    const float* llm_masks = (const float*)d_in[5];
    const int*   sidx      = (const int*)d_in[6];
    const float* word_emb  = (const float*)d_in[7];
    const float* pos_emb   = (const float*)d_in[8];
    const float* tt_emb    = (const float*)d_in[9];
    const float* ln_emb_g  = (const float*)d_in[10];
    const float* ln_emb_b  = (const float*)d_in[11];
    const float* Wq = (const float*)d_in[12];
    const float* bq = (const float*)d_in[13];
    const float* Wk = (const float*)d_in[14];
    const float* bk = (const float*)d_in[15];
    const float* Wv = (const float*)d_in[16];
    const float* bv = (const float*)d_in[17];
    const float* Wo = (const float*)d_in[18];
    const float* bo = (const float*)d_in[19];
    const float* ln1_g = (const float*)d_in[20];
    const float* ln1_b = (const float*)d_in[21];
    const float* W1 = (const float*)d_in[22];
    const float* b1 = (const float*)d_in[23];
    const float* W2 = (const float*)d_in[24];
    const float* b2 = (const float*)d_in[25];
    const float* ln2_g = (const float*)d_in[26];
    const float* ln2_b = (const float*)d_in[27];
    const float* pW1 = (const float*)d_in[28];
    const float* pb1 = (const float*)d_in[29];
    const float* pW2 = (const float*)d_in[30];
    const float* pb2 = (const float*)d_in[31];
    float* out = (float*)d_out;

    float *x, *qkv, *tmp, *emb, *bqkv;
    __nv_bfloat16 *xs, *as_, *hs, *wqkv3, *wo3, *w13, *w23;
    cudaGetSymbolAddress((void**)&x, g_x);
    cudaGetSymbolAddress((void**)&qkv, g_qkv);
    cudaGetSymbolAddress((void**)&tmp, g_t);
    cudaGetSymbolAddress((void**)&emb, g_emb);
    cudaGetSymbolAddress((void**)&bqkv, g_bqkv);
    cudaGetSymbolAddress((void**)&xs, g_xs);
    cudaGetSymbolAddress((void**)&as_, g_as);
    cudaGetSymbolAddress((void**)&hs, g_hs);
    cudaGetSymbolAddress((void**)&wqkv3, g_wqkv3);
    cudaGetSymbolAddress((void**)&wo3, g_wo3);
    cudaGetSymbolAddress((void**)&w13, g_w13);
    cudaGetSymbolAddress((void**)&w23, g_w23);

    cudaFuncSetAttribute(gemm_bf16x3<0>, cudaFuncAttributeMaxDynamicSharedMemorySize, GEMM_SMEM);
    cudaFuncSetAttribute(gemm_bf16x3<1>, cudaFuncAttributeMaxDynamicSharedMemorySize, GEMM_SMEM);

    // one-time (per launch) weight conversion to bf16x3 layouts
    conv_qkv_kernel<<<dim3(6912, 12), 256>>>(Wq, Wk, Wv, bq, bk, bv, wqkv3, bqkv);
    conv_w_kernel<<<dim3(2304, 12), 256>>>(Wo, wo3, 768, 768);
    conv_w_kernel<<<dim3(9216, 12), 256>>>(W1, w13, 768, 3072);
    conv_w_kernel<<<dim3(9216, 12), 256>>>(W2, w23, 3072, 768);

    auto encode = [&](const int* ids, const int* amask, int B, int S) {
        const int T = B * S;
        embed_ln_kernel<<<T, 256>>>(ids, word_emb, pos_emb, tt_emb, ln_emb_g, ln_emb_b, x, xs, S);
        for (int l = 0; l < 12; l++) {
            dim3 g768(6, T / 128), g2304(18, T / 128), g3072(24, T / 128);
            gemm_bf16x3<0><<<g2304, 256, GEMM_SMEM>>>(xs, wqkv3 + (size_t)l * 2304 * 2304,
                                                      bqkv + l * 2304, qkv, T, 2304, 768);
            attn_kernel<<<dim3(S / 4, B, 12), 128>>>(qkv, amask, as_, S);
            gemm_bf16x3<0><<<g768, 256, GEMM_SMEM>>>(as_, wo3 + (size_t)l * 2304 * 768,
                                                     bo + l * 768, tmp, T, 768, 768);
            add_ln_kernel<<<T, 256>>>(x, tmp, ln1_g + l * 768, ln1_b + l * 768, xs);
            gemm_bf16x3<1><<<g3072, 256, GEMM_SMEM>>>(xs, w13 + (size_t)l * 2304 * 3072,
                                                      b1 + l * 3072, hs, T, 3072, 768);
            gemm_bf16x3<0><<<g768, 256, GEMM_SMEM>>>(hs, w23 + (size_t)l * 9216 * 768,
                                                     b2 + l * 768, tmp, T, 768, 3072);
            add_ln_kernel<<<T, 256>>>(x, tmp, ln2_g + l * 768, ln2_b + l * 768, xs);
        }
    };

    // doc pass -> human embeddings
    encode(doc_ids, doc_mask, 2, 2048);
    span_pool_kernel<<<16, 256>>>(x, og_masks, sidx, emb, 2048);
    proj_kernel<<<16, 256>>>(emb, pW1, pb1, pW2, pb2, out);

    // summary pass -> llm embeddings
    encode(sum_ids, sum_mask, 2, 512);
    span_pool_kernel<<<16, 256>>>(x, llm_masks, sidx, emb, 512);
    proj_kernel<<<16, 256>>>(emb, pW1, pb1, pW2, pb2, out + 16 * 128);
}

// round 9
// speedup vs baseline: 1.8651x; 1.0233x over previous
#include <cuda_runtime.h>
#include <cuda_bf16.h>
#include <stdint.h>
#include <math.h>

#define WIN 256

// ---------------- scratch (device globals; no allocation allowed) -------------
__device__ float g_x[4096 * 768];
__device__ float g_qkv[4096 * 2304];
__device__ float g_t[4096 * 768];
__device__ float g_emb[16 * 768];
__device__ float g_bqkv[12 * 2304];
// split activations: [M][2K] bf16, cols [0,K)=hi, [K,2K)=lo
__device__ __nv_bfloat16 g_xs[4096 * 1536];
__device__ __nv_bfloat16 g_as[4096 * 1536];
__device__ __nv_bfloat16 g_hs[(size_t)4096 * 6144];
// bf16x3 weight layouts: [3K][N] per layer (rows [0,K)=hi, [K,2K)=lo, [2K,3K)=hi)
__device__ __nv_bfloat16 g_wqkv3[(size_t)12 * 2304 * 2304];
__device__ __nv_bfloat16 g_wo3[(size_t)12 * 2304 * 768];
__device__ __nv_bfloat16 g_w13[(size_t)12 * 2304 * 3072];
__device__ __nv_bfloat16 g_w23[(size_t)12 * 9216 * 768];

// GEMM smem: 5 stages of (A 128x40 + B 32x136) bf16
#define GEMM_STAGES 5
#define GEMM_SMEM (GEMM_STAGES * (128 * 40 + 32 * 136) * 2)

// ---------------- weight conversion: W[K][N] fp32 -> [3K][N] bf16 (hi,lo,hi) ----
__global__ __launch_bounds__(256)
void conv_w_kernel(const float* __restrict__ W, __nv_bfloat16* __restrict__ W3,
                   int K, int N)
{
    const int l = blockIdx.y;
    const size_t i = (size_t)blockIdx.x * 256 + threadIdx.x;   // < K*N
    const float w = W[(size_t)l * K * N + i];
    const __nv_bfloat16 hi = __float2bfloat16_rn(w);
    const __nv_bfloat16 lo = __float2bfloat16_rn(w - __bfloat162float(hi));
    __nv_bfloat16* O = W3 + (size_t)l * 3 * K * N;
    O[i] = hi;
    O[(size_t)K * N + i] = lo;
    O[(size_t)2 * K * N + i] = hi;
}

// ---------------- QKV pack + convert: Wq|Wk|Wv -> [3*768][2304] bf16 ------------
__global__ __launch_bounds__(256)
void conv_qkv_kernel(const float* __restrict__ Wq, const float* __restrict__ Wk,
                     const float* __restrict__ Wv, const float* __restrict__ bq,
                     const float* __restrict__ bk, const float* __restrict__ bv,
                     __nv_bfloat16* __restrict__ W3, float* __restrict__ bias)
{
    const int l = blockIdx.y;
    const int i = blockIdx.x * 256 + threadIdx.x;   // < 768*2304
    const int k = i / 2304, n = i % 2304;
    const float* src = (n < 768) ? Wq : (n < 1536) ? Wk : Wv;
    const int nn = (n < 768) ? n : (n < 1536) ? n - 768 : n - 1536;
    const float w = src[((size_t)l * 768 + k) * 768 + nn];
    const __nv_bfloat16 hi = __float2bfloat16_rn(w);
    const __nv_bfloat16 lo = __float2bfloat16_rn(w - __bfloat162float(hi));
    __nv_bfloat16* O = W3 + (size_t)l * 2304 * 2304;
    O[(size_t)k * 2304 + n] = hi;
    O[(size_t)(768 + k) * 2304 + n] = lo;
    O[(size_t)(1536 + k) * 2304 + n] = hi;
    if (i < 2304) {
        const float* bsrc = (i < 768) ? bq : (i < 1536) ? bk : bv;
        const int bn = (i < 768) ? i : (i < 1536) ? i - 768 : i - 1536;
        bias[l * 2304 + i] = bsrc[(size_t)l * 768 + bn];
    }
}

// ---------------- bf16x3 tensor-core GEMM, cp.async 5-stage ---------------------
// C[M,N] = Xs[M,2K](bf16 hi|lo) @ B3[3K,N](bf16) + bias
// seg0: Whi*xhi, seg1: Wlo*xhi, seg2: Whi*xlo.
// OUTMODE 0: fp32 C[M][N].  OUTMODE 1: gelu, then bf16 split out C[M][2N].
template <int OUTMODE>
__global__ __launch_bounds__(256, 2)
void gemm_bf16x3(const __nv_bfloat16* __restrict__ A2, const __nv_bfloat16* __restrict__ B3,
                 const float* __restrict__ bias, void* __restrict__ Cout,
                 int M, int N, int K)
{
    extern __shared__ __align__(16) unsigned char smem_raw[];
    __nv_bfloat16* As = (__nv_bfloat16*)smem_raw;                                  // [5][128][40]
    __nv_bfloat16* Bs = (__nv_bfloat16*)(smem_raw + GEMM_STAGES * 128 * 40 * 2);   // [5][32][136]

    const int tid  = threadIdx.x;
    const int lane = tid & 31, warp = tid >> 5;
    const int wm = warp >> 2, wn = warp & 3;
    const int row0 = blockIdx.y * 128, col0 = blockIdx.x * 128;
    const int nk = (3 * K) >> 5;

    const int arow = tid >> 1;          // 0..127
    const int acol = (tid & 1) * 16;    // 0 or 16 (halfs)
    const int brow = tid >> 3;          // 0..31
    const int bcol = (tid & 7) * 16;    // 0..112 (halfs)

    auto issue = [&](int kt) {
        const int stg = kt % GEMM_STAGES;
        const int kk = kt * 32;
        const int seg = kk / K;
        const int acolg = (seg == 2 ? K : 0) + (kk - seg * K);
        const __nv_bfloat16* Ag = A2 + (size_t)(row0 + arow) * (2 * K) + acolg + acol;
        const __nv_bfloat16* Bg = B3 + (size_t)(kk + brow) * N + col0 + bcol;
        const unsigned as_addr = (unsigned)__cvta_generic_to_shared(As + (stg * 128 + arow) * 40 + acol);
        const unsigned bs_addr = (unsigned)__cvta_generic_to_shared(Bs + (stg * 32 + brow) * 136 + bcol);
        asm volatile("cp.async.cg.shared.global [%0], [%1], 16;" :: "r"(as_addr), "l"(Ag));
        asm volatile("cp.async.cg.shared.global [%0], [%1], 16;" :: "r"(as_addr + 16), "l"(Ag + 8));
        asm volatile("cp.async.cg.shared.global [%0], [%1], 16;" :: "r"(bs_addr), "l"(Bg));
        asm volatile("cp.async.cg.shared.global [%0], [%1], 16;" :: "r"(bs_addr + 16), "l"(Bg + 8));
        asm volatile("cp.async.commit_group;");
    };

    float acc[4][4][4];
#pragma unroll
    for (int mi = 0; mi < 4; mi++)
#pragma unroll
        for (int nj = 0; nj < 4; nj++)
#pragma unroll
            for (int q = 0; q < 4; q++) acc[mi][nj][q] = 0.f;

    issue(0);
    issue(1);
    issue(2);
    issue(3);

    for (int kt = 0; kt < nk; kt++) {
        asm volatile("cp.async.wait_group 3;");
        __syncthreads();
        if (kt + 4 < nk) issue(kt + 4);
        else asm volatile("cp.async.commit_group;");

        const int stg = kt % GEMM_STAGES;
        const unsigned aBase = (unsigned)__cvta_generic_to_shared(As + stg * 128 * 40);
        const unsigned bBase = (unsigned)__cvta_generic_to_shared(Bs + stg * 32 * 136);
#pragma unroll
        for (int ks = 0; ks < 2; ks++) {
            unsigned afrag[4][4];
            unsigned bfrag[4][2];
#pragma unroll
            for (int mi = 0; mi < 4; mi++) {
                const int r = wm * 64 + mi * 16 + (lane & 15);
                const int c = ks * 16 + (lane >> 4) * 8;
                const unsigned addr = aBase + (unsigned)(r * 40 + c) * 2u;
                asm volatile("ldmatrix.sync.aligned.m8n8.x4.shared.b16 {%0,%1,%2,%3}, [%4];"
                             : "=r"(afrag[mi][0]), "=r"(afrag[mi][1]),
                               "=r"(afrag[mi][2]), "=r"(afrag[mi][3])
                             : "r"(addr));
            }
#pragma unroll
            for (int nj = 0; nj < 4; nj++) {
                const int kr = ks * 16 + (lane & 15);
                const int c  = wn * 32 + nj * 8;
                const unsigned addr = bBase + (unsigned)(kr * 136 + c) * 2u;
                asm volatile("ldmatrix.sync.aligned.m8n8.x2.trans.shared.b16 {%0,%1}, [%2];"
                             : "=r"(bfrag[nj][0]), "=r"(bfrag[nj][1])
                             : "r"(addr));
            }
#pragma unroll
            for (int mi = 0; mi < 4; mi++)
#pragma unroll
                for (int nj = 0; nj < 4; nj++)
                    asm volatile("mma.sync.aligned.m16n8k16.row.col.f32.bf16.bf16.f32 "
                                 "{%0,%1,%2,%3}, {%4,%5,%6,%7}, {%8,%9}, {%0,%1,%2,%3};"
                                 : "+f"(acc[mi][nj][0]), "+f"(acc[mi][nj][1]),
                                   "+f"(acc[mi][nj][2]), "+f"(acc[mi][nj][3])
                                 : "r"(afrag[mi][0]), "r"(afrag[mi][1]),
                                   "r"(afrag[mi][2]), "r"(afrag[mi][3]),
                                   "r"(bfrag[nj][0]), "r"(bfrag[nj][1]));
        }
    }

#pragma unroll
    for (int mi = 0; mi < 4; mi++) {
        const int r = row0 + wm * 64 + mi * 16 + (lane >> 2);
#pragma unroll
        for (int nj = 0; nj < 4; nj++) {
            const int c = col0 + wn * 32 + nj * 8 + (lane & 3) * 2;
            const float2 b2 = *(const float2*)&bias[c];
            float o0 = acc[mi][nj][0] + b2.x;
            float o1 = acc[mi][nj][1] + b2.y;
            float o2 = acc[mi][nj][2] + b2.x;
            float o3 = acc[mi][nj][3] + b2.y;
            if (OUTMODE == 0) {
                float* C = (float*)Cout;
                *(float2*)&C[(size_t)r * N + c]       = make_float2(o0, o1);
                *(float2*)&C[(size_t)(r + 8) * N + c] = make_float2(o2, o3);
            } else {
                o0 = 0.5f * o0 * (1.f + erff(o0 * 0.70710678118654752f));
                o1 = 0.5f * o1 * (1.f + erff(o1 * 0.70710678118654752f));
                o2 = 0.5f * o2 * (1.f + erff(o2 * 0.70710678118654752f));
                o3 = 0.5f * o3 * (1.f + erff(o3 * 0.70710678118654752f));
                __nv_bfloat16* C2 = (__nv_bfloat16*)Cout;
                const size_t rs = (size_t)2 * N;
                __nv_bfloat162 hp, lp;
                hp.x = __float2bfloat16_rn(o0);
                hp.y = __float2bfloat16_rn(o1);
                lp.x = __float2bfloat16_rn(o0 - __bfloat162float(hp.x));
                lp.y = __float2bfloat16_rn(o1 - __bfloat162float(hp.y));
                *(__nv_bfloat162*)&C2[(size_t)r * rs + c]     = hp;
                *(__nv_bfloat162*)&C2[(size_t)r * rs + N + c] = lp;
                hp.x = __float2bfloat16_rn(o2);
                hp.y = __float2bfloat16_rn(o3);
                lp.x = __float2bfloat16_rn(o2 - __bfloat162float(hp.x));
                lp.y = __float2bfloat16_rn(o3 - __bfloat162float(hp.y));
                *(__nv_bfloat162*)&C2[(size_t)(r + 8) * rs + c]     = hp;
                *(__nv_bfloat162*)&C2[(size_t)(r + 8) * rs + N + c] = lp;
            }
        }
    }
}

// ---------------- split write helper (device inline) ----------------------------
__device__ __forceinline__ void write_split(__nv_bfloat16* xs, size_t row, int col, float v)
{
    const __nv_bfloat16 hi = __float2bfloat16_rn(v);
    const __nv_bfloat16 lo = __float2bfloat16_rn(v - __bfloat162float(hi));
    xs[row * 1536 + col] = hi;
    xs[row * 1536 + 768 + col] = lo;
}

// ---------------- embedding + layernorm (writes x fp32 + xs split) --------------
__global__ __launch_bounds__(256)
void embed_ln_kernel(const int* __restrict__ ids, const float* __restrict__ we,
                     const float* __restrict__ pe, const float* __restrict__ tt,
                     const float* __restrict__ g, const float* __restrict__ bta,
                     float* __restrict__ x, __nv_bfloat16* __restrict__ xs, int S)
{
    const int tok = blockIdx.x;
    const int s   = tok % S;
    const int tid = threadIdx.x;
    const int id  = ids[tok];
    __shared__ float red[256];
    float v[3];
    float sum = 0.f;
#pragma unroll
    for (int i = 0; i < 3; i++) {
        const int dd = tid + i * 256;
        float t = we[(size_t)id * 768 + dd] + pe[(size_t)(s + 2) * 768 + dd] + tt[dd];
        v[i] = t;
        sum += t;
    }
    red[tid] = sum;
    __syncthreads();
    for (int st = 128; st > 0; st >>= 1) { if (tid < st) red[tid] += red[tid + st]; __syncthreads(); }
    const float mu = red[0] * (1.f / 768.f);
    __syncthreads();
    float vs = 0.f;
#pragma unroll
    for (int i = 0; i < 3; i++) { float dv = v[i] - mu; vs += dv * dv; }
    red[tid] = vs;
    __syncthreads();
    for (int st = 128; st > 0; st >>= 1) { if (tid < st) red[tid] += red[tid + st]; __syncthreads(); }
    const float rstd = rsqrtf(red[0] * (1.f / 768.f) + 1e-5f);
#pragma unroll
    for (int i = 0; i < 3; i++) {
        const int dd = tid + i * 256;
        const float o = (v[i] - mu) * rstd * g[dd] + bta[dd];
        x[(size_t)tok * 768 + dd] = o;
        write_split(xs, (size_t)tok, dd, o);
    }
}

// ---------------- x = LN(x + delta), writes x fp32 + xs split -------------------
__global__ __launch_bounds__(256)
void add_ln_kernel(float* __restrict__ x, const float* __restrict__ dlt,
                   const float* __restrict__ g, const float* __restrict__ bta,
                   __nv_bfloat16* __restrict__ xs)
{
    const int tok = blockIdx.x;
    const int tid = threadIdx.x;
    __shared__ float red[256];
    const size_t base = (size_t)tok * 768;
    float v[3];
    float sum = 0.f;
#pragma unroll
    for (int i = 0; i < 3; i++) {
        const int dd = tid + i * 256;
        float t = x[base + dd] + dlt[base + dd];
        v[i] = t;
        sum += t;
    }
    red[tid] = sum;
    __syncthreads();
    for (int st = 128; st > 0; st >>= 1) { if (tid < st) red[tid] += red[tid + st]; __syncthreads(); }
    const float mu = red[0] * (1.f / 768.f);
    __syncthreads();
    float vs = 0.f;
#pragma unroll
    for (int i = 0; i < 3; i++) { float dv = v[i] - mu; vs += dv * dv; }
    red[tid] = vs;
    __syncthreads();
    for (int st = 128; st > 0; st >>= 1) { if (tid < st) red[tid] += red[tid + st]; __syncthreads(); }
    const float rstd = rsqrtf(red[0] * (1.f / 768.f) + 1e-5f);
#pragma unroll
    for (int i = 0; i < 3; i++) {
        const int dd = tid + i * 256;
        const float o = (v[i] - mu) * rstd * g[dd] + bta[dd];
        x[base + dd] = o;
        write_split(xs, (size_t)tok, dd, o);
    }
}

// ---------------- sliding-window attention, 8 queries per block -----------------
// Block (256 thr = 8 warps) handles (b, h, 8 queries). QKV rows of 2304 floats.
// Output written as bf16 split [M][1536] (feeds the Wo GEMM).
__global__ __launch_bounds__(256)
void attn_kernel(const float* __restrict__ QKV, const int* __restrict__ amask,
                 __nv_bfloat16* __restrict__ AS, int S)
{
    const int q0 = blockIdx.x * 8, b = blockIdx.y, h = blockIdx.z;
    const int tid = threadIdx.x, lane = tid & 31, warp = tid >> 5;
    const int g = lane >> 4, li = lane & 15;
    __shared__ float sc[8][528];
    __shared__ float redm[16][8];
    __shared__ float reds[8][8];
    __shared__ float obuf[8][8][64];

    const size_t RS = 2304;
    const size_t base = (size_t)b * S * RS + (size_t)h * 64;
    const float* Q  = QKV + base;
    const float* Kp = QKV + base + 768;
    const float* Vp = QKV + base + 1536;

    int j0 = q0 - WIN; if (j0 < 0) j0 = 0;
    int j1 = q0 + 7 + WIN; if (j1 > S - 1) j1 = S - 1;
    const int nk = j1 - j0 + 1;

    float4 q4[8];
#pragma unroll
    for (int qi = 0; qi < 8; qi++)
        q4[qi] = *(const float4*)&Q[(size_t)(q0 + qi) * RS + 4 * li];

    // scores: 2 keys per warp iteration (16-lane groups), 8 queries each
    float lmax[8] = {-1e30f, -1e30f, -1e30f, -1e30f, -1e30f, -1e30f, -1e30f, -1e30f};
    for (int jj = warp * 2 + g; jj < nk; jj += 16) {
        const int j = j0 + jj;
        const float4 k4 = *(const float4*)&Kp[(size_t)j * RS + 4 * li];
        float p[8];
#pragma unroll
        for (int qi = 0; qi < 8; qi++)
            p[qi] = q4[qi].x * k4.x + q4[qi].y * k4.y + q4[qi].z * k4.z + q4[qi].w * k4.w;
#pragma unroll
        for (int off = 8; off; off >>= 1)
#pragma unroll
            for (int qi = 0; qi < 8; qi++)
                p[qi] += __shfl_xor_sync(0xffffffffu, p[qi], off);
        const int mok = amask[b * S + j];
#pragma unroll
        for (int qi = 0; qi < 8; qi++) {
            const int sq = q0 + qi;
            const bool valid = mok && (j >= sq - WIN) && (j <= sq + WIN);
            const float val = valid ? p[qi] * 0.125f : -1e9f;
            if (li == qi) sc[qi][jj] = val;
            lmax[qi] = fmaxf(lmax[qi], val);
        }
    }
    if (li == 0) {
#pragma unroll
        for (int qi = 0; qi < 8; qi++) redm[warp * 2 + g][qi] = lmax[qi];
    }
    __syncthreads();
    float m[8];
#pragma unroll
    for (int qi = 0; qi < 8; qi++) {
        float mm = redm[0][qi];
#pragma unroll
        for (int w = 1; w < 16; w++) mm = fmaxf(mm, redm[w][qi]);
        m[qi] = mm;
    }

    // exp + sums
    float lsum[8] = {0.f, 0.f, 0.f, 0.f, 0.f, 0.f, 0.f, 0.f};
    for (int jj = tid; jj < nk; jj += 256) {
#pragma unroll
        for (int qi = 0; qi < 8; qi++) {
            const float e = __expf(sc[qi][jj] - m[qi]);
            sc[qi][jj] = e;
            lsum[qi] += e;
        }
    }
#pragma unroll
    for (int off = 16; off; off >>= 1)
#pragma unroll
        for (int qi = 0; qi < 8; qi++)
            lsum[qi] += __shfl_xor_sync(0xffffffffu, lsum[qi], off);
    if (lane == 0) {
#pragma unroll
        for (int qi = 0; qi < 8; qi++) reds[warp][qi] = lsum[qi];
    }
    __syncthreads();
    float inv[8];
#pragma unroll
    for (int qi = 0; qi < 8; qi++)
        inv[qi] = 1.f / (reds[0][qi] + reds[1][qi] + reds[2][qi] + reds[3][qi] +
                         reds[4][qi] + reds[5][qi] + reds[6][qi] + reds[7][qi]);

    // PV: warps split keys, each accumulates all 8 queries (lanes = 2 dims)
    float ax[8] = {0.f, 0.f, 0.f, 0.f, 0.f, 0.f, 0.f, 0.f};
    float ay[8] = {0.f, 0.f, 0.f, 0.f, 0.f, 0.f, 0.f, 0.f};
    for (int jj = warp; jj < nk; jj += 8) {
        const float2 v2 = *(const float2*)&Vp[(size_t)(j0 + jj) * RS + 2 * lane];
#pragma unroll
        for (int qi = 0; qi < 8; qi++) {
            const float p = sc[qi][jj];
            ax[qi] += p * v2.x;
            ay[qi] += p * v2.y;
        }
    }
#pragma unroll
    for (int qi = 0; qi < 8; qi++) {
        obuf[warp][qi][2 * lane]     = ax[qi];
        obuf[warp][qi][2 * lane + 1] = ay[qi];
    }
    __syncthreads();

    // warp w finalizes query w
    {
        const int qi = warp;
        float vx = 0.f, vy = 0.f;
#pragma unroll
        for (int w = 0; w < 8; w++) {
            vx += obuf[w][qi][2 * lane];
            vy += obuf[w][qi][2 * lane + 1];
        }
        vx *= inv[qi];
        vy *= inv[qi];
        const size_t row = (size_t)b * S + q0 + qi;
        const int col = h * 64 + 2 * lane;
        __nv_bfloat162 hp, lp;
        hp.x = __float2bfloat16_rn(vx);
        hp.y = __float2bfloat16_rn(vy);
        lp.x = __float2bfloat16_rn(vx - __bfloat162float(hp.x));
        lp.y = __float2bfloat16_rn(vy - __bfloat162float(hp.y));
        *(__nv_bfloat162*)&AS[row * 1536 + col]       = hp;
        *(__nv_bfloat162*)&AS[row * 1536 + 768 + col] = lp;
    }
}

// ---------------- span pooling ---------------------------------------------------
__global__ __launch_bounds__(256)
void span_pool_kernel(const float* __restrict__ seq, const float* __restrict__ masks,
                      const int* __restrict__ sidx, float* __restrict__ emb, int S)
{
    const int t = blockIdx.x;
    const int b = sidx[t];
    const int tid = threadIdx.x;
    float acc0 = 0.f, acc1 = 0.f, acc2 = 0.f, msum = 0.f;
    for (int s = 0; s < S; s++) {
        const float m = masks[(size_t)t * S + s];
        msum += m;
        const float* row = seq + (size_t)(b * S + s) * 768;
        acc0 += m * row[tid];
        acc1 += m * row[tid + 256];
        acc2 += m * row[tid + 512];
    }
    const float inv = 1.f / fmaxf(msum, 1e-9f);
    emb[(size_t)t * 768 + tid]       = acc0 * inv;
    emb[(size_t)t * 768 + tid + 256] = acc1 * inv;
    emb[(size_t)t * 768 + tid + 512] = acc2 * inv;
}

// ---------------- projection head ----------------------------------------------
__global__ __launch_bounds__(256)
void proj_kernel(const float* __restrict__ emb, const float* __restrict__ pW1,
                 const float* __restrict__ pb1, const float* __restrict__ pW2,
                 const float* __restrict__ pb2, float* __restrict__ out)
{
    const int t = blockIdx.x;
    const int tid = threadIdx.x;
    __shared__ float e[768];
    __shared__ float hdn[768];
    __shared__ float o[128];
    __shared__ float red[256];
    for (int d = tid; d < 768; d += 256) e[d] = emb[(size_t)t * 768 + d];
    __syncthreads();
    for (int j = tid; j < 768; j += 256) {
        float acc = pb1[j];
        for (int d = 0; d < 768; d++) acc += e[d] * pW1[(size_t)d * 768 + j];
        hdn[j] = fmaxf(acc, 0.f);
    }
    __syncthreads();
    if (tid < 128) {
        float acc = pb2[tid];
        for (int j = 0; j < 768; j++) acc += hdn[j] * pW2[(size_t)j * 128 + tid];
        o[tid] = acc;
    }
    __syncthreads();
    red[tid] = (tid < 128) ? o[tid] * o[tid] : 0.f;
    __syncthreads();
    for (int st = 128; st > 0; st >>= 1) { if (tid < st) red[tid] += red[tid + st]; __syncthreads(); }
    const float inv = 1.f / fmaxf(sqrtf(red[0]), 1e-12f);
    if (tid < 128) out[(size_t)t * 128 + tid] = o[tid] * inv;
}

// ---------------- driver ----------------------------------------------------------
extern "C" void kernel_launch(void* const* d_in, const int* in_sizes, int n_in,
                              void* d_out, int out_size)
{
    const int*   doc_ids   = (const int*)d_in[0];
    const int*   doc_mask  = (const int*)d_in[1];
    const int*   sum_ids   = (const int*)d_in[2];
    const int*   sum_mask  = (const int*)d_in[3];
    const float* og_masks  = (const float*)d_in[4];
    const float* llm_masks = (const float*)d_in[5];
    const int*   sidx      = (const int*)d_in[6];
    const float* word_emb  = (const float*)d_in[7];
    const float* pos_emb   = (const float*)d_in[8];
    const float* tt_emb    = (const float*)d_in[9];
    const float* ln_emb_g  = (const float*)d_in[10];
    const float* ln_emb_b  = (const float*)d_in[11];
    const float* Wq = (const float*)d_in[12];
    const float* bq = (const float*)d_in[13];
    const float* Wk = (const float*)d_in[14];
    const float* bk = (const float*)d_in[15];
    const float* Wv = (const float*)d_in[16];
    const float* bv = (const float*)d_in[17];
    const float* Wo = (const float*)d_in[18];
    const float* bo = (const float*)d_in[19];
    const float* ln1_g = (const float*)d_in[20];
    const float* ln1_b = (const float*)d_in[21];
    const float* W1 = (const float*)d_in[22];
    const float* b1 = (const float*)d_in[23];
    const float* W2 = (const float*)d_in[24];
    const float* b2 = (const float*)d_in[25];
    const float* ln2_g = (const float*)d_in[26];
    const float* ln2_b = (const float*)d_in[27];
    const float* pW1 = (const float*)d_in[28];
    const float* pb1 = (const float*)d_in[29];
    const float* pW2 = (const float*)d_in[30];
    const float* pb2 = (const float*)d_in[31];
    float* out = (float*)d_out;

    float *x, *qkv, *tmp, *emb, *bqkv;
    __nv_bfloat16 *xs, *as_, *hs, *wqkv3, *wo3, *w13, *w23;
    cudaGetSymbolAddress((void**)&x, g_x);
    cudaGetSymbolAddress((void**)&qkv, g_qkv);
    cudaGetSymbolAddress((void**)&tmp, g_t);
    cudaGetSymbolAddress((void**)&emb, g_emb);
    cudaGetSymbolAddress((void**)&bqkv, g_bqkv);
    cudaGetSymbolAddress((void**)&xs, g_xs);
    cudaGetSymbolAddress((void**)&as_, g_as);
    cudaGetSymbolAddress((void**)&hs, g_hs);
    cudaGetSymbolAddress((void**)&wqkv3, g_wqkv3);
    cudaGetSymbolAddress((void**)&wo3, g_wo3);
    cudaGetSymbolAddress((void**)&w13, g_w13);
    cudaGetSymbolAddress((void**)&w23, g_w23);

    cudaFuncSetAttribute(gemm_bf16x3<0>, cudaFuncAttributeMaxDynamicSharedMemorySize, GEMM_SMEM);
    cudaFuncSetAttribute(gemm_bf16x3<1>, cudaFuncAttributeMaxDynamicSharedMemorySize, GEMM_SMEM);

    // one-time (per launch) weight conversion to bf16x3 layouts
    conv_qkv_kernel<<<dim3(6912, 12), 256>>>(Wq, Wk, Wv, bq, bk, bv, wqkv3, bqkv);
    conv_w_kernel<<<dim3(2304, 12), 256>>>(Wo, wo3, 768, 768);
    conv_w_kernel<<<dim3(9216, 12), 256>>>(W1, w13, 768, 3072);
    conv_w_kernel<<<dim3(9216, 12), 256>>>(W2, w23, 3072, 768);

    auto encode = [&](const int* ids, const int* amask, int B, int S) {
        const int T = B * S;
        embed_ln_kernel<<<T, 256>>>(ids, word_emb, pos_emb, tt_emb, ln_emb_g, ln_emb_b, x, xs, S);
        for (int l = 0; l < 12; l++) {
            dim3 g768(6, T / 128), g2304(18, T / 128), g3072(24, T / 128);
            gemm_bf16x3<0><<<g2304, 256, GEMM_SMEM>>>(xs, wqkv3 + (size_t)l * 2304 * 2304,
                                                      bqkv + l * 2304, qkv, T, 2304, 768);
            attn_kernel<<<dim3(S / 8, B, 12), 256>>>(qkv, amask, as_, S);
            gemm_bf16x3<0><<<g768, 256, GEMM_SMEM>>>(as_, wo3 + (size_t)l * 2304 * 768,
                                                     bo + l * 768, tmp, T, 768, 768);
            add_ln_kernel<<<T, 256>>>(x, tmp, ln1_g + l * 768, ln1_b + l * 768, xs);
            gemm_bf16x3<1><<<g3072, 256, GEMM_SMEM>>>(xs, w13 + (size_t)l * 2304 * 3072,
                                                      b1 + l * 3072, hs, T, 3072, 768);
            gemm_bf16x3<0><<<g768, 256, GEMM_SMEM>>>(hs, w23 + (size_t)l * 9216 * 768,
                                                     b2 + l * 768, tmp, T, 768, 3072);
            add_ln_kernel<<<T, 256>>>(x, tmp, ln2_g + l * 768, ln2_b + l * 768, xs);
        }
    };

    // doc pass -> human embeddings
    encode(doc_ids, doc_mask, 2, 2048);
    span_pool_kernel<<<16, 256>>>(x, og_masks, sidx, emb, 2048);
    proj_kernel<<<16, 256>>>(emb, pW1, pb1, pW2, pb2, out);

    // summary pass -> llm embeddings
    encode(sum_ids, sum_mask, 2, 512);
    span_pool_kernel<<<16, 256>>>(x, llm_masks, sidx, emb, 512);
    proj_kernel<<<16, 256>>>(emb, pW1, pb1, pW2, pb2, out + 16 * 128);
}

// round 10
// speedup vs baseline: 2.4279x; 1.3017x over previous
#include <cuda_runtime.h>
#include <cuda_fp16.h>
#include <stdint.h>
#include <math.h>

#define WIN 256

// ---------------- scratch (device globals; no allocation allowed) -------------
__device__ float g_x[4096 * 768];
__device__ float g_qkv[4096 * 2304];
__device__ float g_t[4096 * 768];
__device__ float g_emb[16 * 768];
__device__ float g_bqkv[12 * 2304];
// fp16 activations (single rounding)
__device__ __half g_xs[4096 * 768];
__device__ __half g_as[4096 * 768];
__device__ __half g_hs[(size_t)4096 * 3072];
// fp16x2 weight layouts: [2K][N] per layer (rows [0,K)=hi, [K,2K)=lo)
__device__ __half g_wqkv2[(size_t)12 * 1536 * 2304];
__device__ __half g_wo2[(size_t)12 * 1536 * 768];
__device__ __half g_w12[(size_t)12 * 1536 * 3072];
__device__ __half g_w22[(size_t)12 * 6144 * 768];

// GEMM smem: 5 stages of (A 128x40 + B 32x136) half
#define GEMM_STAGES 5
#define GEMM_SMEM (GEMM_STAGES * (128 * 40 + 32 * 136) * 2)

// ---------------- weight conversion: W[K][N] fp32 -> [2K][N] fp16 (hi,lo) -------
__global__ __launch_bounds__(256)
void conv_w_kernel(const float* __restrict__ W, __half* __restrict__ W2,
                   int K, int N)
{
    const int l = blockIdx.y;
    const size_t i = (size_t)blockIdx.x * 256 + threadIdx.x;   // < K*N
    const float w = W[(size_t)l * K * N + i];
    const __half hi = __float2half_rn(w);
    const __half lo = __float2half_rn(w - __half2float(hi));
    __half* O = W2 + (size_t)l * 2 * K * N;
    O[i] = hi;
    O[(size_t)K * N + i] = lo;
}

// ---------------- QKV pack + convert: Wq|Wk|Wv -> [2*768][2304] fp16 ------------
__global__ __launch_bounds__(256)
void conv_qkv_kernel(const float* __restrict__ Wq, const float* __restrict__ Wk,
                     const float* __restrict__ Wv, const float* __restrict__ bq,
                     const float* __restrict__ bk, const float* __restrict__ bv,
                     __half* __restrict__ W2, float* __restrict__ bias)
{
    const int l = blockIdx.y;
    const int i = blockIdx.x * 256 + threadIdx.x;   // < 768*2304
    const int k = i / 2304, n = i % 2304;
    const float* src = (n < 768) ? Wq : (n < 1536) ? Wk : Wv;
    const int nn = (n < 768) ? n : (n < 1536) ? n - 768 : n - 1536;
    const float w = src[((size_t)l * 768 + k) * 768 + nn];
    const __half hi = __float2half_rn(w);
    const __half lo = __float2half_rn(w - __half2float(hi));
    __half* O = W2 + (size_t)l * 1536 * 2304;
    O[(size_t)k * 2304 + n] = hi;
    O[(size_t)(768 + k) * 2304 + n] = lo;
    if (i < 2304) {
        const float* bsrc = (i < 768) ? bq : (i < 1536) ? bk : bv;
        const int bn = (i < 768) ? i : (i < 1536) ? i - 768 : i - 1536;
        bias[l * 2304 + i] = bsrc[(size_t)l * 768 + bn];
    }
}

// ---------------- fp16x2 tensor-core GEMM, cp.async 5-stage ---------------------
// C[M,N] = x~[M,K](fp16) @ W2[2K,N](fp16 hi|lo) + bias
// segment 0 rows: Whi vs x~, segment 1 rows: Wlo vs x~ (same A columns).
// OUTMODE 0: fp32 C[M][N].  OUTMODE 1: gelu, then fp16 out C[M][N].
template <int OUTMODE>
__global__ __launch_bounds__(256, 2)
void gemm_fp16x2(const __half* __restrict__ A1, const __half* __restrict__ B2,
                 const float* __restrict__ bias, void* __restrict__ Cout,
                 int M, int N, int K)
{
    extern __shared__ __align__(16) unsigned char smem_raw[];
    __half* As = (__half*)smem_raw;                                  // [5][128][40]
    __half* Bs = (__half*)(smem_raw + GEMM_STAGES * 128 * 40 * 2);   // [5][32][136]

    const int tid  = threadIdx.x;
    const int lane = tid & 31, warp = tid >> 5;
    const int wm = warp >> 2, wn = warp & 3;
    const int row0 = blockIdx.y * 128, col0 = blockIdx.x * 128;
    const int nk = (2 * K) >> 5;

    const int arow = tid >> 1;          // 0..127
    const int acol = (tid & 1) * 16;    // 0 or 16 (halfs)
    const int brow = tid >> 3;          // 0..31
    const int bcol = (tid & 7) * 16;    // 0..112 (halfs)

    auto issue = [&](int kt) {
        const int stg = kt % GEMM_STAGES;
        const int kk = kt * 32;
        const int acolg = (kk < K) ? kk : kk - K;   // same x~ columns for both segments
        const __half* Ag = A1 + (size_t)(row0 + arow) * K + acolg + acol;
        const __half* Bg = B2 + (size_t)(kk + brow) * N + col0 + bcol;
        const unsigned as_addr = (unsigned)__cvta_generic_to_shared(As + (stg * 128 + arow) * 40 + acol);
        const unsigned bs_addr = (unsigned)__cvta_generic_to_shared(Bs + (stg * 32 + brow) * 136 + bcol);
        asm volatile("cp.async.cg.shared.global [%0], [%1], 16;" :: "r"(as_addr), "l"(Ag));
        asm volatile("cp.async.cg.shared.global [%0], [%1], 16;" :: "r"(as_addr + 16), "l"(Ag + 8));
        asm volatile("cp.async.cg.shared.global [%0], [%1], 16;" :: "r"(bs_addr), "l"(Bg));
        asm volatile("cp.async.cg.shared.global [%0], [%1], 16;" :: "r"(bs_addr + 16), "l"(Bg + 8));
        asm volatile("cp.async.commit_group;");
    };

    float acc[4][4][4];
#pragma unroll
    for (int mi = 0; mi < 4; mi++)
#pragma unroll
        for (int nj = 0; nj < 4; nj++)
#pragma unroll
            for (int q = 0; q < 4; q++) acc[mi][nj][q] = 0.f;

    issue(0);
    issue(1);
    issue(2);
    issue(3);

    for (int kt = 0; kt < nk; kt++) {
        asm volatile("cp.async.wait_group 3;");
        __syncthreads();
        if (kt + 4 < nk) issue(kt + 4);
        else asm volatile("cp.async.commit_group;");

        const int stg = kt % GEMM_STAGES;
        const unsigned aBase = (unsigned)__cvta_generic_to_shared(As + stg * 128 * 40);
        const unsigned bBase = (unsigned)__cvta_generic_to_shared(Bs + stg * 32 * 136);
#pragma unroll
        for (int ks = 0; ks < 2; ks++) {
            unsigned afrag[4][4];
            unsigned bfrag[4][2];
#pragma unroll
            for (int mi = 0; mi < 4; mi++) {
                const int r = wm * 64 + mi * 16 + (lane & 15);
                const int c = ks * 16 + (lane >> 4) * 8;
                const unsigned addr = aBase + (unsigned)(r * 40 + c) * 2u;
                asm volatile("ldmatrix.sync.aligned.m8n8.x4.shared.b16 {%0,%1,%2,%3}, [%4];"
                             : "=r"(afrag[mi][0]), "=r"(afrag[mi][1]),
                               "=r"(afrag[mi][2]), "=r"(afrag[mi][3])
                             : "r"(addr));
            }
#pragma unroll
            for (int nj = 0; nj < 4; nj++) {
                const int kr = ks * 16 + (lane & 15);
                const int c  = wn * 32 + nj * 8;
                const unsigned addr = bBase + (unsigned)(kr * 136 + c) * 2u;
                asm volatile("ldmatrix.sync.aligned.m8n8.x2.trans.shared.b16 {%0,%1}, [%2];"
                             : "=r"(bfrag[nj][0]), "=r"(bfrag[nj][1])
                             : "r"(addr));
            }
#pragma unroll
            for (int mi = 0; mi < 4; mi++)
#pragma unroll
                for (int nj = 0; nj < 4; nj++)
                    asm volatile("mma.sync.aligned.m16n8k16.row.col.f32.f16.f16.f32 "
                                 "{%0,%1,%2,%3}, {%4,%5,%6,%7}, {%8,%9}, {%0,%1,%2,%3};"
                                 : "+f"(acc[mi][nj][0]), "+f"(acc[mi][nj][1]),
                                   "+f"(acc[mi][nj][2]), "+f"(acc[mi][nj][3])
                                 : "r"(afrag[mi][0]), "r"(afrag[mi][1]),
                                   "r"(afrag[mi][2]), "r"(afrag[mi][3]),
                                   "r"(bfrag[nj][0]), "r"(bfrag[nj][1]));
        }
    }

#pragma unroll
    for (int mi = 0; mi < 4; mi++) {
        const int r = row0 + wm * 64 + mi * 16 + (lane >> 2);
#pragma unroll
        for (int nj = 0; nj < 4; nj++) {
            const int c = col0 + wn * 32 + nj * 8 + (lane & 3) * 2;
            const float2 b2 = *(const float2*)&bias[c];
            float o0 = acc[mi][nj][0] + b2.x;
            float o1 = acc[mi][nj][1] + b2.y;
            float o2 = acc[mi][nj][2] + b2.x;
            float o3 = acc[mi][nj][3] + b2.y;
            if (OUTMODE == 0) {
                float* C = (float*)Cout;
                *(float2*)&C[(size_t)r * N + c]       = make_float2(o0, o1);
                *(float2*)&C[(size_t)(r + 8) * N + c] = make_float2(o2, o3);
            } else {
                o0 = 0.5f * o0 * (1.f + erff(o0 * 0.70710678118654752f));
                o1 = 0.5f * o1 * (1.f + erff(o1 * 0.70710678118654752f));
                o2 = 0.5f * o2 * (1.f + erff(o2 * 0.70710678118654752f));
                o3 = 0.5f * o3 * (1.f + erff(o3 * 0.70710678118654752f));
                __half* C2 = (__half*)Cout;
                __half2 p01, p23;
                p01.x = __float2half_rn(o0);
                p01.y = __float2half_rn(o1);
                p23.x = __float2half_rn(o2);
                p23.y = __float2half_rn(o3);
                *(__half2*)&C2[(size_t)r * N + c]       = p01;
                *(__half2*)&C2[(size_t)(r + 8) * N + c] = p23;
            }
        }
    }
}

// ---------------- embedding + layernorm (writes x fp32 + x~ fp16) ---------------
__global__ __launch_bounds__(256)
void embed_ln_kernel(const int* __restrict__ ids, const float* __restrict__ we,
                     const float* __restrict__ pe, const float* __restrict__ tt,
                     const float* __restrict__ g, const float* __restrict__ bta,
                     float* __restrict__ x, __half* __restrict__ xs, int S)
{
    const int tok = blockIdx.x;
    const int s   = tok % S;
    const int tid = threadIdx.x;
    const int id  = ids[tok];
    __shared__ float red[256];
    float v[3];
    float sum = 0.f;
#pragma unroll
    for (int i = 0; i < 3; i++) {
        const int dd = tid + i * 256;
        float t = we[(size_t)id * 768 + dd] + pe[(size_t)(s + 2) * 768 + dd] + tt[dd];
        v[i] = t;
        sum += t;
    }
    red[tid] = sum;
    __syncthreads();
    for (int st = 128; st > 0; st >>= 1) { if (tid < st) red[tid] += red[tid + st]; __syncthreads(); }
    const float mu = red[0] * (1.f / 768.f);
    __syncthreads();
    float vs = 0.f;
#pragma unroll
    for (int i = 0; i < 3; i++) { float dv = v[i] - mu; vs += dv * dv; }
    red[tid] = vs;
    __syncthreads();
    for (int st = 128; st > 0; st >>= 1) { if (tid < st) red[tid] += red[tid + st]; __syncthreads(); }
    const float rstd = rsqrtf(red[0] * (1.f / 768.f) + 1e-5f);
#pragma unroll
    for (int i = 0; i < 3; i++) {
        const int dd = tid + i * 256;
        const float o = (v[i] - mu) * rstd * g[dd] + bta[dd];
        x[(size_t)tok * 768 + dd] = o;
        xs[(size_t)tok * 768 + dd] = __float2half_rn(o);
    }
}

// ---------------- x = LN(x + delta), writes x fp32 + x~ fp16 --------------------
__global__ __launch_bounds__(256)
void add_ln_kernel(float* __restrict__ x, const float* __restrict__ dlt,
                   const float* __restrict__ g, const float* __restrict__ bta,
                   __half* __restrict__ xs)
{
    const int tok = blockIdx.x;
    const int tid = threadIdx.x;
    __shared__ float red[256];
    const size_t base = (size_t)tok * 768;
    float v[3];
    float sum = 0.f;
#pragma unroll
    for (int i = 0; i < 3; i++) {
        const int dd = tid + i * 256;
        float t = x[base + dd] + dlt[base + dd];
        v[i] = t;
        sum += t;
    }
    red[tid] = sum;
    __syncthreads();
    for (int st = 128; st > 0; st >>= 1) { if (tid < st) red[tid] += red[tid + st]; __syncthreads(); }
    const float mu = red[0] * (1.f / 768.f);
    __syncthreads();
    float vs = 0.f;
#pragma unroll
    for (int i = 0; i < 3; i++) { float dv = v[i] - mu; vs += dv * dv; }
    red[tid] = vs;
    __syncthreads();
    for (int st = 128; st > 0; st >>= 1) { if (tid < st) red[tid] += red[tid + st]; __syncthreads(); }
    const float rstd = rsqrtf(red[0] * (1.f / 768.f) + 1e-5f);
#pragma unroll
    for (int i = 0; i < 3; i++) {
        const int dd = tid + i * 256;
        const float o = (v[i] - mu) * rstd * g[dd] + bta[dd];
        x[base + dd] = o;
        xs[base + dd] = __float2half_rn(o);
    }
}

// ---------------- sliding-window attention, 8 queries per block -----------------
// Block (256 thr = 8 warps) handles (b, h, 8 queries). QKV rows of 2304 floats.
// Output written as fp16 [M][768] (feeds the Wo GEMM).
__global__ __launch_bounds__(256)
void attn_kernel(const float* __restrict__ QKV, const int* __restrict__ amask,
                 __half* __restrict__ AS, int S)
{
    const int q0 = blockIdx.x * 8, b = blockIdx.y, h = blockIdx.z;
    const int tid = threadIdx.x, lane = tid & 31, warp = tid >> 5;
    const int g = lane >> 4, li = lane & 15;
    __shared__ float sc[8][528];
    __shared__ float redm[16][8];
    __shared__ float reds[8][8];
    __shared__ float obuf[8][8][64];

    const size_t RS = 2304;
    const size_t base = (size_t)b * S * RS + (size_t)h * 64;
    const float* Q  = QKV + base;
    const float* Kp = QKV + base + 768;
    const float* Vp = QKV + base + 1536;

    int j0 = q0 - WIN; if (j0 < 0) j0 = 0;
    int j1 = q0 + 7 + WIN; if (j1 > S - 1) j1 = S - 1;
    const int nk = j1 - j0 + 1;

    float4 q4[8];
#pragma unroll
    for (int qi = 0; qi < 8; qi++)
        q4[qi] = *(const float4*)&Q[(size_t)(q0 + qi) * RS + 4 * li];

    float lmax[8] = {-1e30f, -1e30f, -1e30f, -1e30f, -1e30f, -1e30f, -1e30f, -1e30f};
    for (int jj = warp * 2 + g; jj < nk; jj += 16) {
        const int j = j0 + jj;
        const float4 k4 = *(const float4*)&Kp[(size_t)j * RS + 4 * li];
        float p[8];
#pragma unroll
        for (int qi = 0; qi < 8; qi++)
            p[qi] = q4[qi].x * k4.x + q4[qi].y * k4.y + q4[qi].z * k4.z + q4[qi].w * k4.w;
#pragma unroll
        for (int off = 8; off; off >>= 1)
#pragma unroll
            for (int qi = 0; qi < 8; qi++)
                p[qi] += __shfl_xor_sync(0xffffffffu, p[qi], off);
        const int mok = amask[b * S + j];
#pragma unroll
        for (int qi = 0; qi < 8; qi++) {
            const int sq = q0 + qi;
            const bool valid = mok && (j >= sq - WIN) && (j <= sq + WIN);
            const float val = valid ? p[qi] * 0.125f : -1e9f;
            if (li == qi) sc[qi][jj] = val;
            lmax[qi] = fmaxf(lmax[qi], val);
        }
    }
    if (li == 0) {
#pragma unroll
        for (int qi = 0; qi < 8; qi++) redm[warp * 2 + g][qi] = lmax[qi];
    }
    __syncthreads();
    float m[8];
#pragma unroll
    for (int qi = 0; qi < 8; qi++) {
        float mm = redm[0][qi];
#pragma unroll
        for (int w = 1; w < 16; w++) mm = fmaxf(mm, redm[w][qi]);
        m[qi] = mm;
    }

    float lsum[8] = {0.f, 0.f, 0.f, 0.f, 0.f, 0.f, 0.f, 0.f};
    for (int jj = tid; jj < nk; jj += 256) {
#pragma unroll
        for (int qi = 0; qi < 8; qi++) {
            const float e = __expf(sc[qi][jj] - m[qi]);
            sc[qi][jj] = e;
            lsum[qi] += e;
        }
    }
#pragma unroll
    for (int off = 16; off; off >>= 1)
#pragma unroll
        for (int qi = 0; qi < 8; qi++)
            lsum[qi] += __shfl_xor_sync(0xffffffffu, lsum[qi], off);
    if (lane == 0) {
#pragma unroll
        for (int qi = 0; qi < 8; qi++) reds[warp][qi] = lsum[qi];
    }
    __syncthreads();
    float inv[8];
#pragma unroll
    for (int qi = 0; qi < 8; qi++)
        inv[qi] = 1.f / (reds[0][qi] + reds[1][qi] + reds[2][qi] + reds[3][qi] +
                         reds[4][qi] + reds[5][qi] + reds[6][qi] + reds[7][qi]);

    float ax[8] = {0.f, 0.f, 0.f, 0.f, 0.f, 0.f, 0.f, 0.f};
    float ay[8] = {0.f, 0.f, 0.f, 0.f, 0.f, 0.f, 0.f, 0.f};
    for (int jj = warp; jj < nk; jj += 8) {
        const float2 v2 = *(const float2*)&Vp[(size_t)(j0 + jj) * RS + 2 * lane];
#pragma unroll
        for (int qi = 0; qi < 8; qi++) {
            const float p = sc[qi][jj];
            ax[qi] += p * v2.x;
            ay[qi] += p * v2.y;
        }
    }
#pragma unroll
    for (int qi = 0; qi < 8; qi++) {
        obuf[warp][qi][2 * lane]     = ax[qi];
        obuf[warp][qi][2 * lane + 1] = ay[qi];
    }
    __syncthreads();

    {
        const int qi = warp;
        float vx = 0.f, vy = 0.f;
#pragma unroll
        for (int w = 0; w < 8; w++) {
            vx += obuf[w][qi][2 * lane];
            vy += obuf[w][qi][2 * lane + 1];
        }
        vx *= inv[qi];
        vy *= inv[qi];
        const size_t row = (size_t)b * S + q0 + qi;
        const int col = h * 64 + 2 * lane;
        __half2 hp;
        hp.x = __float2half_rn(vx);
        hp.y = __float2half_rn(vy);
        *(__half2*)&AS[row * 768 + col] = hp;
    }
}

// ---------------- span pooling ---------------------------------------------------
__global__ __launch_bounds__(256)
void span_pool_kernel(const float* __restrict__ seq, const float* __restrict__ masks,
                      const int* __restrict__ sidx, float* __restrict__ emb, int S)
{
    const int t = blockIdx.x;
    const int b = sidx[t];
    const int tid = threadIdx.x;
    float acc0 = 0.f, acc1 = 0.f, acc2 = 0.f, msum = 0.f;
    for (int s = 0; s < S; s++) {
        const float m = masks[(size_t)t * S + s];
        msum += m;
        const float* row = seq + (size_t)(b * S + s) * 768;
        acc0 += m * row[tid];
        acc1 += m * row[tid + 256];
        acc2 += m * row[tid + 512];
    }
    const float inv = 1.f / fmaxf(msum, 1e-9f);
    emb[(size_t)t * 768 + tid]       = acc0 * inv;
    emb[(size_t)t * 768 + tid + 256] = acc1 * inv;
    emb[(size_t)t * 768 + tid + 512] = acc2 * inv;
}

// ---------------- projection head ----------------------------------------------
__global__ __launch_bounds__(256)
void proj_kernel(const float* __restrict__ emb, const float* __restrict__ pW1,
                 const float* __restrict__ pb1, const float* __restrict__ pW2,
                 const float* __restrict__ pb2, float* __restrict__ out)
{
    const int t = blockIdx.x;
    const int tid = threadIdx.x;
    __shared__ float e[768];
    __shared__ float hdn[768];
    __shared__ float o[128];
    __shared__ float red[256];
    for (int d = tid; d < 768; d += 256) e[d] = emb[(size_t)t * 768 + d];
    __syncthreads();
    for (int j = tid; j < 768; j += 256) {
        float acc = pb1[j];
        for (int d = 0; d < 768; d++) acc += e[d] * pW1[(size_t)d * 768 + j];
        hdn[j] = fmaxf(acc, 0.f);
    }
    __syncthreads();
    if (tid < 128) {
        float acc = pb2[tid];
        for (int j = 0; j < 768; j++) acc += hdn[j] * pW2[(size_t)j * 128 + tid];
        o[tid] = acc;
    }
    __syncthreads();
    red[tid] = (tid < 128) ? o[tid] * o[tid] : 0.f;
    __syncthreads();
    for (int st = 128; st > 0; st >>= 1) { if (tid < st) red[tid] += red[tid + st]; __syncthreads(); }
    const float inv = 1.f / fmaxf(sqrtf(red[0]), 1e-12f);
    if (tid < 128) out[(size_t)t * 128 + tid] = o[tid] * inv;
}

// ---------------- driver ----------------------------------------------------------
extern "C" void kernel_launch(void* const* d_in, const int* in_sizes, int n_in,
                              void* d_out, int out_size)
{
    const int*   doc_ids   = (const int*)d_in[0];
    const int*   doc_mask  = (const int*)d_in[1];
    const int*   sum_ids   = (const int*)d_in[2];
    const int*   sum_mask  = (const int*)d_in[3];
    const float* og_masks  = (const float*)d_in[4];
    const float* llm_masks = (const float*)d_in[5];
    const int*   sidx      = (const int*)d_in[6];
    const float* word_emb  = (const float*)d_in[7];
    const float* pos_emb   = (const float*)d_in[8];
    const float* tt_emb    = (const float*)d_in[9];
    const float* ln_emb_g  = (const float*)d_in[10];
    const float* ln_emb_b  = (const float*)d_in[11];
    const float* Wq = (const float*)d_in[12];
    const float* bq = (const float*)d_in[13];
    const float* Wk = (const float*)d_in[14];
    const float* bk = (const float*)d_in[15];
    const float* Wv = (const float*)d_in[16];
    const float* bv = (const float*)d_in[17];
    const float* Wo = (const float*)d_in[18];
    const float* bo = (const float*)d_in[19];
    const float* ln1_g = (const float*)d_in[20];
    const float* ln1_b = (const float*)d_in[21];
    const float* W1 = (const float*)d_in[22];
    const float* b1 = (const float*)d_in[23];
    const float* W2 = (const float*)d_in[24];
    const float* b2 = (const float*)d_in[25];
    const float* ln2_g = (const float*)d_in[26];
    const float* ln2_b = (const float*)d_in[27];
    const float* pW1 = (const float*)d_in[28];
    const float* pb1 = (const float*)d_in[29];
    const float* pW2 = (const float*)d_in[30];
    const float* pb2 = (const float*)d_in[31];
    float* out = (float*)d_out;

    float *x, *qkv, *tmp, *emb, *bqkv;
    __half *xs, *as_, *hs, *wqkv2, *wo2, *w12, *w22;
    cudaGetSymbolAddress((void**)&x, g_x);
    cudaGetSymbolAddress((void**)&qkv, g_qkv);
    cudaGetSymbolAddress((void**)&tmp, g_t);
    cudaGetSymbolAddress((void**)&emb, g_emb);
    cudaGetSymbolAddress((void**)&bqkv, g_bqkv);
    cudaGetSymbolAddress((void**)&xs, g_xs);
    cudaGetSymbolAddress((void**)&as_, g_as);
    cudaGetSymbolAddress((void**)&hs, g_hs);
    cudaGetSymbolAddress((void**)&wqkv2, g_wqkv2);
    cudaGetSymbolAddress((void**)&wo2, g_wo2);
    cudaGetSymbolAddress((void**)&w12, g_w12);
    cudaGetSymbolAddress((void**)&w22, g_w22);

    cudaFuncSetAttribute(gemm_fp16x2<0>, cudaFuncAttributeMaxDynamicSharedMemorySize, GEMM_SMEM);
    cudaFuncSetAttribute(gemm_fp16x2<1>, cudaFuncAttributeMaxDynamicSharedMemorySize, GEMM_SMEM);

    // one-time (per launch) weight conversion to fp16x2 layouts
    conv_qkv_kernel<<<dim3(6912, 12), 256>>>(Wq, Wk, Wv, bq, bk, bv, wqkv2, bqkv);
    conv_w_kernel<<<dim3(2304, 12), 256>>>(Wo, wo2, 768, 768);
    conv_w_kernel<<<dim3(9216, 12), 256>>>(W1, w12, 768, 3072);
    conv_w_kernel<<<dim3(9216, 12), 256>>>(W2, w22, 3072, 768);

    auto encode = [&](const int* ids, const int* amask, int B, int S) {
        const int T = B * S;
        embed_ln_kernel<<<T, 256>>>(ids, word_emb, pos_emb, tt_emb, ln_emb_g, ln_emb_b, x, xs, S);
        for (int l = 0; l < 12; l++) {
            dim3 g768(6, T / 128), g2304(18, T / 128), g3072(24, T / 128);
            gemm_fp16x2<0><<<g2304, 256, GEMM_SMEM>>>(xs, wqkv2 + (size_t)l * 1536 * 2304,
                                                      bqkv + l * 2304, qkv, T, 2304, 768);
            attn_kernel<<<dim3(S / 8, B, 12), 256>>>(qkv, amask, as_, S);
            gemm_fp16x2<0><<<g768, 256, GEMM_SMEM>>>(as_, wo2 + (size_t)l * 1536 * 768,
                                                     bo + l * 768, tmp, T, 768, 768);
            add_ln_kernel<<<T, 256>>>(x, tmp, ln1_g + l * 768, ln1_b + l * 768, xs);
            gemm_fp16x2<1><<<g3072, 256, GEMM_SMEM>>>(xs, w12 + (size_t)l * 1536 * 3072,
                                                      b1 + l * 3072, hs, T, 3072, 768);
            gemm_fp16x2<0><<<g768, 256, GEMM_SMEM>>>(hs, w22 + (size_t)l * 6144 * 768,
                                                     b2 + l * 768, tmp, T, 768, 3072);
            add_ln_kernel<<<T, 256>>>(x, tmp, ln2_g + l * 768, ln2_b + l * 768, xs);
        }
    };

    // doc pass -> human embeddings
    encode(doc_ids, doc_mask, 2, 2048);
    span_pool_kernel<<<16, 256>>>(x, og_masks, sidx, emb, 2048);
    proj_kernel<<<16, 256>>>(emb, pW1, pb1, pW2, pb2, out);

    // summary pass -> llm embeddings
    encode(sum_ids, sum_mask, 2, 512);
    span_pool_kernel<<<16, 256>>>(x, llm_masks, sidx, emb, 512);
    proj_kernel<<<16, 256>>>(emb, pW1, pb1, pW2, pb2, out + 16 * 128);
}

// round 11
// speedup vs baseline: 3.2029x; 1.3192x over previous
#include <cuda_runtime.h>
#include <cuda_fp16.h>
#include <stdint.h>
#include <math.h>

#define WIN 256

// ---------------- scratch (device globals; no allocation allowed) -------------
__device__ float g_x[4096 * 768];
__device__ float g_t[4096 * 768];
__device__ float g_emb[16 * 768];
__device__ float g_bqkv[12 * 2304];
// fp16 activations
__device__ __half g_qkv[(size_t)4096 * 2304];
__device__ __half g_xs[4096 * 768];
__device__ __half g_as[4096 * 768];
__device__ __half g_hs[(size_t)4096 * 3072];
// fp16 weights: [K][N] per layer
__device__ __half g_wqkv[(size_t)12 * 768 * 2304];
__device__ __half g_wo[(size_t)12 * 768 * 768];
__device__ __half g_w1[(size_t)12 * 768 * 3072];
__device__ __half g_w2[(size_t)12 * 3072 * 768];

// GEMM smem: 5 stages of (A 128x40 + B 32x136) half
#define GEMM_STAGES 5
#define GEMM_SMEM (GEMM_STAGES * (128 * 40 + 32 * 136) * 2)

// ---------------- weight conversion: W[K][N] fp32 -> [K][N] fp16 ----------------
__global__ __launch_bounds__(256)
void conv_w_kernel(const float* __restrict__ W, __half* __restrict__ W2,
                   int K, int N)
{
    const int l = blockIdx.y;
    const size_t i = (size_t)blockIdx.x * 256 + threadIdx.x;   // < K*N
    W2[(size_t)l * K * N + i] = __float2half_rn(W[(size_t)l * K * N + i]);
}

// ---------------- QKV pack + convert: Wq|Wk|Wv -> [768][2304] fp16 --------------
__global__ __launch_bounds__(256)
void conv_qkv_kernel(const float* __restrict__ Wq, const float* __restrict__ Wk,
                     const float* __restrict__ Wv, const float* __restrict__ bq,
                     const float* __restrict__ bk, const float* __restrict__ bv,
                     __half* __restrict__ W2, float* __restrict__ bias)
{
    const int l = blockIdx.y;
    const int i = blockIdx.x * 256 + threadIdx.x;   // < 768*2304
    const int k = i / 2304, n = i % 2304;
    const float* src = (n < 768) ? Wq : (n < 1536) ? Wk : Wv;
    const int nn = (n < 768) ? n : (n < 1536) ? n - 768 : n - 1536;
    W2[(size_t)l * 768 * 2304 + i] = __float2half_rn(src[((size_t)l * 768 + k) * 768 + nn]);
    if (i < 2304) {
        const float* bsrc = (i < 768) ? bq : (i < 1536) ? bk : bv;
        const int bn = (i < 768) ? i : (i < 1536) ? i - 768 : i - 1536;
        bias[l * 2304 + i] = bsrc[(size_t)l * 768 + bn];
    }
}

// ---------------- fp16 tensor-core GEMM, cp.async 5-stage -----------------------
// C[M,N] = x~[M,K](fp16) @ W[K,N](fp16) + bias
// OUTMODE 0: fp32 out.  OUTMODE 1: gelu + fp16 out.  OUTMODE 2: fp16 out.
template <int OUTMODE>
__global__ __launch_bounds__(256, 2)
void gemm_fp16(const __half* __restrict__ A1, const __half* __restrict__ B1,
               const float* __restrict__ bias, void* __restrict__ Cout,
               int M, int N, int K)
{
    extern __shared__ __align__(16) unsigned char smem_raw[];
    __half* As = (__half*)smem_raw;                                  // [5][128][40]
    __half* Bs = (__half*)(smem_raw + GEMM_STAGES * 128 * 40 * 2);   // [5][32][136]

    const int tid  = threadIdx.x;
    const int lane = tid & 31, warp = tid >> 5;
    const int wm = warp >> 2, wn = warp & 3;
    const int row0 = blockIdx.y * 128, col0 = blockIdx.x * 128;
    const int nk = K >> 5;

    const int arow = tid >> 1;          // 0..127
    const int acol = (tid & 1) * 16;    // 0 or 16 (halfs)
    const int brow = tid >> 3;          // 0..31
    const int bcol = (tid & 7) * 16;    // 0..112 (halfs)

    auto issue = [&](int kt) {
        const int stg = kt % GEMM_STAGES;
        const int kk = kt * 32;
        const __half* Ag = A1 + (size_t)(row0 + arow) * K + kk + acol;
        const __half* Bg = B1 + (size_t)(kk + brow) * N + col0 + bcol;
        const unsigned as_addr = (unsigned)__cvta_generic_to_shared(As + (stg * 128 + arow) * 40 + acol);
        const unsigned bs_addr = (unsigned)__cvta_generic_to_shared(Bs + (stg * 32 + brow) * 136 + bcol);
        asm volatile("cp.async.cg.shared.global [%0], [%1], 16;" :: "r"(as_addr), "l"(Ag));
        asm volatile("cp.async.cg.shared.global [%0], [%1], 16;" :: "r"(as_addr + 16), "l"(Ag + 8));
        asm volatile("cp.async.cg.shared.global [%0], [%1], 16;" :: "r"(bs_addr), "l"(Bg));
        asm volatile("cp.async.cg.shared.global [%0], [%1], 16;" :: "r"(bs_addr + 16), "l"(Bg + 8));
        asm volatile("cp.async.commit_group;");
    };

    float acc[4][4][4];
#pragma unroll
    for (int mi = 0; mi < 4; mi++)
#pragma unroll
        for (int nj = 0; nj < 4; nj++)
#pragma unroll
            for (int q = 0; q < 4; q++) acc[mi][nj][q] = 0.f;

    issue(0);
    issue(1);
    issue(2);
    issue(3);

    for (int kt = 0; kt < nk; kt++) {
        asm volatile("cp.async.wait_group 3;");
        __syncthreads();
        if (kt + 4 < nk) issue(kt + 4);
        else asm volatile("cp.async.commit_group;");

        const int stg = kt % GEMM_STAGES;
        const unsigned aBase = (unsigned)__cvta_generic_to_shared(As + stg * 128 * 40);
        const unsigned bBase = (unsigned)__cvta_generic_to_shared(Bs + stg * 32 * 136);
#pragma unroll
        for (int ks = 0; ks < 2; ks++) {
            unsigned afrag[4][4];
            unsigned bfrag[4][2];
#pragma unroll
            for (int mi = 0; mi < 4; mi++) {
                const int r = wm * 64 + mi * 16 + (lane & 15);
                const int c = ks * 16 + (lane >> 4) * 8;
                const unsigned addr = aBase + (unsigned)(r * 40 + c) * 2u;
                asm volatile("ldmatrix.sync.aligned.m8n8.x4.shared.b16 {%0,%1,%2,%3}, [%4];"
                             : "=r"(afrag[mi][0]), "=r"(afrag[mi][1]),
                               "=r"(afrag[mi][2]), "=r"(afrag[mi][3])
                             : "r"(addr));
            }
#pragma unroll
            for (int nj = 0; nj < 4; nj++) {
                const int kr = ks * 16 + (lane & 15);
                const int c  = wn * 32 + nj * 8;
                const unsigned addr = bBase + (unsigned)(kr * 136 + c) * 2u;
                asm volatile("ldmatrix.sync.aligned.m8n8.x2.trans.shared.b16 {%0,%1}, [%2];"
                             : "=r"(bfrag[nj][0]), "=r"(bfrag[nj][1])
                             : "r"(addr));
            }
#pragma unroll
            for (int mi = 0; mi < 4; mi++)
#pragma unroll
                for (int nj = 0; nj < 4; nj++)
                    asm volatile("mma.sync.aligned.m16n8k16.row.col.f32.f16.f16.f32 "
                                 "{%0,%1,%2,%3}, {%4,%5,%6,%7}, {%8,%9}, {%0,%1,%2,%3};"
                                 : "+f"(acc[mi][nj][0]), "+f"(acc[mi][nj][1]),
                                   "+f"(acc[mi][nj][2]), "+f"(acc[mi][nj][3])
                                 : "r"(afrag[mi][0]), "r"(afrag[mi][1]),
                                   "r"(afrag[mi][2]), "r"(afrag[mi][3]),
                                   "r"(bfrag[nj][0]), "r"(bfrag[nj][1]));
        }
    }

#pragma unroll
    for (int mi = 0; mi < 4; mi++) {
        const int r = row0 + wm * 64 + mi * 16 + (lane >> 2);
#pragma unroll
        for (int nj = 0; nj < 4; nj++) {
            const int c = col0 + wn * 32 + nj * 8 + (lane & 3) * 2;
            const float2 b2 = *(const float2*)&bias[c];
            float o0 = acc[mi][nj][0] + b2.x;
            float o1 = acc[mi][nj][1] + b2.y;
            float o2 = acc[mi][nj][2] + b2.x;
            float o3 = acc[mi][nj][3] + b2.y;
            if (OUTMODE == 0) {
                float* C = (float*)Cout;
                *(float2*)&C[(size_t)r * N + c]       = make_float2(o0, o1);
                *(float2*)&C[(size_t)(r + 8) * N + c] = make_float2(o2, o3);
            } else {
                if (OUTMODE == 1) {
                    o0 = 0.5f * o0 * (1.f + erff(o0 * 0.70710678118654752f));
                    o1 = 0.5f * o1 * (1.f + erff(o1 * 0.70710678118654752f));
                    o2 = 0.5f * o2 * (1.f + erff(o2 * 0.70710678118654752f));
                    o3 = 0.5f * o3 * (1.f + erff(o3 * 0.70710678118654752f));
                }
                __half* C2 = (__half*)Cout;
                __half2 p01, p23;
                p01.x = __float2half_rn(o0);
                p01.y = __float2half_rn(o1);
                p23.x = __float2half_rn(o2);
                p23.y = __float2half_rn(o3);
                *(__half2*)&C2[(size_t)r * N + c]       = p01;
                *(__half2*)&C2[(size_t)(r + 8) * N + c] = p23;
            }
        }
    }
}

// ---------------- embedding + layernorm (writes x fp32 + x~ fp16) ---------------
__global__ __launch_bounds__(256)
void embed_ln_kernel(const int* __restrict__ ids, const float* __restrict__ we,
                     const float* __restrict__ pe, const float* __restrict__ tt,
                     const float* __restrict__ g, const float* __restrict__ bta,
                     float* __restrict__ x, __half* __restrict__ xs, int S)
{
    const int tok = blockIdx.x;
    const int s   = tok % S;
    const int tid = threadIdx.x;
    const int id  = ids[tok];
    __shared__ float red[256];
    float v[3];
    float sum = 0.f;
#pragma unroll
    for (int i = 0; i < 3; i++) {
        const int dd = tid + i * 256;
        float t = we[(size_t)id * 768 + dd] + pe[(size_t)(s + 2) * 768 + dd] + tt[dd];
        v[i] = t;
        sum += t;
    }
    red[tid] = sum;
    __syncthreads();
    for (int st = 128; st > 0; st >>= 1) { if (tid < st) red[tid] += red[tid + st]; __syncthreads(); }
    const float mu = red[0] * (1.f / 768.f);
    __syncthreads();
    float vs = 0.f;
#pragma unroll
    for (int i = 0; i < 3; i++) { float dv = v[i] - mu; vs += dv * dv; }
    red[tid] = vs;
    __syncthreads();
    for (int st = 128; st > 0; st >>= 1) { if (tid < st) red[tid] += red[tid + st]; __syncthreads(); }
    const float rstd = rsqrtf(red[0] * (1.f / 768.f) + 1e-5f);
#pragma unroll
    for (int i = 0; i < 3; i++) {
        const int dd = tid + i * 256;
        const float o = (v[i] - mu) * rstd * g[dd] + bta[dd];
        x[(size_t)tok * 768 + dd] = o;
        xs[(size_t)tok * 768 + dd] = __float2half_rn(o);
    }
}

// ---------------- x = LN(x + delta), writes x fp32 + x~ fp16 --------------------
__global__ __launch_bounds__(256)
void add_ln_kernel(float* __restrict__ x, const float* __restrict__ dlt,
                   const float* __restrict__ g, const float* __restrict__ bta,
                   __half* __restrict__ xs)
{
    const int tok = blockIdx.x;
    const int tid = threadIdx.x;
    __shared__ float red[256];
    const size_t base = (size_t)tok * 768;
    float v[3];
    float sum = 0.f;
#pragma unroll
    for (int i = 0; i < 3; i++) {
        const int dd = tid + i * 256;
        float t = x[base + dd] + dlt[base + dd];
        v[i] = t;
        sum += t;
    }
    red[tid] = sum;
    __syncthreads();
    for (int st = 128; st > 0; st >>= 1) { if (tid < st) red[tid] += red[tid + st]; __syncthreads(); }
    const float mu = red[0] * (1.f / 768.f);
    __syncthreads();
    float vs = 0.f;
#pragma unroll
    for (int i = 0; i < 3; i++) { float dv = v[i] - mu; vs += dv * dv; }
    red[tid] = vs;
    __syncthreads();
    for (int st = 128; st > 0; st >>= 1) { if (tid < st) red[tid] += red[tid + st]; __syncthreads(); }
    const float rstd = rsqrtf(red[0] * (1.f / 768.f) + 1e-5f);
#pragma unroll
    for (int i = 0; i < 3; i++) {
        const int dd = tid + i * 256;
        const float o = (v[i] - mu) * rstd * g[dd] + bta[dd];
        x[base + dd] = o;
        xs[base + dd] = __float2half_rn(o);
    }
}

// ---------------- sliding-window attention, 8 queries per block, fp16 QKV -------
// Block (256 thr = 8 warps) handles (b, h, 8 queries). QKV rows of 2304 halfs.
// Output written as fp16 [M][768] (feeds the Wo GEMM).
__global__ __launch_bounds__(256)
void attn_kernel(const __half* __restrict__ QKV, const int* __restrict__ amask,
                 __half* __restrict__ AS, int S)
{
    const int q0 = blockIdx.x * 8, b = blockIdx.y, h = blockIdx.z;
    const int tid = threadIdx.x, lane = tid & 31, warp = tid >> 5;
    const int g = lane >> 4, li = lane & 15;
    __shared__ float sc[8][528];
    __shared__ float redm[16][8];
    __shared__ float reds[8][8];
    __shared__ float obuf[8][8][64];

    const size_t RS = 2304;
    const size_t base = (size_t)b * S * RS + (size_t)h * 64;
    const __half* Q  = QKV + base;
    const __half* Kp = QKV + base + 768;
    const __half* Vp = QKV + base + 1536;

    int j0 = q0 - WIN; if (j0 < 0) j0 = 0;
    int j1 = q0 + 7 + WIN; if (j1 > S - 1) j1 = S - 1;
    const int nk = j1 - j0 + 1;

    // each of 16 lanes holds 4 q dims as floats
    float4 q4[8];
#pragma unroll
    for (int qi = 0; qi < 8; qi++) {
        const __half2 a = *(const __half2*)&Q[(size_t)(q0 + qi) * RS + 4 * li];
        const __half2 bh = *(const __half2*)&Q[(size_t)(q0 + qi) * RS + 4 * li + 2];
        const float2 fa = __half22float2(a);
        const float2 fb = __half22float2(bh);
        q4[qi] = make_float4(fa.x, fa.y, fb.x, fb.y);
    }

    float lmax[8] = {-1e30f, -1e30f, -1e30f, -1e30f, -1e30f, -1e30f, -1e30f, -1e30f};
    for (int jj = warp * 2 + g; jj < nk; jj += 16) {
        const int j = j0 + jj;
        const __half2 ka = *(const __half2*)&Kp[(size_t)j * RS + 4 * li];
        const __half2 kb = *(const __half2*)&Kp[(size_t)j * RS + 4 * li + 2];
        const float2 fka = __half22float2(ka);
        const float2 fkb = __half22float2(kb);
        float p[8];
#pragma unroll
        for (int qi = 0; qi < 8; qi++)
            p[qi] = q4[qi].x * fka.x + q4[qi].y * fka.y + q4[qi].z * fkb.x + q4[qi].w * fkb.y;
#pragma unroll
        for (int off = 8; off; off >>= 1)
#pragma unroll
            for (int qi = 0; qi < 8; qi++)
                p[qi] += __shfl_xor_sync(0xffffffffu, p[qi], off);
        const int mok = amask[b * S + j];
#pragma unroll
        for (int qi = 0; qi < 8; qi++) {
            const int sq = q0 + qi;
            const bool valid = mok && (j >= sq - WIN) && (j <= sq + WIN);
            const float val = valid ? p[qi] * 0.125f : -1e9f;
            if (li == qi) sc[qi][jj] = val;
            lmax[qi] = fmaxf(lmax[qi], val);
        }
    }
    if (li == 0) {
#pragma unroll
        for (int qi = 0; qi < 8; qi++) redm[warp * 2 + g][qi] = lmax[qi];
    }
    __syncthreads();
    float m[8];
#pragma unroll
    for (int qi = 0; qi < 8; qi++) {
        float mm = redm[0][qi];
#pragma unroll
        for (int w = 1; w < 16; w++) mm = fmaxf(mm, redm[w][qi]);
        m[qi] = mm;
    }

    float lsum[8] = {0.f, 0.f, 0.f, 0.f, 0.f, 0.f, 0.f, 0.f};
    for (int jj = tid; jj < nk; jj += 256) {
#pragma unroll
        for (int qi = 0; qi < 8; qi++) {
            const float e = __expf(sc[qi][jj] - m[qi]);
            sc[qi][jj] = e;
            lsum[qi] += e;
        }
    }
#pragma unroll
    for (int off = 16; off; off >>= 1)
#pragma unroll
        for (int qi = 0; qi < 8; qi++)
            lsum[qi] += __shfl_xor_sync(0xffffffffu, lsum[qi], off);
    if (lane == 0) {
#pragma unroll
        for (int qi = 0; qi < 8; qi++) reds[warp][qi] = lsum[qi];
    }
    __syncthreads();
    float inv[8];
#pragma unroll
    for (int qi = 0; qi < 8; qi++)
        inv[qi] = 1.f / (reds[0][qi] + reds[1][qi] + reds[2][qi] + reds[3][qi] +
                         reds[4][qi] + reds[5][qi] + reds[6][qi] + reds[7][qi]);

    float ax[8] = {0.f, 0.f, 0.f, 0.f, 0.f, 0.f, 0.f, 0.f};
    float ay[8] = {0.f, 0.f, 0.f, 0.f, 0.f, 0.f, 0.f, 0.f};
    for (int jj = warp; jj < nk; jj += 8) {
        const __half2 vh = *(const __half2*)&Vp[(size_t)(j0 + jj) * RS + 2 * lane];
        const float2 v2 = __half22float2(vh);
#pragma unroll
        for (int qi = 0; qi < 8; qi++) {
            const float p = sc[qi][jj];
            ax[qi] += p * v2.x;
            ay[qi] += p * v2.y;
        }
    }
#pragma unroll
    for (int qi = 0; qi < 8; qi++) {
        obuf[warp][qi][2 * lane]     = ax[qi];
        obuf[warp][qi][2 * lane + 1] = ay[qi];
    }
    __syncthreads();

    {
        const int qi = warp;
        float vx = 0.f, vy = 0.f;
#pragma unroll
        for (int w = 0; w < 8; w++) {
            vx += obuf[w][qi][2 * lane];
            vy += obuf[w][qi][2 * lane + 1];
        }
        vx *= inv[qi];
        vy *= inv[qi];
        const size_t row = (size_t)b * S + q0 + qi;
        const int col = h * 64 + 2 * lane;
        __half2 hp;
        hp.x = __float2half_rn(vx);
        hp.y = __float2half_rn(vy);
        *(__half2*)&AS[row * 768 + col] = hp;
    }
}

// ---------------- span pooling ---------------------------------------------------
__global__ __launch_bounds__(256)
void span_pool_kernel(const float* __restrict__ seq, const float* __restrict__ masks,
                      const int* __restrict__ sidx, float* __restrict__ emb, int S)
{
    const int t = blockIdx.x;
    const int b = sidx[t];
    const int tid = threadIdx.x;
    float acc0 = 0.f, acc1 = 0.f, acc2 = 0.f, msum = 0.f;
    for (int s = 0; s < S; s++) {
        const float m = masks[(size_t)t * S + s];
        msum += m;
        const float* row = seq + (size_t)(b * S + s) * 768;
        acc0 += m * row[tid];
        acc1 += m * row[tid + 256];
        acc2 += m * row[tid + 512];
    }
    const float inv = 1.f / fmaxf(msum, 1e-9f);
    emb[(size_t)t * 768 + tid]       = acc0 * inv;
    emb[(size_t)t * 768 + tid + 256] = acc1 * inv;
    emb[(size_t)t * 768 + tid + 512] = acc2 * inv;
}

// ---------------- projection head ----------------------------------------------
__global__ __launch_bounds__(256)
void proj_kernel(const float* __restrict__ emb, const float* __restrict__ pW1,
                 const float* __restrict__ pb1, const float* __restrict__ pW2,
                 const float* __restrict__ pb2, float* __restrict__ out)
{
    const int t = blockIdx.x;
    const int tid = threadIdx.x;
    __shared__ float e[768];
    __shared__ float hdn[768];
    __shared__ float o[128];
    __shared__ float red[256];
    for (int d = tid; d < 768; d += 256) e[d] = emb[(size_t)t * 768 + d];
    __syncthreads();
    for (int j = tid; j < 768; j += 256) {
        float acc = pb1[j];
        for (int d = 0; d < 768; d++) acc += e[d] * pW1[(size_t)d * 768 + j];
        hdn[j] = fmaxf(acc, 0.f);
    }
    __syncthreads();
    if (tid < 128) {
        float acc = pb2[tid];
        for (int j = 0; j < 768; j++) acc += hdn[j] * pW2[(size_t)j * 128 + tid];
        o[tid] = acc;
    }
    __syncthreads();
    red[tid] = (tid < 128) ? o[tid] * o[tid] : 0.f;
    __syncthreads();
    for (int st = 128; st > 0; st >>= 1) { if (tid < st) red[tid] += red[tid + st]; __syncthreads(); }
    const float inv = 1.f / fmaxf(sqrtf(red[0]), 1e-12f);
    if (tid < 128) out[(size_t)t * 128 + tid] = o[tid] * inv;
}

// ---------------- driver ----------------------------------------------------------
extern "C" void kernel_launch(void* const* d_in, const int* in_sizes, int n_in,
                              void* d_out, int out_size)
{
    const int*   doc_ids   = (const int*)d_in[0];
    const int*   doc_mask  = (const int*)d_in[1];
    const int*   sum_ids   = (const int*)d_in[2];
    const int*   sum_mask  = (const int*)d_in[3];
    const float* og_masks  = (const float*)d_in[4];
    const float* llm_masks = (const float*)d_in[5];
    const int*   sidx      = (const int*)d_in[6];
    const float* word_emb  = (const float*)d_in[7];
    const float* pos_emb   = (const float*)d_in[8];
    const float* tt_emb    = (const float*)d_in[9];
    const float* ln_emb_g  = (const float*)d_in[10];
    const float* ln_emb_b  = (const float*)d_in[11];
    const float* Wq = (const float*)d_in[12];
    const float* bq = (const float*)d_in[13];
    const float* Wk = (const float*)d_in[14];
    const float* bk = (const float*)d_in[15];
    const float* Wv = (const float*)d_in[16];
    const float* bv = (const float*)d_in[17];
    const float* Wo = (const float*)d_in[18];
    const float* bo = (const float*)d_in[19];
    const float* ln1_g = (const float*)d_in[20];
    const float* ln1_b = (const float*)d_in[21];
    const float* W1 = (const float*)d_in[22];
    const float* b1 = (const float*)d_in[23];
    const float* W2 = (const float*)d_in[24];
    const float* b2 = (const float*)d_in[25];
    const float* ln2_g = (const float*)d_in[26];
    const float* ln2_b = (const float*)d_in[27];
    const float* pW1 = (const float*)d_in[28];
    const float* pb1 = (const float*)d_in[29];
    const float* pW2 = (const float*)d_in[30];
    const float* pb2 = (const float*)d_in[31];
    float* out = (float*)d_out;

    float *x, *tmp, *emb, *bqkv;
    __half *qkv, *xs, *as_, *hs, *wqkv, *wo, *w1, *w2;
    cudaGetSymbolAddress((void**)&x, g_x);
    cudaGetSymbolAddress((void**)&tmp, g_t);
    cudaGetSymbolAddress((void**)&emb, g_emb);
    cudaGetSymbolAddress((void**)&bqkv, g_bqkv);
    cudaGetSymbolAddress((void**)&qkv, g_qkv);
    cudaGetSymbolAddress((void**)&xs, g_xs);
    cudaGetSymbolAddress((void**)&as_, g_as);
    cudaGetSymbolAddress((void**)&hs, g_hs);
    cudaGetSymbolAddress((void**)&wqkv, g_wqkv);
    cudaGetSymbolAddress((void**)&wo, g_wo);
    cudaGetSymbolAddress((void**)&w1, g_w1);
    cudaGetSymbolAddress((void**)&w2, g_w2);

    cudaFuncSetAttribute(gemm_fp16<0>, cudaFuncAttributeMaxDynamicSharedMemorySize, GEMM_SMEM);
    cudaFuncSetAttribute(gemm_fp16<1>, cudaFuncAttributeMaxDynamicSharedMemorySize, GEMM_SMEM);
    cudaFuncSetAttribute(gemm_fp16<2>, cudaFuncAttributeMaxDynamicSharedMemorySize, GEMM_SMEM);

    // one-time (per launch) weight conversion to fp16 layouts
    conv_qkv_kernel<<<dim3(6912, 12), 256>>>(Wq, Wk, Wv, bq, bk, bv, wqkv, bqkv);
    conv_w_kernel<<<dim3(2304, 12), 256>>>(Wo, wo, 768, 768);
    conv_w_kernel<<<dim3(9216, 12), 256>>>(W1, w1, 768, 3072);
    conv_w_kernel<<<dim3(9216, 12), 256>>>(W2, w2, 3072, 768);

    auto encode = [&](const int* ids, const int* amask, int B, int S) {
        const int T = B * S;
        embed_ln_kernel<<<T, 256>>>(ids, word_emb, pos_emb, tt_emb, ln_emb_g, ln_emb_b, x, xs, S);
        for (int l = 0; l < 12; l++) {
            dim3 g768(6, T / 128), g2304(18, T / 128), g3072(24, T / 128);
            gemm_fp16<2><<<g2304, 256, GEMM_SMEM>>>(xs, wqkv + (size_t)l * 768 * 2304,
                                                    bqkv + l * 2304, qkv, T, 2304, 768);
            attn_kernel<<<dim3(S / 8, B, 12), 256>>>(qkv, amask, as_, S);
            gemm_fp16<0><<<g768, 256, GEMM_SMEM>>>(as_, wo + (size_t)l * 768 * 768,
                                                   bo + l * 768, tmp, T, 768, 768);
            add_ln_kernel<<<T, 256>>>(x, tmp, ln1_g + l * 768, ln1_b + l * 768, xs);
            gemm_fp16<1><<<g3072, 256, GEMM_SMEM>>>(xs, w1 + (size_t)l * 768 * 3072,
                                                    b1 + l * 3072, hs, T, 3072, 768);
            gemm_fp16<0><<<g768, 256, GEMM_SMEM>>>(hs, w2 + (size_t)l * 3072 * 768,
                                                   b2 + l * 768, tmp, T, 768, 3072);
            add_ln_kernel<<<T, 256>>>(x, tmp, ln2_g + l * 768, ln2_b + l * 768, xs);
        }
    };

    // doc pass -> human embeddings
    encode(doc_ids, doc_mask, 2, 2048);
    span_pool_kernel<<<16, 256>>>(x, og_masks, sidx, emb, 2048);
    proj_kernel<<<16, 256>>>(emb, pW1, pb1, pW2, pb2, out);

    // summary pass -> llm embeddings
    encode(sum_ids, sum_mask, 2, 512);
    span_pool_kernel<<<16, 256>>>(x, llm_masks, sidx, emb, 512);
    proj_kernel<<<16, 256>>>(emb, pW1, pb1, pW2, pb2, out + 16 * 128);
}

// round 12
// speedup vs baseline: 3.5617x; 1.1120x over previous
#include <cuda_runtime.h>
#include <cuda_fp16.h>
#include <stdint.h>
#include <math.h>

#define WIN 256
#define TTOT 5120   // 4096 doc tokens + 1024 summary tokens

// ---------------- scratch (device globals; no allocation allowed) -------------
__device__ float g_x[TTOT * 768];
__device__ float g_t[TTOT * 768];
__device__ float g_emb[16 * 768];
__device__ float g_bqkv[12 * 2304];
// fp16 activations
__device__ __half g_qkv[(size_t)TTOT * 2304];
__device__ __half g_xs[TTOT * 768];
__device__ __half g_as[TTOT * 768];
__device__ __half g_hs[(size_t)TTOT * 3072];
// fp16 weights: [K][N] per layer
__device__ __half g_wqkv[(size_t)12 * 768 * 2304];
__device__ __half g_wo[(size_t)12 * 768 * 768];
__device__ __half g_w1[(size_t)12 * 768 * 3072];
__device__ __half g_w2[(size_t)12 * 3072 * 768];

// GEMM smem: 5 stages of (A 128x40 + B 32x136) half
#define GEMM_STAGES 5
#define GEMM_SMEM (GEMM_STAGES * (128 * 40 + 32 * 136) * 2)

// ---------------- weight conversion: W[K][N] fp32 -> [K][N] fp16 ----------------
__global__ __launch_bounds__(256)
void conv_w_kernel(const float* __restrict__ W, __half* __restrict__ W2,
                   int K, int N)
{
    const int l = blockIdx.y;
    const size_t i = (size_t)blockIdx.x * 256 + threadIdx.x;   // < K*N
    W2[(size_t)l * K * N + i] = __float2half_rn(W[(size_t)l * K * N + i]);
}

// ---------------- QKV pack + convert: Wq|Wk|Wv -> [768][2304] fp16 --------------
__global__ __launch_bounds__(256)
void conv_qkv_kernel(const float* __restrict__ Wq, const float* __restrict__ Wk,
                     const float* __restrict__ Wv, const float* __restrict__ bq,
                     const float* __restrict__ bk, const float* __restrict__ bv,
                     __half* __restrict__ W2, float* __restrict__ bias)
{
    const int l = blockIdx.y;
    const int i = blockIdx.x * 256 + threadIdx.x;   // < 768*2304
    const int k = i / 2304, n = i % 2304;
    const float* src = (n < 768) ? Wq : (n < 1536) ? Wk : Wv;
    const int nn = (n < 768) ? n : (n < 1536) ? n - 768 : n - 1536;
    W2[(size_t)l * 768 * 2304 + i] = __float2half_rn(src[((size_t)l * 768 + k) * 768 + nn]);
    if (i < 2304) {
        const float* bsrc = (i < 768) ? bq : (i < 1536) ? bk : bv;
        const int bn = (i < 768) ? i : (i < 1536) ? i - 768 : i - 1536;
        bias[l * 2304 + i] = bsrc[(size_t)l * 768 + bn];
    }
}

// ---------------- fp16 tensor-core GEMM, cp.async 5-stage -----------------------
// C[M,N] = x~[M,K](fp16) @ W[K,N](fp16) + bias
// OUTMODE 0: fp32 out.  OUTMODE 1: gelu + fp16 out.  OUTMODE 2: fp16 out.
template <int OUTMODE>
__global__ __launch_bounds__(256, 2)
void gemm_fp16(const __half* __restrict__ A1, const __half* __restrict__ B1,
               const float* __restrict__ bias, void* __restrict__ Cout,
               int M, int N, int K)
{
    extern __shared__ __align__(16) unsigned char smem_raw[];
    __half* As = (__half*)smem_raw;                                  // [5][128][40]
    __half* Bs = (__half*)(smem_raw + GEMM_STAGES * 128 * 40 * 2);   // [5][32][136]

    const int tid  = threadIdx.x;
    const int lane = tid & 31, warp = tid >> 5;
    const int wm = warp >> 2, wn = warp & 3;
    const int row0 = blockIdx.y * 128, col0 = blockIdx.x * 128;
    const int nk = K >> 5;

    const int arow = tid >> 1;          // 0..127
    const int acol = (tid & 1) * 16;    // 0 or 16 (halfs)
    const int brow = tid >> 3;          // 0..31
    const int bcol = (tid & 7) * 16;    // 0..112 (halfs)

    auto issue = [&](int kt) {
        const int stg = kt % GEMM_STAGES;
        const int kk = kt * 32;
        const __half* Ag = A1 + (size_t)(row0 + arow) * K + kk + acol;
        const __half* Bg = B1 + (size_t)(kk + brow) * N + col0 + bcol;
        const unsigned as_addr = (unsigned)__cvta_generic_to_shared(As + (stg * 128 + arow) * 40 + acol);
        const unsigned bs_addr = (unsigned)__cvta_generic_to_shared(Bs + (stg * 32 + brow) * 136 + bcol);
        asm volatile("cp.async.cg.shared.global [%0], [%1], 16;" :: "r"(as_addr), "l"(Ag));
        asm volatile("cp.async.cg.shared.global [%0], [%1], 16;" :: "r"(as_addr + 16), "l"(Ag + 8));
        asm volatile("cp.async.cg.shared.global [%0], [%1], 16;" :: "r"(bs_addr), "l"(Bg));
        asm volatile("cp.async.cg.shared.global [%0], [%1], 16;" :: "r"(bs_addr + 16), "l"(Bg + 8));
        asm volatile("cp.async.commit_group;");
    };

    float acc[4][4][4];
#pragma unroll
    for (int mi = 0; mi < 4; mi++)
#pragma unroll
        for (int nj = 0; nj < 4; nj++)
#pragma unroll
            for (int q = 0; q < 4; q++) acc[mi][nj][q] = 0.f;

    issue(0);
    issue(1);
    issue(2);
    issue(3);

    for (int kt = 0; kt < nk; kt++) {
        asm volatile("cp.async.wait_group 3;");
        __syncthreads();
        if (kt + 4 < nk) issue(kt + 4);
        else asm volatile("cp.async.commit_group;");

        const int stg = kt % GEMM_STAGES;
        const unsigned aBase = (unsigned)__cvta_generic_to_shared(As + stg * 128 * 40);
        const unsigned bBase = (unsigned)__cvta_generic_to_shared(Bs + stg * 32 * 136);
#pragma unroll
        for (int ks = 0; ks < 2; ks++) {
            unsigned afrag[4][4];
            unsigned bfrag[4][2];
#pragma unroll
            for (int mi = 0; mi < 4; mi++) {
                const int r = wm * 64 + mi * 16 + (lane & 15);
                const int c = ks * 16 + (lane >> 4) * 8;
                const unsigned addr = aBase + (unsigned)(r * 40 + c) * 2u;
                asm volatile("ldmatrix.sync.aligned.m8n8.x4.shared.b16 {%0,%1,%2,%3}, [%4];"
                             : "=r"(afrag[mi][0]), "=r"(afrag[mi][1]),
                               "=r"(afrag[mi][2]), "=r"(afrag[mi][3])
                             : "r"(addr));
            }
#pragma unroll
            for (int nj = 0; nj < 4; nj++) {
                const int kr = ks * 16 + (lane & 15);
                const int c  = wn * 32 + nj * 8;
                const unsigned addr = bBase + (unsigned)(kr * 136 + c) * 2u;
                asm volatile("ldmatrix.sync.aligned.m8n8.x2.trans.shared.b16 {%0,%1}, [%2];"
                             : "=r"(bfrag[nj][0]), "=r"(bfrag[nj][1])
                             : "r"(addr));
            }
#pragma unroll
            for (int mi = 0; mi < 4; mi++)
#pragma unroll
                for (int nj = 0; nj < 4; nj++)
                    asm volatile("mma.sync.aligned.m16n8k16.row.col.f32.f16.f16.f32 "
                                 "{%0,%1,%2,%3}, {%4,%5,%6,%7}, {%8,%9}, {%0,%1,%2,%3};"
                                 : "+f"(acc[mi][nj][0]), "+f"(acc[mi][nj][1]),
                                   "+f"(acc[mi][nj][2]), "+f"(acc[mi][nj][3])
                                 : "r"(afrag[mi][0]), "r"(afrag[mi][1]),
                                   "r"(afrag[mi][2]), "r"(afrag[mi][3]),
                                   "r"(bfrag[nj][0]), "r"(bfrag[nj][1]));
        }
    }

#pragma unroll
    for (int mi = 0; mi < 4; mi++) {
        const int r = row0 + wm * 64 + mi * 16 + (lane >> 2);
#pragma unroll
        for (int nj = 0; nj < 4; nj++) {
            const int c = col0 + wn * 32 + nj * 8 + (lane & 3) * 2;
            const float2 b2 = *(const float2*)&bias[c];
            float o0 = acc[mi][nj][0] + b2.x;
            float o1 = acc[mi][nj][1] + b2.y;
            float o2 = acc[mi][nj][2] + b2.x;
            float o3 = acc[mi][nj][3] + b2.y;
            if (OUTMODE == 0) {
                float* C = (float*)Cout;
                *(float2*)&C[(size_t)r * N + c]       = make_float2(o0, o1);
                *(float2*)&C[(size_t)(r + 8) * N + c] = make_float2(o2, o3);
            } else {
                if (OUTMODE == 1) {
                    o0 = 0.5f * o0 * (1.f + erff(o0 * 0.70710678118654752f));
                    o1 = 0.5f * o1 * (1.f + erff(o1 * 0.70710678118654752f));
                    o2 = 0.5f * o2 * (1.f + erff(o2 * 0.70710678118654752f));
                    o3 = 0.5f * o3 * (1.f + erff(o3 * 0.70710678118654752f));
                }
                __half* C2 = (__half*)Cout;
                __half2 p01, p23;
                p01.x = __float2half_rn(o0);
                p01.y = __float2half_rn(o1);
                p23.x = __float2half_rn(o2);
                p23.y = __float2half_rn(o3);
                *(__half2*)&C2[(size_t)r * N + c]       = p01;
                *(__half2*)&C2[(size_t)(r + 8) * N + c] = p23;
            }
        }
    }
}

// ---------------- embedding + layernorm, merged doc+sum batch -------------------
// rows [0,4096): doc (B=2,S=2048); rows [4096,5120): summary (B=2,S=512)
__global__ __launch_bounds__(256)
void embed_ln_kernel(const int* __restrict__ doc_ids, const int* __restrict__ sum_ids,
                     const float* __restrict__ we,
                     const float* __restrict__ pe, const float* __restrict__ tt,
                     const float* __restrict__ g, const float* __restrict__ bta,
                     float* __restrict__ x, __half* __restrict__ xs)
{
    const int tok = blockIdx.x;
    const bool is_doc = tok < 4096;
    const int s  = is_doc ? (tok & 2047) : ((tok - 4096) & 511);
    const int id = is_doc ? doc_ids[tok] : sum_ids[tok - 4096];
    const int tid = threadIdx.x;
    __shared__ float red[256];
    float v[3];
    float sum = 0.f;
#pragma unroll
    for (int i = 0; i < 3; i++) {
        const int dd = tid + i * 256;
        float t = we[(size_t)id * 768 + dd] + pe[(size_t)(s + 2) * 768 + dd] + tt[dd];
        v[i] = t;
        sum += t;
    }
    red[tid] = sum;
    __syncthreads();
    for (int st = 128; st > 0; st >>= 1) { if (tid < st) red[tid] += red[tid + st]; __syncthreads(); }
    const float mu = red[0] * (1.f / 768.f);
    __syncthreads();
    float vs = 0.f;
#pragma unroll
    for (int i = 0; i < 3; i++) { float dv = v[i] - mu; vs += dv * dv; }
    red[tid] = vs;
    __syncthreads();
    for (int st = 128; st > 0; st >>= 1) { if (tid < st) red[tid] += red[tid + st]; __syncthreads(); }
    const float rstd = rsqrtf(red[0] * (1.f / 768.f) + 1e-5f);
#pragma unroll
    for (int i = 0; i < 3; i++) {
        const int dd = tid + i * 256;
        const float o = (v[i] - mu) * rstd * g[dd] + bta[dd];
        x[(size_t)tok * 768 + dd] = o;
        xs[(size_t)tok * 768 + dd] = __float2half_rn(o);
    }
}

// ---------------- x = LN(x + delta), writes x fp32 + x~ fp16 --------------------
__global__ __launch_bounds__(256)
void add_ln_kernel(float* __restrict__ x, const float* __restrict__ dlt,
                   const float* __restrict__ g, const float* __restrict__ bta,
                   __half* __restrict__ xs)
{
    const int tok = blockIdx.x;
    const int tid = threadIdx.x;
    __shared__ float red[256];
    const size_t base = (size_t)tok * 768;
    float v[3];
    float sum = 0.f;
#pragma unroll
    for (int i = 0; i < 3; i++) {
        const int dd = tid + i * 256;
        float t = x[base + dd] + dlt[base + dd];
        v[i] = t;
        sum += t;
    }
    red[tid] = sum;
    __syncthreads();
    for (int st = 128; st > 0; st >>= 1) { if (tid < st) red[tid] += red[tid + st]; __syncthreads(); }
    const float mu = red[0] * (1.f / 768.f);
    __syncthreads();
    float vs = 0.f;
#pragma unroll
    for (int i = 0; i < 3; i++) { float dv = v[i] - mu; vs += dv * dv; }
    red[tid] = vs;
    __syncthreads();
    for (int st = 128; st > 0; st >>= 1) { if (tid < st) red[tid] += red[tid + st]; __syncthreads(); }
    const float rstd = rsqrtf(red[0] * (1.f / 768.f) + 1e-5f);
#pragma unroll
    for (int i = 0; i < 3; i++) {
        const int dd = tid + i * 256;
        const float o = (v[i] - mu) * rstd * g[dd] + bta[dd];
        x[base + dd] = o;
        xs[base + dd] = __float2half_rn(o);
    }
}

// ---------------- sliding-window attention, 8 queries per block, fp16 QKV -------
// Block (256 thr = 8 warps) handles (b, h, 8 queries) of one sequence set.
// rowoff selects the token-row base (0 for doc, 4096 for summary).
__global__ __launch_bounds__(256)
void attn_kernel(const __half* __restrict__ QKV, const int* __restrict__ amask,
                 __half* __restrict__ AS, int S, int rowoff)
{
    const int q0 = blockIdx.x * 8, b = blockIdx.y, h = blockIdx.z;
    const int tid = threadIdx.x, lane = tid & 31, warp = tid >> 5;
    const int g = lane >> 4, li = lane & 15;
    __shared__ float sc[8][528];
    __shared__ float redm[16][8];
    __shared__ float reds[8][8];
    __shared__ float obuf[8][8][64];

    const size_t RS = 2304;
    const size_t base = ((size_t)rowoff + (size_t)b * S) * RS + (size_t)h * 64;
    const __half* Q  = QKV + base;
    const __half* Kp = QKV + base + 768;
    const __half* Vp = QKV + base + 1536;

    int j0 = q0 - WIN; if (j0 < 0) j0 = 0;
    int j1 = q0 + 7 + WIN; if (j1 > S - 1) j1 = S - 1;
    const int nk = j1 - j0 + 1;

    float4 q4[8];
#pragma unroll
    for (int qi = 0; qi < 8; qi++) {
        const __half2 a = *(const __half2*)&Q[(size_t)(q0 + qi) * RS + 4 * li];
        const __half2 bh = *(const __half2*)&Q[(size_t)(q0 + qi) * RS + 4 * li + 2];
        const float2 fa = __half22float2(a);
        const float2 fb = __half22float2(bh);
        q4[qi] = make_float4(fa.x, fa.y, fb.x, fb.y);
    }

    float lmax[8] = {-1e30f, -1e30f, -1e30f, -1e30f, -1e30f, -1e30f, -1e30f, -1e30f};
    for (int jj = warp * 2 + g; jj < nk; jj += 16) {
        const int j = j0 + jj;
        const __half2 ka = *(const __half2*)&Kp[(size_t)j * RS + 4 * li];
        const __half2 kb = *(const __half2*)&Kp[(size_t)j * RS + 4 * li + 2];
        const float2 fka = __half22float2(ka);
        const float2 fkb = __half22float2(kb);
        float p[8];
#pragma unroll
        for (int qi = 0; qi < 8; qi++)
            p[qi] = q4[qi].x * fka.x + q4[qi].y * fka.y + q4[qi].z * fkb.x + q4[qi].w * fkb.y;
#pragma unroll
        for (int off = 8; off; off >>= 1)
#pragma unroll
            for (int qi = 0; qi < 8; qi++)
                p[qi] += __shfl_xor_sync(0xffffffffu, p[qi], off);
        const int mok = amask[b * S + j];
#pragma unroll
        for (int qi = 0; qi < 8; qi++) {
            const int sq = q0 + qi;
            const bool valid = mok && (j >= sq - WIN) && (j <= sq + WIN);
            const float val = valid ? p[qi] * 0.125f : -1e9f;
            if (li == qi) sc[qi][jj] = val;
            lmax[qi] = fmaxf(lmax[qi], val);
        }
    }
    if (li == 0) {
#pragma unroll
        for (int qi = 0; qi < 8; qi++) redm[warp * 2 + g][qi] = lmax[qi];
    }
    __syncthreads();
    float m[8];
#pragma unroll
    for (int qi = 0; qi < 8; qi++) {
        float mm = redm[0][qi];
#pragma unroll
        for (int w = 1; w < 16; w++) mm = fmaxf(mm, redm[w][qi]);
        m[qi] = mm;
    }

    float lsum[8] = {0.f, 0.f, 0.f, 0.f, 0.f, 0.f, 0.f, 0.f};
    for (int jj = tid; jj < nk; jj += 256) {
#pragma unroll
        for (int qi = 0; qi < 8; qi++) {
            const float e = __expf(sc[qi][jj] - m[qi]);
            sc[qi][jj] = e;
            lsum[qi] += e;
        }
    }
#pragma unroll
    for (int off = 16; off; off >>= 1)
#pragma unroll
        for (int qi = 0; qi < 8; qi++)
            lsum[qi] += __shfl_xor_sync(0xffffffffu, lsum[qi], off);
    if (lane == 0) {
#pragma unroll
        for (int qi = 0; qi < 8; qi++) reds[warp][qi] = lsum[qi];
    }
    __syncthreads();
    float inv[8];
#pragma unroll
    for (int qi = 0; qi < 8; qi++)
        inv[qi] = 1.f / (reds[0][qi] + reds[1][qi] + reds[2][qi] + reds[3][qi] +
                         reds[4][qi] + reds[5][qi] + reds[6][qi] + reds[7][qi]);

    float ax[8] = {0.f, 0.f, 0.f, 0.f, 0.f, 0.f, 0.f, 0.f};
    float ay[8] = {0.f, 0.f, 0.f, 0.f, 0.f, 0.f, 0.f, 0.f};
    for (int jj = warp; jj < nk; jj += 8) {
        const __half2 vh = *(const __half2*)&Vp[(size_t)(j0 + jj) * RS + 2 * lane];
        const float2 v2 = __half22float2(vh);
#pragma unroll
        for (int qi = 0; qi < 8; qi++) {
            const float p = sc[qi][jj];
            ax[qi] += p * v2.x;
            ay[qi] += p * v2.y;
        }
    }
#pragma unroll
    for (int qi = 0; qi < 8; qi++) {
        obuf[warp][qi][2 * lane]     = ax[qi];
        obuf[warp][qi][2 * lane + 1] = ay[qi];
    }
    __syncthreads();

    {
        const int qi = warp;
        float vx = 0.f, vy = 0.f;
#pragma unroll
        for (int w = 0; w < 8; w++) {
            vx += obuf[w][qi][2 * lane];
            vy += obuf[w][qi][2 * lane + 1];
        }
        vx *= inv[qi];
        vy *= inv[qi];
        const size_t row = (size_t)rowoff + (size_t)b * S + q0 + qi;
        const int col = h * 64 + 2 * lane;
        __half2 hp;
        hp.x = __float2half_rn(vx);
        hp.y = __float2half_rn(vy);
        *(__half2*)&AS[row * 768 + col] = hp;
    }
}

// ---------------- span pooling ---------------------------------------------------
__global__ __launch_bounds__(256)
void span_pool_kernel(const float* __restrict__ seq, const float* __restrict__ masks,
                      const int* __restrict__ sidx, float* __restrict__ emb, int S)
{
    const int t = blockIdx.x;
    const int b = sidx[t];
    const int tid = threadIdx.x;
    float acc0 = 0.f, acc1 = 0.f, acc2 = 0.f, msum = 0.f;
    for (int s = 0; s < S; s++) {
        const float m = masks[(size_t)t * S + s];
        msum += m;
        const float* row = seq + (size_t)(b * S + s) * 768;
        acc0 += m * row[tid];
        acc1 += m * row[tid + 256];
        acc2 += m * row[tid + 512];
    }
    const float inv = 1.f / fmaxf(msum, 1e-9f);
    emb[(size_t)t * 768 + tid]       = acc0 * inv;
    emb[(size_t)t * 768 + tid + 256] = acc1 * inv;
    emb[(size_t)t * 768 + tid + 512] = acc2 * inv;
}

// ---------------- projection head ----------------------------------------------
__global__ __launch_bounds__(256)
void proj_kernel(const float* __restrict__ emb, const float* __restrict__ pW1,
                 const float* __restrict__ pb1, const float* __restrict__ pW2,
                 const float* __restrict__ pb2, float* __restrict__ out)
{
    const int t = blockIdx.x;
    const int tid = threadIdx.x;
    __shared__ float e[768];
    __shared__ float hdn[768];
    __shared__ float o[128];
    __shared__ float red[256];
    for (int d = tid; d < 768; d += 256) e[d] = emb[(size_t)t * 768 + d];
    __syncthreads();
    for (int j = tid; j < 768; j += 256) {
        float acc = pb1[j];
        for (int d = 0; d < 768; d++) acc += e[d] * pW1[(size_t)d * 768 + j];
        hdn[j] = fmaxf(acc, 0.f);
    }
    __syncthreads();
    if (tid < 128) {
        float acc = pb2[tid];
        for (int j = 0; j < 768; j++) acc += hdn[j] * pW2[(size_t)j * 128 + tid];
        o[tid] = acc;
    }
    __syncthreads();
    red[tid] = (tid < 128) ? o[tid] * o[tid] : 0.f;
    __syncthreads();
    for (int st = 128; st > 0; st >>= 1) { if (tid < st) red[tid] += red[tid + st]; __syncthreads(); }
    const float inv = 1.f / fmaxf(sqrtf(red[0]), 1e-12f);
    if (tid < 128) out[(size_t)t * 128 + tid] = o[tid] * inv;
}

// ---------------- driver ----------------------------------------------------------
extern "C" void kernel_launch(void* const* d_in, const int* in_sizes, int n_in,
                              void* d_out, int out_size)
{
    const int*   doc_ids   = (const int*)d_in[0];
    const int*   doc_mask  = (const int*)d_in[1];
    const int*   sum_ids   = (const int*)d_in[2];
    const int*   sum_mask  = (const int*)d_in[3];
    const float* og_masks  = (const float*)d_in[4];
    const float* llm_masks = (const float*)d_in[5];
    const int*   sidx      = (const int*)d_in[6];
    const float* word_emb  = (const float*)d_in[7];
    const float* pos_emb   = (const float*)d_in[8];
    const float* tt_emb    = (const float*)d_in[9];
    const float* ln_emb_g  = (const float*)d_in[10];
    const float* ln_emb_b  = (const float*)d_in[11];
    const float* Wq = (const float*)d_in[12];
    const float* bq = (const float*)d_in[13];
    const float* Wk = (const float*)d_in[14];
    const float* bk = (const float*)d_in[15];
    const float* Wv = (const float*)d_in[16];
    const float* bv = (const float*)d_in[17];
    const float* Wo = (const float*)d_in[18];
    const float* bo = (const float*)d_in[19];
    const float* ln1_g = (const float*)d_in[20];
    const float* ln1_b = (const float*)d_in[21];
    const float* W1 = (const float*)d_in[22];
    const float* b1 = (const float*)d_in[23];
    const float* W2 = (const float*)d_in[24];
    const float* b2 = (const float*)d_in[25];
    const float* ln2_g = (const float*)d_in[26];
    const float* ln2_b = (const float*)d_in[27];
    const float* pW1 = (const float*)d_in[28];
    const float* pb1 = (const float*)d_in[29];
    const float* pW2 = (const float*)d_in[30];
    const float* pb2 = (const float*)d_in[31];
    float* out = (float*)d_out;

    float *x, *tmp, *emb, *bqkv;
    __half *qkv, *xs, *as_, *hs, *wqkv, *wo, *w1, *w2;
    cudaGetSymbolAddress((void**)&x, g_x);
    cudaGetSymbolAddress((void**)&tmp, g_t);
    cudaGetSymbolAddress((void**)&emb, g_emb);
    cudaGetSymbolAddress((void**)&bqkv, g_bqkv);
    cudaGetSymbolAddress((void**)&qkv, g_qkv);
    cudaGetSymbolAddress((void**)&xs, g_xs);
    cudaGetSymbolAddress((void**)&as_, g_as);
    cudaGetSymbolAddress((void**)&hs, g_hs);
    cudaGetSymbolAddress((void**)&wqkv, g_wqkv);
    cudaGetSymbolAddress((void**)&wo, g_wo);
    cudaGetSymbolAddress((void**)&w1, g_w1);
    cudaGetSymbolAddress((void**)&w2, g_w2);

    cudaFuncSetAttribute(gemm_fp16<0>, cudaFuncAttributeMaxDynamicSharedMemorySize, GEMM_SMEM);
    cudaFuncSetAttribute(gemm_fp16<1>, cudaFuncAttributeMaxDynamicSharedMemorySize, GEMM_SMEM);
    cudaFuncSetAttribute(gemm_fp16<2>, cudaFuncAttributeMaxDynamicSharedMemorySize, GEMM_SMEM);

    // one-time (per launch) weight conversion to fp16 layouts
    conv_qkv_kernel<<<dim3(6912, 12), 256>>>(Wq, Wk, Wv, bq, bk, bv, wqkv, bqkv);
    conv_w_kernel<<<dim3(2304, 12), 256>>>(Wo, wo, 768, 768);
    conv_w_kernel<<<dim3(9216, 12), 256>>>(W1, w1, 768, 3072);
    conv_w_kernel<<<dim3(9216, 12), 256>>>(W2, w2, 3072, 768);

    // merged encoder: rows [0,4096) = doc (B=2,S=2048), rows [4096,5120) = summary (B=2,S=512)
    const int T = TTOT;
    embed_ln_kernel<<<T, 256>>>(doc_ids, sum_ids, word_emb, pos_emb, tt_emb,
                                ln_emb_g, ln_emb_b, x, xs);
    for (int l = 0; l < 12; l++) {
        dim3 g768(6, T / 128), g2304(18, T / 128), g3072(24, T / 128);
        gemm_fp16<2><<<g2304, 256, GEMM_SMEM>>>(xs, wqkv + (size_t)l * 768 * 2304,
                                                bqkv + l * 2304, qkv, T, 2304, 768);
        attn_kernel<<<dim3(256, 2, 12), 256>>>(qkv, doc_mask, as_, 2048, 0);
        attn_kernel<<<dim3(64, 2, 12), 256>>>(qkv, sum_mask, as_, 512, 4096);
        gemm_fp16<0><<<g768, 256, GEMM_SMEM>>>(as_, wo + (size_t)l * 768 * 768,
                                               bo + l * 768, tmp, T, 768, 768);
        add_ln_kernel<<<T, 256>>>(x, tmp, ln1_g + l * 768, ln1_b + l * 768, xs);
        gemm_fp16<1><<<g3072, 256, GEMM_SMEM>>>(xs, w1 + (size_t)l * 768 * 3072,
                                                b1 + l * 3072, hs, T, 3072, 768);
        gemm_fp16<0><<<g768, 256, GEMM_SMEM>>>(hs, w2 + (size_t)l * 3072 * 768,
                                               b2 + l * 768, tmp, T, 768, 3072);
        add_ln_kernel<<<T, 256>>>(x, tmp, ln2_g + l * 768, ln2_b + l * 768, xs);
    }

    // span pooling + projection heads
    span_pool_kernel<<<16, 256>>>(x, og_masks, sidx, emb, 2048);
    proj_kernel<<<16, 256>>>(emb, pW1, pb1, pW2, pb2, out);
    span_pool_kernel<<<16, 256>>>(x + (size_t)4096 * 768, llm_masks, sidx, emb, 512);
    proj_kernel<<<16, 256>>>(emb, pW1, pb1, pW2, pb2, out + 16 * 128);
}

// round 13
// speedup vs baseline: 3.8008x; 1.0672x over previous
#include <cuda_runtime.h>
#include <cuda_fp16.h>
#include <stdint.h>
#include <math.h>

#define WIN 256
#define TTOT 5120   // 4096 doc tokens + 1024 summary tokens

// ---------------- scratch (device globals; no allocation allowed) -------------
__device__ float g_x[TTOT * 768];
__device__ float g_t[TTOT * 768];
__device__ float g_emb[16 * 768];
__device__ float g_bqkv[12 * 2304];
// fp16 activations
__device__ __half g_qkv[(size_t)TTOT * 2304];
__device__ __half g_xs[TTOT * 768];
__device__ __half g_as[TTOT * 768];
__device__ __half g_hs[(size_t)TTOT * 3072];
// fp16 weights: [K][N] per layer
__device__ __half g_wqkv[(size_t)12 * 768 * 2304];
__device__ __half g_wo[(size_t)12 * 768 * 768];
__device__ __half g_w1[(size_t)12 * 768 * 3072];
__device__ __half g_w2[(size_t)12 * 3072 * 768];

// GEMM smem: 5 stages of (A 128x40 + B 32x136) half
#define GEMM_STAGES 5
#define GEMM_SMEM (GEMM_STAGES * (128 * 40 + 32 * 136) * 2)

// ---------------- merged weight conversion (Wo|W1|W2), 4 elems/thread ----------
#define WO_N 7077888ull     // 12*768*768
#define W1_N 28311552ull    // 12*768*3072
#define W2_N 28311552ull    // 12*3072*768

__global__ __launch_bounds__(256)
void conv_all_kernel(const float* __restrict__ Wo, const float* __restrict__ W1,
                     const float* __restrict__ W2, __half* __restrict__ wo,
                     __half* __restrict__ w1, __half* __restrict__ w2)
{
    size_t i = ((size_t)blockIdx.x * 256 + threadIdx.x) * 4;
    const float* src;
    __half* dst;
    if (i < WO_N) { src = Wo; dst = wo; }
    else if (i < WO_N + W1_N) { i -= WO_N; src = W1; dst = w1; }
    else { i -= WO_N + W1_N; src = W2; dst = w2; }
    const float4 v = *(const float4*)&src[i];
    *(__half2*)&dst[i]     = __floats2half2_rn(v.x, v.y);
    *(__half2*)&dst[i + 2] = __floats2half2_rn(v.z, v.w);
}

// ---------------- QKV pack + convert: Wq|Wk|Wv -> [768][2304] fp16, 4/thread ----
__global__ __launch_bounds__(256)
void conv_qkv_kernel(const float* __restrict__ Wq, const float* __restrict__ Wk,
                     const float* __restrict__ Wv, const float* __restrict__ bq,
                     const float* __restrict__ bk, const float* __restrict__ bv,
                     __half* __restrict__ W2h, float* __restrict__ bias)
{
    const int l = blockIdx.y;
    const int i = (blockIdx.x * 256 + threadIdx.x) * 4;   // < 768*2304, 4-aligned
    const int k = i / 2304, n = i % 2304;                 // 4-group never crosses 768-boundary
    const float* src = (n < 768) ? Wq : (n < 1536) ? Wk : Wv;
    const int nn = (n < 768) ? n : (n < 1536) ? n - 768 : n - 1536;
    const float4 v = *(const float4*)&src[((size_t)l * 768 + k) * 768 + nn];
    __half* O = W2h + (size_t)l * 768 * 2304 + i;
    *(__half2*)&O[0] = __floats2half2_rn(v.x, v.y);
    *(__half2*)&O[2] = __floats2half2_rn(v.z, v.w);
    if (i < 2304) {
        const float* bsrc = (i < 768) ? bq : (i < 1536) ? bk : bv;
        const int bn = (i < 768) ? i : (i < 1536) ? i - 768 : i - 1536;
        const float4 b4 = *(const float4*)&bsrc[(size_t)l * 768 + bn];
        *(float4*)&bias[l * 2304 + i] = b4;
    }
}

// ---------------- fp16 tensor-core GEMM, cp.async 5-stage -----------------------
// C[M,N] = x~[M,K](fp16) @ W[K,N](fp16) + bias
// OUTMODE 0: fp32 out.  OUTMODE 1: gelu + fp16 out.  OUTMODE 2: fp16 out.
template <int OUTMODE>
__global__ __launch_bounds__(256, 2)
void gemm_fp16(const __half* __restrict__ A1, const __half* __restrict__ B1,
               const float* __restrict__ bias, void* __restrict__ Cout,
               int M, int N, int K)
{
    extern __shared__ __align__(16) unsigned char smem_raw[];
    __half* As = (__half*)smem_raw;                                  // [5][128][40]
    __half* Bs = (__half*)(smem_raw + GEMM_STAGES * 128 * 40 * 2);   // [5][32][136]

    const int tid  = threadIdx.x;
    const int lane = tid & 31, warp = tid >> 5;
    const int wm = warp >> 2, wn = warp & 3;
    const int row0 = blockIdx.y * 128, col0 = blockIdx.x * 128;
    const int nk = K >> 5;

    const int arow = tid >> 1;          // 0..127
    const int acol = (tid & 1) * 16;    // 0 or 16 (halfs)
    const int brow = tid >> 3;          // 0..31
    const int bcol = (tid & 7) * 16;    // 0..112 (halfs)

    auto issue = [&](int kt) {
        const int stg = kt % GEMM_STAGES;
        const int kk = kt * 32;
        const __half* Ag = A1 + (size_t)(row0 + arow) * K + kk + acol;
        const __half* Bg = B1 + (size_t)(kk + brow) * N + col0 + bcol;
        const unsigned as_addr = (unsigned)__cvta_generic_to_shared(As + (stg * 128 + arow) * 40 + acol);
        const unsigned bs_addr = (unsigned)__cvta_generic_to_shared(Bs + (stg * 32 + brow) * 136 + bcol);
        asm volatile("cp.async.cg.shared.global [%0], [%1], 16;" :: "r"(as_addr), "l"(Ag));
        asm volatile("cp.async.cg.shared.global [%0], [%1], 16;" :: "r"(as_addr + 16), "l"(Ag + 8));
        asm volatile("cp.async.cg.shared.global [%0], [%1], 16;" :: "r"(bs_addr), "l"(Bg));
        asm volatile("cp.async.cg.shared.global [%0], [%1], 16;" :: "r"(bs_addr + 16), "l"(Bg + 8));
        asm volatile("cp.async.commit_group;");
    };

    float acc[4][4][4];
#pragma unroll
    for (int mi = 0; mi < 4; mi++)
#pragma unroll
        for (int nj = 0; nj < 4; nj++)
#pragma unroll
            for (int q = 0; q < 4; q++) acc[mi][nj][q] = 0.f;

    issue(0);
    issue(1);
    issue(2);
    issue(3);

    for (int kt = 0; kt < nk; kt++) {
        asm volatile("cp.async.wait_group 3;");
        __syncthreads();
        if (kt + 4 < nk) issue(kt + 4);
        else asm volatile("cp.async.commit_group;");

        const int stg = kt % GEMM_STAGES;
        const unsigned aBase = (unsigned)__cvta_generic_to_shared(As + stg * 128 * 40);
        const unsigned bBase = (unsigned)__cvta_generic_to_shared(Bs + stg * 32 * 136);
#pragma unroll
        for (int ks = 0; ks < 2; ks++) {
            unsigned afrag[4][4];
            unsigned bfrag[4][2];
#pragma unroll
            for (int mi = 0; mi < 4; mi++) {
                const int r = wm * 64 + mi * 16 + (lane & 15);
                const int c = ks * 16 + (lane >> 4) * 8;
                const unsigned addr = aBase + (unsigned)(r * 40 + c) * 2u;
                asm volatile("ldmatrix.sync.aligned.m8n8.x4.shared.b16 {%0,%1,%2,%3}, [%4];"
                             : "=r"(afrag[mi][0]), "=r"(afrag[mi][1]),
                               "=r"(afrag[mi][2]), "=r"(afrag[mi][3])
                             : "r"(addr));
            }
#pragma unroll
            for (int nj = 0; nj < 4; nj++) {
                const int kr = ks * 16 + (lane & 15);
                const int c  = wn * 32 + nj * 8;
                const unsigned addr = bBase + (unsigned)(kr * 136 + c) * 2u;
                asm volatile("ldmatrix.sync.aligned.m8n8.x2.trans.shared.b16 {%0,%1}, [%2];"
                             : "=r"(bfrag[nj][0]), "=r"(bfrag[nj][1])
                             : "r"(addr));
            }
#pragma unroll
            for (int mi = 0; mi < 4; mi++)
#pragma unroll
                for (int nj = 0; nj < 4; nj++)
                    asm volatile("mma.sync.aligned.m16n8k16.row.col.f32.f16.f16.f32 "
                                 "{%0,%1,%2,%3}, {%4,%5,%6,%7}, {%8,%9}, {%0,%1,%2,%3};"
                                 : "+f"(acc[mi][nj][0]), "+f"(acc[mi][nj][1]),
                                   "+f"(acc[mi][nj][2]), "+f"(acc[mi][nj][3])
                                 : "r"(afrag[mi][0]), "r"(afrag[mi][1]),
                                   "r"(afrag[mi][2]), "r"(afrag[mi][3]),
                                   "r"(bfrag[nj][0]), "r"(bfrag[nj][1]));
        }
    }

#pragma unroll
    for (int mi = 0; mi < 4; mi++) {
        const int r = row0 + wm * 64 + mi * 16 + (lane >> 2);
#pragma unroll
        for (int nj = 0; nj < 4; nj++) {
            const int c = col0 + wn * 32 + nj * 8 + (lane & 3) * 2;
            const float2 b2 = *(const float2*)&bias[c];
            float o0 = acc[mi][nj][0] + b2.x;
            float o1 = acc[mi][nj][1] + b2.y;
            float o2 = acc[mi][nj][2] + b2.x;
            float o3 = acc[mi][nj][3] + b2.y;
            if (OUTMODE == 0) {
                float* C = (float*)Cout;
                *(float2*)&C[(size_t)r * N + c]       = make_float2(o0, o1);
                *(float2*)&C[(size_t)(r + 8) * N + c] = make_float2(o2, o3);
            } else {
                if (OUTMODE == 1) {
                    o0 = 0.5f * o0 * (1.f + erff(o0 * 0.70710678118654752f));
                    o1 = 0.5f * o1 * (1.f + erff(o1 * 0.70710678118654752f));
                    o2 = 0.5f * o2 * (1.f + erff(o2 * 0.70710678118654752f));
                    o3 = 0.5f * o3 * (1.f + erff(o3 * 0.70710678118654752f));
                }
                __half* C2 = (__half*)Cout;
                *(__half2*)&C2[(size_t)r * N + c]       = __floats2half2_rn(o0, o1);
                *(__half2*)&C2[(size_t)(r + 8) * N + c] = __floats2half2_rn(o2, o3);
            }
        }
    }
}

// ---------------- embedding + layernorm, merged batch, 192 thr, float4 ----------
__global__ __launch_bounds__(192)
void embed_ln_kernel(const int* __restrict__ doc_ids, const int* __restrict__ sum_ids,
                     const float* __restrict__ we,
                     const float* __restrict__ pe, const float* __restrict__ tt,
                     const float* __restrict__ g, const float* __restrict__ bta,
                     float* __restrict__ x, __half* __restrict__ xs)
{
    const int tok = blockIdx.x;
    const bool is_doc = tok < 4096;
    const int s  = is_doc ? (tok & 2047) : ((tok - 4096) & 511);
    const int id = is_doc ? doc_ids[tok] : sum_ids[tok - 4096];
    const int tid = threadIdx.x, lane = tid & 31, warp = tid >> 5;
    const int c0 = tid * 4;
    __shared__ float red[2][6];

    const float4 w4 = *(const float4*)&we[(size_t)id * 768 + c0];
    const float4 p4 = *(const float4*)&pe[(size_t)(s + 2) * 768 + c0];
    const float4 t4 = *(const float4*)&tt[c0];
    float4 v = make_float4(w4.x + p4.x + t4.x, w4.y + p4.y + t4.y,
                           w4.z + p4.z + t4.z, w4.w + p4.w + t4.w);

    float sum = v.x + v.y + v.z + v.w;
#pragma unroll
    for (int off = 16; off; off >>= 1) sum += __shfl_xor_sync(0xffffffffu, sum, off);
    if (lane == 0) red[0][warp] = sum;
    __syncthreads();
    const float mu = (red[0][0] + red[0][1] + red[0][2] + red[0][3] + red[0][4] + red[0][5]) * (1.f / 768.f);

    float vs = (v.x - mu) * (v.x - mu) + (v.y - mu) * (v.y - mu) +
               (v.z - mu) * (v.z - mu) + (v.w - mu) * (v.w - mu);
#pragma unroll
    for (int off = 16; off; off >>= 1) vs += __shfl_xor_sync(0xffffffffu, vs, off);
    if (lane == 0) red[1][warp] = vs;
    __syncthreads();
    const float rstd = rsqrtf((red[1][0] + red[1][1] + red[1][2] + red[1][3] + red[1][4] + red[1][5]) * (1.f / 768.f) + 1e-5f);

    const float4 g4 = *(const float4*)&g[c0];
    const float4 b4 = *(const float4*)&bta[c0];
    float4 o;
    o.x = (v.x - mu) * rstd * g4.x + b4.x;
    o.y = (v.y - mu) * rstd * g4.y + b4.y;
    o.z = (v.z - mu) * rstd * g4.z + b4.z;
    o.w = (v.w - mu) * rstd * g4.w + b4.w;
    *(float4*)&x[(size_t)tok * 768 + c0] = o;
    __half2* xo = (__half2*)&xs[(size_t)tok * 768 + c0];
    xo[0] = __floats2half2_rn(o.x, o.y);
    xo[1] = __floats2half2_rn(o.z, o.w);
}

// ---------------- x = LN(x + delta), 192 thr, float4 ----------------------------
__global__ __launch_bounds__(192)
void add_ln_kernel(float* __restrict__ x, const float* __restrict__ dlt,
                   const float* __restrict__ g, const float* __restrict__ bta,
                   __half* __restrict__ xs)
{
    const int tok = blockIdx.x;
    const int tid = threadIdx.x, lane = tid & 31, warp = tid >> 5;
    const int c0 = tid * 4;
    __shared__ float red[2][6];
    const size_t base = (size_t)tok * 768 + c0;

    const float4 x4 = *(const float4*)&x[base];
    const float4 d4 = *(const float4*)&dlt[base];
    float4 v = make_float4(x4.x + d4.x, x4.y + d4.y, x4.z + d4.z, x4.w + d4.w);

    float sum = v.x + v.y + v.z + v.w;
#pragma unroll
    for (int off = 16; off; off >>= 1) sum += __shfl_xor_sync(0xffffffffu, sum, off);
    if (lane == 0) red[0][warp] = sum;
    __syncthreads();
    const float mu = (red[0][0] + red[0][1] + red[0][2] + red[0][3] + red[0][4] + red[0][5]) * (1.f / 768.f);

    float vs = (v.x - mu) * (v.x - mu) + (v.y - mu) * (v.y - mu) +
               (v.z - mu) * (v.z - mu) + (v.w - mu) * (v.w - mu);
#pragma unroll
    for (int off = 16; off; off >>= 1) vs += __shfl_xor_sync(0xffffffffu, vs, off);
    if (lane == 0) red[1][warp] = vs;
    __syncthreads();
    const float rstd = rsqrtf((red[1][0] + red[1][1] + red[1][2] + red[1][3] + red[1][4] + red[1][5]) * (1.f / 768.f) + 1e-5f);

    const float4 g4 = *(const float4*)&g[c0];
    const float4 b4 = *(const float4*)&bta[c0];
    float4 o;
    o.x = (v.x - mu) * rstd * g4.x + b4.x;
    o.y = (v.y - mu) * rstd * g4.y + b4.y;
    o.z = (v.z - mu) * rstd * g4.z + b4.z;
    o.w = (v.w - mu) * rstd * g4.w + b4.w;
    *(float4*)&x[base] = o;
    __half2* xo = (__half2*)&xs[base];
    xo[0] = __floats2half2_rn(o.x, o.y);
    xo[1] = __floats2half2_rn(o.z, o.w);
}

// ---------------- sliding-window attention, doc+sum fused, 8 q/block ------------
// gridDim.x = 256 (doc) + 64 (sum). Block (256 thr) handles (seqset, b, h, 8 q).
__global__ __launch_bounds__(256)
void attn_kernel(const __half* __restrict__ QKV, const int* __restrict__ doc_mask,
                 const int* __restrict__ sum_mask, __half* __restrict__ AS)
{
    const bool is_doc = blockIdx.x < 256;
    const int S = is_doc ? 2048 : 512;
    const int rowoff = is_doc ? 0 : 4096;
    const int* amask = is_doc ? doc_mask : sum_mask;
    const int q0 = (is_doc ? blockIdx.x : blockIdx.x - 256) * 8;
    const int b = blockIdx.y, h = blockIdx.z;
    const int tid = threadIdx.x, lane = tid & 31, warp = tid >> 5;
    const int g = lane >> 4, li = lane & 15;
    __shared__ float sc[8][528];
    __shared__ float redm[16][8];
    __shared__ float reds[8][8];
    __shared__ float obuf[8][8][64];

    const size_t RS = 2304;
    const size_t base = ((size_t)rowoff + (size_t)b * S) * RS + (size_t)h * 64;
    const __half* Q  = QKV + base;
    const __half* Kp = QKV + base + 768;
    const __half* Vp = QKV + base + 1536;

    int j0 = q0 - WIN; if (j0 < 0) j0 = 0;
    int j1 = q0 + 7 + WIN; if (j1 > S - 1) j1 = S - 1;
    const int nk = j1 - j0 + 1;

    float4 q4[8];
#pragma unroll
    for (int qi = 0; qi < 8; qi++) {
        const __half2 a = *(const __half2*)&Q[(size_t)(q0 + qi) * RS + 4 * li];
        const __half2 bh = *(const __half2*)&Q[(size_t)(q0 + qi) * RS + 4 * li + 2];
        const float2 fa = __half22float2(a);
        const float2 fb = __half22float2(bh);
        q4[qi] = make_float4(fa.x, fa.y, fb.x, fb.y);
    }

    float lmax[8] = {-1e30f, -1e30f, -1e30f, -1e30f, -1e30f, -1e30f, -1e30f, -1e30f};
    for (int jj = warp * 2 + g; jj < nk; jj += 16) {
        const int j = j0 + jj;
        const __half2 ka = *(const __half2*)&Kp[(size_t)j * RS + 4 * li];
        const __half2 kb = *(const __half2*)&Kp[(size_t)j * RS + 4 * li + 2];
        const float2 fka = __half22float2(ka);
        const float2 fkb = __half22float2(kb);
        float p[8];
#pragma unroll
        for (int qi = 0; qi < 8; qi++)
            p[qi] = q4[qi].x * fka.x + q4[qi].y * fka.y + q4[qi].z * fkb.x + q4[qi].w * fkb.y;
#pragma unroll
        for (int off = 8; off; off >>= 1)
#pragma unroll
            for (int qi = 0; qi < 8; qi++)
                p[qi] += __shfl_xor_sync(0xffffffffu, p[qi], off);
        const int mok = amask[b * S + j];
#pragma unroll
        for (int qi = 0; qi < 8; qi++) {
            const int sq = q0 + qi;
            const bool valid = mok && (j >= sq - WIN) && (j <= sq + WIN);
            const float val = valid ? p[qi] * 0.125f : -1e9f;
            if (li == qi) sc[qi][jj] = val;
            lmax[qi] = fmaxf(lmax[qi], val);
        }
    }
    if (li == 0) {
#pragma unroll
        for (int qi = 0; qi < 8; qi++) redm[warp * 2 + g][qi] = lmax[qi];
    }
    __syncthreads();
    float m[8];
#pragma unroll
    for (int qi = 0; qi < 8; qi++) {
        float mm = redm[0][qi];
#pragma unroll
        for (int w = 1; w < 16; w++) mm = fmaxf(mm, redm[w][qi]);
        m[qi] = mm;
    }

    float lsum[8] = {0.f, 0.f, 0.f, 0.f, 0.f, 0.f, 0.f, 0.f};
    for (int jj = tid; jj < nk; jj += 256) {
#pragma unroll
        for (int qi = 0; qi < 8; qi++) {
            const float e = __expf(sc[qi][jj] - m[qi]);
            sc[qi][jj] = e;
            lsum[qi] += e;
        }
    }
#pragma unroll
    for (int off = 16; off; off >>= 1)
#pragma unroll
        for (int qi = 0; qi < 8; qi++)
            lsum[qi] += __shfl_xor_sync(0xffffffffu, lsum[qi], off);
    if (lane == 0) {
#pragma unroll
        for (int qi = 0; qi < 8; qi++) reds[warp][qi] = lsum[qi];
    }
    __syncthreads();
    float inv[8];
#pragma unroll
    for (int qi = 0; qi < 8; qi++)
        inv[qi] = 1.f / (reds[0][qi] + reds[1][qi] + reds[2][qi] + reds[3][qi] +
                         reds[4][qi] + reds[5][qi] + reds[6][qi] + reds[7][qi]);

    float ax[8] = {0.f, 0.f, 0.f, 0.f, 0.f, 0.f, 0.f, 0.f};
    float ay[8] = {0.f, 0.f, 0.f, 0.f, 0.f, 0.f, 0.f, 0.f};
    for (int jj = warp; jj < nk; jj += 8) {
        const __half2 vh = *(const __half2*)&Vp[(size_t)(j0 + jj) * RS + 2 * lane];
        const float2 v2 = __half22float2(vh);
#pragma unroll
        for (int qi = 0; qi < 8; qi++) {
            const float p = sc[qi][jj];
            ax[qi] += p * v2.x;
            ay[qi] += p * v2.y;
        }
    }
#pragma unroll
    for (int qi = 0; qi < 8; qi++) {
        obuf[warp][qi][2 * lane]     = ax[qi];
        obuf[warp][qi][2 * lane + 1] = ay[qi];
    }
    __syncthreads();

    {
        const int qi = warp;
        float vx = 0.f, vy = 0.f;
#pragma unroll
        for (int w = 0; w < 8; w++) {
            vx += obuf[w][qi][2 * lane];
            vy += obuf[w][qi][2 * lane + 1];
        }
        vx *= inv[qi];
        vy *= inv[qi];
        const size_t row = (size_t)rowoff + (size_t)b * S + q0 + qi;
        const int col = h * 64 + 2 * lane;
        *(__half2*)&AS[row * 768 + col] = __floats2half2_rn(vx, vy);
    }
}

// ---------------- span pooling ---------------------------------------------------
__global__ __launch_bounds__(256)
void span_pool_kernel(const float* __restrict__ seq, const float* __restrict__ masks,
                      const int* __restrict__ sidx, float* __restrict__ emb, int S)
{
    const int t = blockIdx.x;
    const int b = sidx[t];
    const int tid = threadIdx.x;
    float acc0 = 0.f, acc1 = 0.f, acc2 = 0.f, msum = 0.f;
    for (int s = 0; s < S; s++) {
        const float m = masks[(size_t)t * S + s];
        msum += m;
        const float* row = seq + (size_t)(b * S + s) * 768;
        acc0 += m * row[tid];
        acc1 += m * row[tid + 256];
        acc2 += m * row[tid + 512];
    }
    const float inv = 1.f / fmaxf(msum, 1e-9f);
    emb[(size_t)t * 768 + tid]       = acc0 * inv;
    emb[(size_t)t * 768 + tid + 256] = acc1 * inv;
    emb[(size_t)t * 768 + tid + 512] = acc2 * inv;
}

// ---------------- projection head ----------------------------------------------
__global__ __launch_bounds__(256)
void proj_kernel(const float* __restrict__ emb, const float* __restrict__ pW1,
                 const float* __restrict__ pb1, const float* __restrict__ pW2,
                 const float* __restrict__ pb2, float* __restrict__ out)
{
    const int t = blockIdx.x;
    const int tid = threadIdx.x;
    __shared__ float e[768];
    __shared__ float hdn[768];
    __shared__ float o[128];
    __shared__ float red[256];
    for (int d = tid; d < 768; d += 256) e[d] = emb[(size_t)t * 768 + d];
    __syncthreads();
    for (int j = tid; j < 768; j += 256) {
        float acc = pb1[j];
        for (int d = 0; d < 768; d++) acc += e[d] * pW1[(size_t)d * 768 + j];
        hdn[j] = fmaxf(acc, 0.f);
    }
    __syncthreads();
    if (tid < 128) {
        float acc = pb2[tid];
        for (int j = 0; j < 768; j++) acc += hdn[j] * pW2[(size_t)j * 128 + tid];
        o[tid] = acc;
    }
    __syncthreads();
    red[tid] = (tid < 128) ? o[tid] * o[tid] : 0.f;
    __syncthreads();
    for (int st = 128; st > 0; st >>= 1) { if (tid < st) red[tid] += red[tid + st]; __syncthreads(); }
    const float inv = 1.f / fmaxf(sqrtf(red[0]), 1e-12f);
    if (tid < 128) out[(size_t)t * 128 + tid] = o[tid] * inv;
}

// ---------------- driver ----------------------------------------------------------
extern "C" void kernel_launch(void* const* d_in, const int* in_sizes, int n_in,
                              void* d_out, int out_size)
{
    const int*   doc_ids   = (const int*)d_in[0];
    const int*   doc_mask  = (const int*)d_in[1];
    const int*   sum_ids   = (const int*)d_in[2];
    const int*   sum_mask  = (const int*)d_in[3];
    const float* og_masks  = (const float*)d_in[4];
    const float* llm_masks = (const float*)d_in[5];
    const int*   sidx      = (const int*)d_in[6];
    const float* word_emb  = (const float*)d_in[7];
    const float* pos_emb   = (const float*)d_in[8];
    const float* tt_emb    = (const float*)d_in[9];
    const float* ln_emb_g  = (const float*)d_in[10];
    const float* ln_emb_b  = (const float*)d_in[11];
    const float* Wq = (const float*)d_in[12];
    const float* bq = (const float*)d_in[13];
    const float* Wk = (const float*)d_in[14];
    const float* bk = (const float*)d_in[15];
    const float* Wv = (const float*)d_in[16];
    const float* bv = (const float*)d_in[17];
    const float* Wo = (const float*)d_in[18];
    const float* bo = (const float*)d_in[19];
    const float* ln1_g = (const float*)d_in[20];
    const float* ln1_b = (const float*)d_in[21];
    const float* W1 = (const float*)d_in[22];
    const float* b1 = (const float*)d_in[23];
    const float* W2 = (const float*)d_in[24];
    const float* b2 = (const float*)d_in[25];
    const float* ln2_g = (const float*)d_in[26];
    const float* ln2_b = (const float*)d_in[27];
    const float* pW1 = (const float*)d_in[28];
    const float* pb1 = (const float*)d_in[29];
    const float* pW2 = (const float*)d_in[30];
    const float* pb2 = (const float*)d_in[31];
    float* out = (float*)d_out;

    float *x, *tmp, *emb, *bqkv;
    __half *qkv, *xs, *as_, *hs, *wqkv, *wo, *w1, *w2;
    cudaGetSymbolAddress((void**)&x, g_x);
    cudaGetSymbolAddress((void**)&tmp, g_t);
    cudaGetSymbolAddress((void**)&emb, g_emb);
    cudaGetSymbolAddress((void**)&bqkv, g_bqkv);
    cudaGetSymbolAddress((void**)&qkv, g_qkv);
    cudaGetSymbolAddress((void**)&xs, g_xs);
    cudaGetSymbolAddress((void**)&as_, g_as);
    cudaGetSymbolAddress((void**)&hs, g_hs);
    cudaGetSymbolAddress((void**)&wqkv, g_wqkv);
    cudaGetSymbolAddress((void**)&wo, g_wo);
    cudaGetSymbolAddress((void**)&w1, g_w1);
    cudaGetSymbolAddress((void**)&w2, g_w2);

    cudaFuncSetAttribute(gemm_fp16<0>, cudaFuncAttributeMaxDynamicSharedMemorySize, GEMM_SMEM);
    cudaFuncSetAttribute(gemm_fp16<1>, cudaFuncAttributeMaxDynamicSharedMemorySize, GEMM_SMEM);
    cudaFuncSetAttribute(gemm_fp16<2>, cudaFuncAttributeMaxDynamicSharedMemorySize, GEMM_SMEM);

    // one-time (per launch) weight conversion to fp16 layouts (2 launches)
    conv_qkv_kernel<<<dim3(1728, 12), 256>>>(Wq, Wk, Wv, bq, bk, bv, wqkv, bqkv);
    conv_all_kernel<<<62208, 256>>>(Wo, W1, W2, wo, w1, w2);

    // merged encoder: rows [0,4096) = doc (B=2,S=2048), rows [4096,5120) = summary
    const int T = TTOT;
    embed_ln_kernel<<<T, 192>>>(doc_ids, sum_ids, word_emb, pos_emb, tt_emb,
                                ln_emb_g, ln_emb_b, x, xs);
    for (int l = 0; l < 12; l++) {
        dim3 g768(6, T / 128), g2304(18, T / 128), g3072(24, T / 128);
        gemm_fp16<2><<<g2304, 256, GEMM_SMEM>>>(xs, wqkv + (size_t)l * 768 * 2304,
                                                bqkv + l * 2304, qkv, T, 2304, 768);
        attn_kernel<<<dim3(320, 2, 12), 256>>>(qkv, doc_mask, sum_mask, as_);
        gemm_fp16<0><<<g768, 256, GEMM_SMEM>>>(as_, wo + (size_t)l * 768 * 768,
                                               bo + l * 768, tmp, T, 768, 768);
        add_ln_kernel<<<T, 192>>>(x, tmp, ln1_g + l * 768, ln1_b + l * 768, xs);
        gemm_fp16<1><<<g3072, 256, GEMM_SMEM>>>(xs, w1 + (size_t)l * 768 * 3072,
                                                b1 + l * 3072, hs, T, 3072, 768);
        gemm_fp16<0><<<g768, 256, GEMM_SMEM>>>(hs, w2 + (size_t)l * 3072 * 768,
                                               b2 + l * 768, tmp, T, 768, 3072);
        add_ln_kernel<<<T, 192>>>(x, tmp, ln2_g + l * 768, ln2_b + l * 768, xs);
    }

    // span pooling + projection heads
    span_pool_kernel<<<16, 256>>>(x, og_masks, sidx, emb, 2048);
    proj_kernel<<<16, 256>>>(emb, pW1, pb1, pW2, pb2, out);
    span_pool_kernel<<<16, 256>>>(x + (size_t)4096 * 768, llm_masks, sidx, emb, 512);
    proj_kernel<<<16, 256>>>(emb, pW1, pb1, pW2, pb2, out + 16 * 128);
}